// round 1
// baseline (speedup 1.0000x reference)
#include <cuda_runtime.h>

// Shapes are fixed by the problem.
#define Bv 2
#define Sv 2048
#define Ev 1024
#define Hv 16
#define Dv 64
#define Mv (Bv * Sv) /* 4096 */

// Scratch (allocation-free rule: __device__ globals). 4 x 16 MB.
__device__ float g_q[(size_t)Mv * Ev];
__device__ float g_k[(size_t)Mv * Ev];
__device__ float g_v[(size_t)Mv * Ev];
__device__ float g_attn[(size_t)Mv * Ev];

// ---------------------------------------------------------------------------
// SGEMM: C[M,N] = A[M,K] @ W[N,K]^T + bias[N]
// Both operands K-minor (row-major X, row-major W) => "NT" gemm, ideal loads.
// 128x128 block tile, BK=8, 256 threads, 8x8 per thread.
// ---------------------------------------------------------------------------
__global__ void __launch_bounds__(256)
gemm_bias_nt(const float* __restrict__ A, const float* __restrict__ W,
             const float* __restrict__ bias, float* __restrict__ C,
             int M, int N, int K)
{
    __shared__ float As[8][128];
    __shared__ float Bs[8][128];

    const int tid = threadIdx.x;
    const int tx = tid & 15;          // 0..15  -> 8 cols each
    const int ty = tid >> 4;          // 0..15  -> 8 rows each
    const int bm = blockIdx.y << 7;
    const int bn = blockIdx.x << 7;

    const int lrow = tid >> 1;        // 0..127
    const int lc4  = (tid & 1) << 2;  // 0 or 4
    const float* Ap = A + (size_t)(bm + lrow) * K + lc4;
    const float* Wp = W + (size_t)(bn + lrow) * K + lc4;

    float acc[8][8];
#pragma unroll
    for (int i = 0; i < 8; i++)
#pragma unroll
        for (int j = 0; j < 8; j++) acc[i][j] = 0.f;

    for (int kt = 0; kt < K; kt += 8) {
        const float4 av = *(const float4*)(Ap + kt);
        const float4 wv = *(const float4*)(Wp + kt);
        __syncthreads();  // previous iter's smem reads complete
        As[lc4 + 0][lrow] = av.x; As[lc4 + 1][lrow] = av.y;
        As[lc4 + 2][lrow] = av.z; As[lc4 + 3][lrow] = av.w;
        Bs[lc4 + 0][lrow] = wv.x; Bs[lc4 + 1][lrow] = wv.y;
        Bs[lc4 + 2][lrow] = wv.z; Bs[lc4 + 3][lrow] = wv.w;
        __syncthreads();
#pragma unroll
        for (int kk = 0; kk < 8; kk++) {
            float a[8], b[8];
            *(float4*)&a[0] = *(const float4*)&As[kk][ty * 8];
            *(float4*)&a[4] = *(const float4*)&As[kk][ty * 8 + 4];
            *(float4*)&b[0] = *(const float4*)&Bs[kk][tx * 8];
            *(float4*)&b[4] = *(const float4*)&Bs[kk][tx * 8 + 4];
#pragma unroll
            for (int i = 0; i < 8; i++)
#pragma unroll
                for (int j = 0; j < 8; j++)
                    acc[i][j] = fmaf(a[i], b[j], acc[i][j]);
        }
    }

#pragma unroll
    for (int i = 0; i < 8; i++) {
        const int row = bm + ty * 8 + i;
        float* cp = C + (size_t)row * N + bn + tx * 8;
#pragma unroll
        for (int j = 0; j < 8; j += 4) {
            float4 o;
            o.x = acc[i][j + 0] + bias[bn + tx * 8 + j + 0];
            o.y = acc[i][j + 1] + bias[bn + tx * 8 + j + 1];
            o.z = acc[i][j + 2] + bias[bn + tx * 8 + j + 2];
            o.w = acc[i][j + 3] + bias[bn + tx * 8 + j + 3];
            *(float4*)(cp + j) = o;
        }
    }
}

// ---------------------------------------------------------------------------
// Flash attention, fp32, online softmax.
// Grid: (S/64, H, B). Block: 256 threads (16x16), each thread owns a 4x4
// fragment of the 64x64 score tile and a 4x4 fragment of the 64x64 output.
// Tiles use row stride 68 floats (272 B, 16B-aligned): conflict-light for
// both the transposed stores and the float4 fragment reads.
// ---------------------------------------------------------------------------
#define FSTR 68
#define FA_SMEM (3 * 64 * FSTR * 4)

__global__ void __launch_bounds__(256)
flash_attn(const float* __restrict__ Qp, const float* __restrict__ Kp,
           const float* __restrict__ Vp, const int* __restrict__ mask,
           float* __restrict__ Op)
{
    extern __shared__ float sm[];
    float (*Qs)[FSTR]  = (float(*)[FSTR])(sm);
    float (*KVs)[FSTR] = (float(*)[FSTR])(sm + 64 * FSTR);
    float (*Ps)[FSTR]  = (float(*)[FSTR])(sm + 2 * 64 * FSTR);

    const int tid = threadIdx.x;
    const int tx = tid & 15;
    const int ty = tid >> 4;
    const int b  = blockIdx.z;
    const int h  = blockIdx.y;
    const int qb = blockIdx.x << 6;
    const int hb = h << 6;

    const int lr = tid & 63;          // tile row handled by this thread on loads
    const int lk = (tid >> 6) << 4;   // 16-wide column chunk

    // Load Q tile transposed: Qs[k][r] = Q[qb+r][hb+k]
    {
        const float* src = Qp + (size_t)(b * Sv + qb + lr) * Ev + hb + lk;
#pragma unroll
        for (int j = 0; j < 16; j += 4) {
            const float4 v = *(const float4*)(src + j);
            Qs[lk + j + 0][lr] = v.x; Qs[lk + j + 1][lr] = v.y;
            Qs[lk + j + 2][lr] = v.z; Qs[lk + j + 3][lr] = v.w;
        }
    }

    float m_i[4], l_i[4], o[4][4];
#pragma unroll
    for (int i = 0; i < 4; i++) {
        m_i[i] = -1e30f; l_i[i] = 0.f;
#pragma unroll
        for (int j = 0; j < 4; j++) o[i][j] = 0.f;
    }

    for (int kv = 0; kv < Sv; kv += 64) {
        // ---- load K tile transposed into KVs: KVs[k][c] = K[kv+c][hb+k] ----
        const float* ksrc = Kp + (size_t)(b * Sv + kv + lr) * Ev + hb + lk;
        float4 kreg[4];
#pragma unroll
        for (int j = 0; j < 4; j++) kreg[j] = *(const float4*)(ksrc + 4 * j);
        __syncthreads();  // prior iter finished reading KVs/Ps (also covers Q store iter 0)
#pragma unroll
        for (int j = 0; j < 4; j++) {
            KVs[lk + 4 * j + 0][lr] = kreg[j].x; KVs[lk + 4 * j + 1][lr] = kreg[j].y;
            KVs[lk + 4 * j + 2][lr] = kreg[j].z; KVs[lk + 4 * j + 3][lr] = kreg[j].w;
        }
        __syncthreads();

        // ---- S = Q K^T (64x64x64), 4x4 fragment per thread ----
        float s[4][4];
#pragma unroll
        for (int i = 0; i < 4; i++)
#pragma unroll
            for (int j = 0; j < 4; j++) s[i][j] = 0.f;
#pragma unroll 16
        for (int k = 0; k < 64; k++) {
            float qa[4], kb[4];
            *(float4*)qa = *(const float4*)&Qs[k][ty * 4];
            *(float4*)kb = *(const float4*)&KVs[k][tx * 4];
#pragma unroll
            for (int i = 0; i < 4; i++)
#pragma unroll
                for (int j = 0; j < 4; j++)
                    s[i][j] = fmaf(qa[i], kb[j], s[i][j]);
        }

        // ---- mask, scale, online softmax (rows shared by 16 lanes) ----
#pragma unroll
        for (int i = 0; i < 4; i++) {
            const int4 mk = *(const int4*)(mask +
                (size_t)(b * Sv + qb + ty * 4 + i) * Sv + kv + tx * 4);
            s[i][0] = mk.x ? s[i][0] * 0.125f : -1e9f;
            s[i][1] = mk.y ? s[i][1] * 0.125f : -1e9f;
            s[i][2] = mk.z ? s[i][2] * 0.125f : -1e9f;
            s[i][3] = mk.w ? s[i][3] * 0.125f : -1e9f;

            float mx = fmaxf(fmaxf(s[i][0], s[i][1]), fmaxf(s[i][2], s[i][3]));
#pragma unroll
            for (int off = 8; off; off >>= 1)
                mx = fmaxf(mx, __shfl_xor_sync(0xffffffffu, mx, off));
            const float mn   = fmaxf(m_i[i], mx);
            const float corr = __expf(m_i[i] - mn);
            m_i[i] = mn;

            float rs = 0.f;
#pragma unroll
            for (int j = 0; j < 4; j++) {
                s[i][j] = __expf(s[i][j] - mn);
                rs += s[i][j];
            }
#pragma unroll
            for (int off = 8; off; off >>= 1)
                rs += __shfl_xor_sync(0xffffffffu, rs, off);
            l_i[i] = l_i[i] * corr + rs;
#pragma unroll
            for (int j = 0; j < 4; j++) o[i][j] *= corr;
        }

        __syncthreads();  // all lanes done reading KVs(K) and Ps(prev)

        // ---- stage P transposed, load V tile (natural layout) ----
#pragma unroll
        for (int i = 0; i < 4; i++)
#pragma unroll
            for (int j = 0; j < 4; j++)
                Ps[tx * 4 + j][ty * 4 + i] = s[i][j];
        {
            const float* vsrc = Vp + (size_t)(b * Sv + kv + lr) * Ev + hb + lk;
#pragma unroll
            for (int j = 0; j < 16; j += 4)
                *(float4*)&KVs[lr][lk + j] = *(const float4*)(vsrc + j);
        }
        __syncthreads();

        // ---- O += P V (64x64x64) ----
#pragma unroll 16
        for (int kk = 0; kk < 64; kk++) {
            float pa[4], vb[4];
            *(float4*)pa = *(const float4*)&Ps[kk][ty * 4];
            *(float4*)vb = *(const float4*)&KVs[kk][tx * 4];
#pragma unroll
            for (int i = 0; i < 4; i++)
#pragma unroll
                for (int j = 0; j < 4; j++)
                    o[i][j] = fmaf(pa[i], vb[j], o[i][j]);
        }
    }

    // ---- normalize and write to [B, S, E] with col = hb + d ----
#pragma unroll
    for (int i = 0; i < 4; i++) {
        const float inv = 1.f / l_i[i];
        float4 ov;
        ov.x = o[i][0] * inv; ov.y = o[i][1] * inv;
        ov.z = o[i][2] * inv; ov.w = o[i][3] * inv;
        *(float4*)(Op + (size_t)(b * Sv + qb + ty * 4 + i) * Ev + hb + tx * 4) = ov;
    }
}

// ---------------------------------------------------------------------------
extern "C" void kernel_launch(void* const* d_in, const int* in_sizes, int n_in,
                              void* d_out, int out_size)
{
    (void)in_sizes; (void)n_in; (void)out_size;
    const float* query = (const float*)d_in[0];
    const float* key   = (const float*)d_in[1];
    const float* value = (const float*)d_in[2];
    const int*   mask  = (const int*)  d_in[3];
    const float* Wq = (const float*)d_in[4];
    const float* bq = (const float*)d_in[5];
    const float* Wk = (const float*)d_in[6];
    const float* bk = (const float*)d_in[7];
    const float* Wv = (const float*)d_in[8];
    const float* bv = (const float*)d_in[9];
    const float* Wo = (const float*)d_in[10];
    const float* bo = (const float*)d_in[11];
    float* out = (float*)d_out;

    float *qp, *kp, *vp, *ap;
    cudaGetSymbolAddress((void**)&qp, g_q);
    cudaGetSymbolAddress((void**)&kp, g_k);
    cudaGetSymbolAddress((void**)&vp, g_v);
    cudaGetSymbolAddress((void**)&ap, g_attn);

    cudaFuncSetAttribute(flash_attn,
                         cudaFuncAttributeMaxDynamicSharedMemorySize, FA_SMEM);

    const dim3 ggrid(Ev / 128, Mv / 128);  // (8, 32)
    gemm_bias_nt<<<ggrid, 256>>>(query, Wq, bq, qp, Mv, Ev, Ev);
    gemm_bias_nt<<<ggrid, 256>>>(key,   Wk, bk, kp, Mv, Ev, Ev);
    gemm_bias_nt<<<ggrid, 256>>>(value, Wv, bv, vp, Mv, Ev, Ev);

    flash_attn<<<dim3(Sv / 64, Hv, Bv), 256, FA_SMEM>>>(qp, kp, vp, mask, ap);

    gemm_bias_nt<<<ggrid, 256>>>(ap, Wo, bo, out, Mv, Ev, Ev);
}

// round 3
// speedup vs baseline: 1.3668x; 1.3668x over previous
#include <cuda_runtime.h>
#include <cuda_bf16.h>
#include <cstdint>

// Shapes are fixed by the problem.
#define Bv 2
#define Sv 2048
#define Ev 1024
#define Hv 16
#define Dv 64
#define Mv (Bv * Sv) /* 4096 */

// Scratch (allocation-free rule: __device__ globals).
__device__ float g_q[(size_t)Mv * Ev];
__device__ float g_k[(size_t)Mv * Ev];
__device__ float g_v[(size_t)Mv * Ev];
__device__ float g_attn[(size_t)Mv * Ev];
__device__ __nv_bfloat16 g_ah[(size_t)Mv * Ev];
__device__ __nv_bfloat16 g_al[(size_t)Mv * Ev];
__device__ __nv_bfloat16 g_wh[(size_t)Ev * Ev];
__device__ __nv_bfloat16 g_wl[(size_t)Ev * Ev];

// ---------------------------------------------------------------------------
// Family-portable tensor-core helpers (HMMA / LDSM — legal on base sm_103)
// ---------------------------------------------------------------------------
__device__ __forceinline__ uint32_t smem_u32(const void* p) {
    uint32_t a;
    asm("{ .reg .u64 t; cvta.to.shared.u64 t, %1; cvt.u32.u64 %0, t; }"
        : "=r"(a) : "l"(p));
    return a;
}

__device__ __forceinline__ void ldsm_x4(uint32_t* r, uint32_t addr) {
    asm volatile("ldmatrix.sync.aligned.m8n8.x4.shared.b16 {%0,%1,%2,%3}, [%4];"
                 : "=r"(r[0]), "=r"(r[1]), "=r"(r[2]), "=r"(r[3]) : "r"(addr));
}

__device__ __forceinline__ void mma_bf16(float* c, const uint32_t* a, const uint32_t* b) {
    asm volatile(
        "mma.sync.aligned.m16n8k16.row.col.f32.bf16.bf16.f32 "
        "{%0,%1,%2,%3}, {%4,%5,%6,%7}, {%8,%9}, {%0,%1,%2,%3};"
        : "+f"(c[0]), "+f"(c[1]), "+f"(c[2]), "+f"(c[3])
        : "r"(a[0]), "r"(a[1]), "r"(a[2]), "r"(a[3]), "r"(b[0]), "r"(b[1]));
}

// ---------------------------------------------------------------------------
// Split fp32 -> bf16 hi/lo (bf16x3 scheme), float4-vectorized
// ---------------------------------------------------------------------------
__global__ void __launch_bounds__(256)
split_bf16(const float4* __restrict__ x, uint2* __restrict__ hi,
           uint2* __restrict__ lo, int n4)
{
    int i = blockIdx.x * 256 + threadIdx.x;
    if (i >= n4) return;
    const float4 v = x[i];
    float f[4] = {v.x, v.y, v.z, v.w};
    unsigned short h[4], l[4];
#pragma unroll
    for (int j = 0; j < 4; j++) {
        __nv_bfloat16 hb = __float2bfloat16(f[j]);
        __nv_bfloat16 lb = __float2bfloat16(f[j] - __bfloat162float(hb));
        h[j] = __bfloat16_as_ushort(hb);
        l[j] = __bfloat16_as_ushort(lb);
    }
    uint2 ho, loo;
    ho.x  = (uint32_t)h[0] | ((uint32_t)h[1] << 16);
    ho.y  = (uint32_t)h[2] | ((uint32_t)h[3] << 16);
    loo.x = (uint32_t)l[0] | ((uint32_t)l[1] << 16);
    loo.y = (uint32_t)l[2] | ((uint32_t)l[3] << 16);
    hi[i] = ho;
    lo[i] = loo;
}

// ---------------------------------------------------------------------------
// HMMA GEMM: C[M,N] = A[M,K] @ W[N,K]^T + bias, bf16x3 split, fp32 accum.
// M=4096, N=1024, K=1024. 128x128 CTA tile, BK=32, 8 warps (2m x 4n),
// warp tile 64x32, m16n8k16 fragments via ldmatrix.
// Smem row stride 40 bf16 (80B): conflict-free ldmatrix + float4 stores.
// ---------------------------------------------------------------------------
#define GK 1024
#define GN 1024
#define SSTR 40

__global__ void __launch_bounds__(256)
gemm_mma(const __nv_bfloat16* __restrict__ Ahg, const __nv_bfloat16* __restrict__ Alg,
         const __nv_bfloat16* __restrict__ Bhg, const __nv_bfloat16* __restrict__ Blg,
         const float* __restrict__ bias, float* __restrict__ C)
{
    __shared__ __nv_bfloat16 Ah_s[128 * SSTR];
    __shared__ __nv_bfloat16 Al_s[128 * SSTR];
    __shared__ __nv_bfloat16 Bh_s[128 * SSTR];
    __shared__ __nv_bfloat16 Bl_s[128 * SSTR];

    const int tid  = threadIdx.x;
    const int lane = tid & 31;
    const int wid  = tid >> 5;
    const int wm   = (wid & 1) * 64;   // warp m-base within tile
    const int wn   = (wid >> 1) * 32;  // warp n-base within tile
    const int bm = blockIdx.y << 7;
    const int bn = blockIdx.x << 7;

    const uint32_t ah_b = smem_u32(Ah_s);
    const uint32_t al_b = smem_u32(Al_s);
    const uint32_t bh_b = smem_u32(Bh_s);
    const uint32_t bl_b = smem_u32(Bl_s);

    // gmem->smem slice: 512 float4-chunks per array; thread does chunks tid, tid+256
    const int r0 = tid >> 2;             // rows 0..63
    const int c8 = (tid & 3) * 8;        // col offset in bf16 (0,8,16,24)

    float acc[4][4][4];
#pragma unroll
    for (int i = 0; i < 4; i++)
#pragma unroll
        for (int j = 0; j < 4; j++)
#pragma unroll
            for (int q = 0; q < 4; q++) acc[i][j][q] = 0.f;

    // ldmatrix smem byte addresses (constant across k-loop except ks offset)
    // A: row = wm + i*16 + (lane&15), col = ks*16 + (lane>>4)*8
    // B: g = lane>>3; row n = wn + j*16 + (lane&7) + (g>>1)*8, col = ks*16 + (g&1)*8
    const int a_row = wm + (lane & 15);
    const int a_col = (lane >> 4) * 8;
    const int g     = lane >> 3;
    const int b_row = wn + (lane & 7) + (g >> 1) * 8;
    const int b_col = (g & 1) * 8;

    for (int kt = 0; kt < GK; kt += 32) {
        // prefetch gmem to regs
        float4 va0, va1, vb0, vb1, vc0, vc1, vd0, vd1;
        {
            const size_t o0 = (size_t)(bm + r0) * GK + kt + c8;
            const size_t o1 = (size_t)(bm + r0 + 64) * GK + kt + c8;
            const size_t p0 = (size_t)(bn + r0) * GK + kt + c8;
            const size_t p1 = (size_t)(bn + r0 + 64) * GK + kt + c8;
            va0 = *(const float4*)(Ahg + o0); va1 = *(const float4*)(Ahg + o1);
            vb0 = *(const float4*)(Alg + o0); vb1 = *(const float4*)(Alg + o1);
            vc0 = *(const float4*)(Bhg + p0); vc1 = *(const float4*)(Bhg + p1);
            vd0 = *(const float4*)(Blg + p0); vd1 = *(const float4*)(Blg + p1);
        }
        __syncthreads();  // previous iter's smem reads done
        *(float4*)&Ah_s[r0 * SSTR + c8]        = va0;
        *(float4*)&Ah_s[(r0 + 64) * SSTR + c8] = va1;
        *(float4*)&Al_s[r0 * SSTR + c8]        = vb0;
        *(float4*)&Al_s[(r0 + 64) * SSTR + c8] = vb1;
        *(float4*)&Bh_s[r0 * SSTR + c8]        = vc0;
        *(float4*)&Bh_s[(r0 + 64) * SSTR + c8] = vc1;
        *(float4*)&Bl_s[r0 * SSTR + c8]        = vd0;
        *(float4*)&Bl_s[(r0 + 64) * SSTR + c8] = vd1;
        __syncthreads();

#pragma unroll
        for (int ks = 0; ks < 2; ks++) {
            uint32_t afh[4][4], afl[4][4];
#pragma unroll
            for (int i = 0; i < 4; i++) {
                const uint32_t off = ((a_row + i * 16) * SSTR + ks * 16 + a_col) * 2;
                ldsm_x4(afh[i], ah_b + off);
                ldsm_x4(afl[i], al_b + off);
            }
            uint32_t bfh[4][2], bfl[4][2];
#pragma unroll
            for (int j = 0; j < 2; j++) {
                const uint32_t off = ((b_row + j * 16) * SSTR + ks * 16 + b_col) * 2;
                uint32_t r[4];
                ldsm_x4(r, bh_b + off);
                bfh[2 * j][0] = r[0]; bfh[2 * j][1] = r[1];
                bfh[2 * j + 1][0] = r[2]; bfh[2 * j + 1][1] = r[3];
                ldsm_x4(r, bl_b + off);
                bfl[2 * j][0] = r[0]; bfl[2 * j][1] = r[1];
                bfl[2 * j + 1][0] = r[2]; bfl[2 * j + 1][1] = r[3];
            }
#pragma unroll
            for (int i = 0; i < 4; i++)
#pragma unroll
                for (int j = 0; j < 4; j++) {
                    mma_bf16(acc[i][j], afh[i], bfh[j]);
                    mma_bf16(acc[i][j], afh[i], bfl[j]);
                    mma_bf16(acc[i][j], afl[i], bfh[j]);
                }
        }
    }

    // epilogue: c frag rows = lane>>2 (+8), cols = (lane&3)*2 (+1)
#pragma unroll
    for (int i = 0; i < 4; i++) {
        const int grow = bm + wm + i * 16 + (lane >> 2);
#pragma unroll
        for (int j = 0; j < 4; j++) {
            const int gcol = bn + wn + j * 8 + (lane & 3) * 2;
            const float b0 = bias[gcol], b1 = bias[gcol + 1];
            float2 v0, v1;
            v0.x = acc[i][j][0] + b0; v0.y = acc[i][j][1] + b1;
            v1.x = acc[i][j][2] + b0; v1.y = acc[i][j][3] + b1;
            *(float2*)(C + (size_t)grow * GN + gcol) = v0;
            *(float2*)(C + (size_t)(grow + 8) * GN + gcol) = v1;
        }
    }
}

// ---------------------------------------------------------------------------
// Flash attention, fp32, online softmax (unchanged from passing R1 kernel).
// ---------------------------------------------------------------------------
#define FSTR 68
#define FA_SMEM (3 * 64 * FSTR * 4)

__global__ void __launch_bounds__(256)
flash_attn(const float* __restrict__ Qp, const float* __restrict__ Kp,
           const float* __restrict__ Vp, const int* __restrict__ mask,
           float* __restrict__ Op)
{
    extern __shared__ float sm[];
    float (*Qs)[FSTR]  = (float(*)[FSTR])(sm);
    float (*KVs)[FSTR] = (float(*)[FSTR])(sm + 64 * FSTR);
    float (*Ps)[FSTR]  = (float(*)[FSTR])(sm + 2 * 64 * FSTR);

    const int tid = threadIdx.x;
    const int tx = tid & 15;
    const int ty = tid >> 4;
    const int b  = blockIdx.z;
    const int h  = blockIdx.y;
    const int qb = blockIdx.x << 6;
    const int hb = h << 6;

    const int lr = tid & 63;
    const int lk = (tid >> 6) << 4;

    {
        const float* src = Qp + (size_t)(b * Sv + qb + lr) * Ev + hb + lk;
#pragma unroll
        for (int j = 0; j < 16; j += 4) {
            const float4 v = *(const float4*)(src + j);
            Qs[lk + j + 0][lr] = v.x; Qs[lk + j + 1][lr] = v.y;
            Qs[lk + j + 2][lr] = v.z; Qs[lk + j + 3][lr] = v.w;
        }
    }

    float m_i[4], l_i[4], o[4][4];
#pragma unroll
    for (int i = 0; i < 4; i++) {
        m_i[i] = -1e30f; l_i[i] = 0.f;
#pragma unroll
        for (int j = 0; j < 4; j++) o[i][j] = 0.f;
    }

    for (int kv = 0; kv < Sv; kv += 64) {
        const float* ksrc = Kp + (size_t)(b * Sv + kv + lr) * Ev + hb + lk;
        float4 kreg[4];
#pragma unroll
        for (int j = 0; j < 4; j++) kreg[j] = *(const float4*)(ksrc + 4 * j);
        __syncthreads();
#pragma unroll
        for (int j = 0; j < 4; j++) {
            KVs[lk + 4 * j + 0][lr] = kreg[j].x; KVs[lk + 4 * j + 1][lr] = kreg[j].y;
            KVs[lk + 4 * j + 2][lr] = kreg[j].z; KVs[lk + 4 * j + 3][lr] = kreg[j].w;
        }
        __syncthreads();

        float s[4][4];
#pragma unroll
        for (int i = 0; i < 4; i++)
#pragma unroll
            for (int j = 0; j < 4; j++) s[i][j] = 0.f;
#pragma unroll 16
        for (int k = 0; k < 64; k++) {
            float qa[4], kb[4];
            *(float4*)qa = *(const float4*)&Qs[k][ty * 4];
            *(float4*)kb = *(const float4*)&KVs[k][tx * 4];
#pragma unroll
            for (int i = 0; i < 4; i++)
#pragma unroll
                for (int j = 0; j < 4; j++)
                    s[i][j] = fmaf(qa[i], kb[j], s[i][j]);
        }

#pragma unroll
        for (int i = 0; i < 4; i++) {
            const int4 mk = *(const int4*)(mask +
                (size_t)(b * Sv + qb + ty * 4 + i) * Sv + kv + tx * 4);
            s[i][0] = mk.x ? s[i][0] * 0.125f : -1e9f;
            s[i][1] = mk.y ? s[i][1] * 0.125f : -1e9f;
            s[i][2] = mk.z ? s[i][2] * 0.125f : -1e9f;
            s[i][3] = mk.w ? s[i][3] * 0.125f : -1e9f;

            float mx = fmaxf(fmaxf(s[i][0], s[i][1]), fmaxf(s[i][2], s[i][3]));
#pragma unroll
            for (int off = 8; off; off >>= 1)
                mx = fmaxf(mx, __shfl_xor_sync(0xffffffffu, mx, off));
            const float mn   = fmaxf(m_i[i], mx);
            const float corr = __expf(m_i[i] - mn);
            m_i[i] = mn;

            float rs = 0.f;
#pragma unroll
            for (int j = 0; j < 4; j++) {
                s[i][j] = __expf(s[i][j] - mn);
                rs += s[i][j];
            }
#pragma unroll
            for (int off = 8; off; off >>= 1)
                rs += __shfl_xor_sync(0xffffffffu, rs, off);
            l_i[i] = l_i[i] * corr + rs;
#pragma unroll
            for (int j = 0; j < 4; j++) o[i][j] *= corr;
        }

        __syncthreads();

#pragma unroll
        for (int i = 0; i < 4; i++)
#pragma unroll
            for (int j = 0; j < 4; j++)
                Ps[tx * 4 + j][ty * 4 + i] = s[i][j];
        {
            const float* vsrc = Vp + (size_t)(b * Sv + kv + lr) * Ev + hb + lk;
#pragma unroll
            for (int j = 0; j < 16; j += 4)
                *(float4*)&KVs[lr][lk + j] = *(const float4*)(vsrc + j);
        }
        __syncthreads();

#pragma unroll 16
        for (int kk = 0; kk < 64; kk++) {
            float pa[4], vb[4];
            *(float4*)pa = *(const float4*)&Ps[kk][ty * 4];
            *(float4*)vb = *(const float4*)&KVs[kk][tx * 4];
#pragma unroll
            for (int i = 0; i < 4; i++)
#pragma unroll
                for (int j = 0; j < 4; j++)
                    o[i][j] = fmaf(pa[i], vb[j], o[i][j]);
        }
    }

#pragma unroll
    for (int i = 0; i < 4; i++) {
        const float inv = 1.f / l_i[i];
        float4 ov;
        ov.x = o[i][0] * inv; ov.y = o[i][1] * inv;
        ov.z = o[i][2] * inv; ov.w = o[i][3] * inv;
        *(float4*)(Op + (size_t)(b * Sv + qb + ty * 4 + i) * Ev + hb + tx * 4) = ov;
    }
}

// ---------------------------------------------------------------------------
extern "C" void kernel_launch(void* const* d_in, const int* in_sizes, int n_in,
                              void* d_out, int out_size)
{
    (void)in_sizes; (void)n_in; (void)out_size;
    const float* query = (const float*)d_in[0];
    const float* key   = (const float*)d_in[1];
    const float* value = (const float*)d_in[2];
    const int*   mask  = (const int*)  d_in[3];
    const float* Wq = (const float*)d_in[4];
    const float* bq = (const float*)d_in[5];
    const float* Wk = (const float*)d_in[6];
    const float* bk = (const float*)d_in[7];
    const float* Wv = (const float*)d_in[8];
    const float* bv = (const float*)d_in[9];
    const float* Wo = (const float*)d_in[10];
    const float* bo = (const float*)d_in[11];
    float* out = (float*)d_out;

    float *qp, *kp, *vp, *ap;
    __nv_bfloat16 *ah, *al, *wh, *wl;
    cudaGetSymbolAddress((void**)&qp, g_q);
    cudaGetSymbolAddress((void**)&kp, g_k);
    cudaGetSymbolAddress((void**)&vp, g_v);
    cudaGetSymbolAddress((void**)&ap, g_attn);
    cudaGetSymbolAddress((void**)&ah, g_ah);
    cudaGetSymbolAddress((void**)&al, g_al);
    cudaGetSymbolAddress((void**)&wh, g_wh);
    cudaGetSymbolAddress((void**)&wl, g_wl);

    cudaFuncSetAttribute(flash_attn,
                         cudaFuncAttributeMaxDynamicSharedMemorySize, FA_SMEM);

    const int nA4 = (Mv * Ev) / 4;
    const int nW4 = (Ev * Ev) / 4;
    const dim3 ggrid(GN / 128, Mv / 128);  // (8, 32)

    // Q projection
    split_bf16<<<nA4 / 256, 256>>>((const float4*)query, (uint2*)ah, (uint2*)al, nA4);
    split_bf16<<<nW4 / 256, 256>>>((const float4*)Wq, (uint2*)wh, (uint2*)wl, nW4);
    gemm_mma<<<ggrid, 256>>>(ah, al, wh, wl, bq, qp);
    // K projection
    split_bf16<<<nA4 / 256, 256>>>((const float4*)key, (uint2*)ah, (uint2*)al, nA4);
    split_bf16<<<nW4 / 256, 256>>>((const float4*)Wk, (uint2*)wh, (uint2*)wl, nW4);
    gemm_mma<<<ggrid, 256>>>(ah, al, wh, wl, bk, kp);
    // V projection
    split_bf16<<<nA4 / 256, 256>>>((const float4*)value, (uint2*)ah, (uint2*)al, nA4);
    split_bf16<<<nW4 / 256, 256>>>((const float4*)Wv, (uint2*)wh, (uint2*)wl, nW4);
    gemm_mma<<<ggrid, 256>>>(ah, al, wh, wl, bv, vp);

    // Attention
    flash_attn<<<dim3(Sv / 64, Hv, Bv), 256, FA_SMEM>>>(qp, kp, vp, mask, ap);

    // Output projection
    split_bf16<<<nA4 / 256, 256>>>((const float4*)ap, (uint2*)ah, (uint2*)al, nA4);
    split_bf16<<<nW4 / 256, 256>>>((const float4*)Wo, (uint2*)wh, (uint2*)wl, nW4);
    gemm_mma<<<ggrid, 256>>>(ah, al, wh, wl, bo, out);
}

// round 4
// speedup vs baseline: 2.5098x; 1.8363x over previous
#include <cuda_runtime.h>
#include <cuda_fp16.h>
#include <cstdint>

// Shapes are fixed by the problem.
#define Bv 2
#define Sv 2048
#define Ev 1024
#define Hv 16
#define Dv 64
#define Mv (Bv * Sv) /* 4096 */

// Scratch (allocation-free rule: __device__ globals), all fp16 hi/lo pairs.
__device__ __half g_xh[(size_t)Mv * Ev];  // activation split (query/key/value, reused)
__device__ __half g_xl[(size_t)Mv * Ev];
__device__ __half g_wh[(size_t)Ev * Ev];  // weight split (reused)
__device__ __half g_wl[(size_t)Ev * Ev];
__device__ __half g_qh[(size_t)Mv * Ev];
__device__ __half g_ql[(size_t)Mv * Ev];
__device__ __half g_kh[(size_t)Mv * Ev];
__device__ __half g_kl[(size_t)Mv * Ev];
__device__ __half g_vh[(size_t)Mv * Ev];
__device__ __half g_vl[(size_t)Mv * Ev];
__device__ __half g_oh[(size_t)Mv * Ev];
__device__ __half g_ol[(size_t)Mv * Ev];

// ---------------------------------------------------------------------------
// Family-portable tensor-core helpers (HMMA / LDSM — legal on base sm_103)
// ---------------------------------------------------------------------------
__device__ __forceinline__ uint32_t smem_u32(const void* p) {
    uint32_t a;
    asm("{ .reg .u64 t; cvta.to.shared.u64 t, %1; cvt.u32.u64 %0, t; }"
        : "=r"(a) : "l"(p));
    return a;
}

__device__ __forceinline__ void ldsm_x4(uint32_t* r, uint32_t addr) {
    asm volatile("ldmatrix.sync.aligned.m8n8.x4.shared.b16 {%0,%1,%2,%3}, [%4];"
                 : "=r"(r[0]), "=r"(r[1]), "=r"(r[2]), "=r"(r[3]) : "r"(addr));
}

__device__ __forceinline__ void ldsm_x4_t(uint32_t* r, uint32_t addr) {
    asm volatile("ldmatrix.sync.aligned.m8n8.x4.trans.shared.b16 {%0,%1,%2,%3}, [%4];"
                 : "=r"(r[0]), "=r"(r[1]), "=r"(r[2]), "=r"(r[3]) : "r"(addr));
}

__device__ __forceinline__ void mma_f16(float* c, const uint32_t* a, const uint32_t* b) {
    asm volatile(
        "mma.sync.aligned.m16n8k16.row.col.f32.f16.f16.f32 "
        "{%0,%1,%2,%3}, {%4,%5,%6,%7}, {%8,%9}, {%0,%1,%2,%3};"
        : "+f"(c[0]), "+f"(c[1]), "+f"(c[2]), "+f"(c[3])
        : "r"(a[0]), "r"(a[1]), "r"(a[2]), "r"(a[3]), "r"(b[0]), "r"(b[1]));
}

__device__ __forceinline__ uint32_t h2u(__half2 v) {
    return *reinterpret_cast<uint32_t*>(&v);
}

// ---------------------------------------------------------------------------
// Split fp32 -> fp16 hi/lo, float4-vectorized
// ---------------------------------------------------------------------------
__global__ void __launch_bounds__(256)
split_f16(const float4* __restrict__ x, uint2* __restrict__ hi,
          uint2* __restrict__ lo, int n4)
{
    int i = blockIdx.x * 256 + threadIdx.x;
    if (i >= n4) return;
    const float4 v = x[i];
    float f[4] = {v.x, v.y, v.z, v.w};
    unsigned short h[4], l[4];
#pragma unroll
    for (int j = 0; j < 4; j++) {
        __half hb = __float2half_rn(f[j]);
        __half lb = __float2half_rn(f[j] - __half2float(hb));
        h[j] = __half_as_ushort(hb);
        l[j] = __half_as_ushort(lb);
    }
    uint2 ho, loo;
    ho.x  = (uint32_t)h[0] | ((uint32_t)h[1] << 16);
    ho.y  = (uint32_t)h[2] | ((uint32_t)h[3] << 16);
    loo.x = (uint32_t)l[0] | ((uint32_t)l[1] << 16);
    loo.y = (uint32_t)l[2] | ((uint32_t)l[3] << 16);
    hi[i] = ho;
    lo[i] = loo;
}

// ---------------------------------------------------------------------------
// HMMA GEMM: C[M,N] = A[M,K] @ W[N,K]^T + bias, fp16x3 split, fp32 accum.
// Same proven structure as R3 (bf16 -> fp16 dtype swap). Epilogue writes
// either fp32 (O projection) or fp16 hi/lo (Q/K/V projections).
// ---------------------------------------------------------------------------
#define GK 1024
#define GN 1024
#define SSTR 40

__global__ void __launch_bounds__(256)
gemm_f16(const __half* __restrict__ Ahg, const __half* __restrict__ Alg,
         const __half* __restrict__ Bhg, const __half* __restrict__ Blg,
         const float* __restrict__ bias,
         float* __restrict__ Cf, __half* __restrict__ Ch, __half* __restrict__ Cl,
         int half_out)
{
    __shared__ __half Ah_s[128 * SSTR];
    __shared__ __half Al_s[128 * SSTR];
    __shared__ __half Bh_s[128 * SSTR];
    __shared__ __half Bl_s[128 * SSTR];

    const int tid  = threadIdx.x;
    const int lane = tid & 31;
    const int wid  = tid >> 5;
    const int wm   = (wid & 1) * 64;
    const int wn   = (wid >> 1) * 32;
    const int bm = blockIdx.y << 7;
    const int bn = blockIdx.x << 7;

    const uint32_t ah_b = smem_u32(Ah_s);
    const uint32_t al_b = smem_u32(Al_s);
    const uint32_t bh_b = smem_u32(Bh_s);
    const uint32_t bl_b = smem_u32(Bl_s);

    const int r0 = tid >> 2;
    const int c8 = (tid & 3) * 8;

    float acc[4][4][4];
#pragma unroll
    for (int i = 0; i < 4; i++)
#pragma unroll
        for (int j = 0; j < 4; j++)
#pragma unroll
            for (int q = 0; q < 4; q++) acc[i][j][q] = 0.f;

    const int a_row = wm + (lane & 15);
    const int a_col = (lane >> 4) * 8;
    const int g     = lane >> 3;
    const int b_row = wn + (lane & 7) + (g >> 1) * 8;
    const int b_col = (g & 1) * 8;

    for (int kt = 0; kt < GK; kt += 32) {
        float4 va0, va1, vb0, vb1, vc0, vc1, vd0, vd1;
        {
            const size_t o0 = (size_t)(bm + r0) * GK + kt + c8;
            const size_t o1 = (size_t)(bm + r0 + 64) * GK + kt + c8;
            const size_t p0 = (size_t)(bn + r0) * GK + kt + c8;
            const size_t p1 = (size_t)(bn + r0 + 64) * GK + kt + c8;
            va0 = *(const float4*)(Ahg + o0); va1 = *(const float4*)(Ahg + o1);
            vb0 = *(const float4*)(Alg + o0); vb1 = *(const float4*)(Alg + o1);
            vc0 = *(const float4*)(Bhg + p0); vc1 = *(const float4*)(Bhg + p1);
            vd0 = *(const float4*)(Blg + p0); vd1 = *(const float4*)(Blg + p1);
        }
        __syncthreads();
        *(float4*)&Ah_s[r0 * SSTR + c8]        = va0;
        *(float4*)&Ah_s[(r0 + 64) * SSTR + c8] = va1;
        *(float4*)&Al_s[r0 * SSTR + c8]        = vb0;
        *(float4*)&Al_s[(r0 + 64) * SSTR + c8] = vb1;
        *(float4*)&Bh_s[r0 * SSTR + c8]        = vc0;
        *(float4*)&Bh_s[(r0 + 64) * SSTR + c8] = vc1;
        *(float4*)&Bl_s[r0 * SSTR + c8]        = vd0;
        *(float4*)&Bl_s[(r0 + 64) * SSTR + c8] = vd1;
        __syncthreads();

#pragma unroll
        for (int ks = 0; ks < 2; ks++) {
            uint32_t afh[4][4], afl[4][4];
#pragma unroll
            for (int i = 0; i < 4; i++) {
                const uint32_t off = ((a_row + i * 16) * SSTR + ks * 16 + a_col) * 2;
                ldsm_x4(afh[i], ah_b + off);
                ldsm_x4(afl[i], al_b + off);
            }
            uint32_t bfh[4][2], bfl[4][2];
#pragma unroll
            for (int j = 0; j < 2; j++) {
                const uint32_t off = ((b_row + j * 16) * SSTR + ks * 16 + b_col) * 2;
                uint32_t r[4];
                ldsm_x4(r, bh_b + off);
                bfh[2 * j][0] = r[0]; bfh[2 * j][1] = r[1];
                bfh[2 * j + 1][0] = r[2]; bfh[2 * j + 1][1] = r[3];
                ldsm_x4(r, bl_b + off);
                bfl[2 * j][0] = r[0]; bfl[2 * j][1] = r[1];
                bfl[2 * j + 1][0] = r[2]; bfl[2 * j + 1][1] = r[3];
            }
#pragma unroll
            for (int i = 0; i < 4; i++)
#pragma unroll
                for (int j = 0; j < 4; j++) {
                    mma_f16(acc[i][j], afh[i], bfh[j]);
                    mma_f16(acc[i][j], afh[i], bfl[j]);
                    mma_f16(acc[i][j], afl[i], bfh[j]);
                }
        }
    }

#pragma unroll
    for (int i = 0; i < 4; i++) {
        const int grow = bm + wm + i * 16 + (lane >> 2);
#pragma unroll
        for (int j = 0; j < 4; j++) {
            const int gcol = bn + wn + j * 8 + (lane & 3) * 2;
            const float b0 = bias[gcol], b1 = bias[gcol + 1];
            const float v00 = acc[i][j][0] + b0, v01 = acc[i][j][1] + b1;
            const float v10 = acc[i][j][2] + b0, v11 = acc[i][j][3] + b1;
            if (half_out) {
                const __half h00 = __float2half_rn(v00), h01 = __float2half_rn(v01);
                const __half h10 = __float2half_rn(v10), h11 = __float2half_rn(v11);
                const __half l00 = __float2half_rn(v00 - __half2float(h00));
                const __half l01 = __float2half_rn(v01 - __half2float(h01));
                const __half l10 = __float2half_rn(v10 - __half2float(h10));
                const __half l11 = __float2half_rn(v11 - __half2float(h11));
                *(__half2*)(Ch + (size_t)grow * GN + gcol)       = __halves2half2(h00, h01);
                *(__half2*)(Ch + (size_t)(grow + 8) * GN + gcol) = __halves2half2(h10, h11);
                *(__half2*)(Cl + (size_t)grow * GN + gcol)       = __halves2half2(l00, l01);
                *(__half2*)(Cl + (size_t)(grow + 8) * GN + gcol) = __halves2half2(l10, l11);
            } else {
                float2 v0, v1;
                v0.x = v00; v0.y = v01;
                v1.x = v10; v1.y = v11;
                *(float2*)(Cf + (size_t)grow * GN + gcol) = v0;
                *(float2*)(Cf + (size_t)(grow + 8) * GN + gcol) = v1;
            }
        }
    }
}

// ---------------------------------------------------------------------------
// Flash attention on HMMA, split-fp16, online softmax.
// CTA: 128 threads = 4 warps, q-tile 64 (16 rows/warp), kv chunk 64.
// Q fragments register-resident across the KV loop. K via non-trans ldmatrix,
// V via ldmatrix.trans from natural [kv][d] layout.
// Grid: (S/64, H, B) = (32, 16, 2).
// ---------------------------------------------------------------------------
#define KSTR 72

__global__ void __launch_bounds__(128)
flash_mma(const __half* __restrict__ Qh, const __half* __restrict__ Ql,
          const __half* __restrict__ Kh, const __half* __restrict__ Kl,
          const __half* __restrict__ Vh, const __half* __restrict__ Vl,
          const int* __restrict__ mask,
          __half* __restrict__ Oh, __half* __restrict__ Ol)
{
    __shared__ __half sKh[64 * KSTR], sKl[64 * KSTR];
    __shared__ __half sVh[64 * KSTR], sVl[64 * KSTR];

    const int tid = threadIdx.x, lane = tid & 31, warp = tid >> 5;
    const int b = blockIdx.z, h = blockIdx.y;
    const int qb = blockIdx.x << 6, hb = h << 6;

    const uint32_t kh_b = smem_u32(sKh), kl_b = smem_u32(sKl);
    const uint32_t vh_b = smem_u32(sVh), vl_b = smem_u32(sVl);

    const int sr = tid >> 3;          // staging row (16 per pass, x4 passes)
    const int sj = (tid & 7) * 8;     // halves column offset

    // ---- stage Q (once) into sKh/sKl, pull A-fragments to registers ----
#pragma unroll
    for (int i = 0; i < 4; i++) {
        const int r = sr + i * 16;
        const size_t gq = (size_t)(b * Sv + qb + r) * Ev + hb + sj;
        *(uint4*)(sKh + r * KSTR + sj) = *(const uint4*)(Qh + gq);
        *(uint4*)(sKl + r * KSTR + sj) = *(const uint4*)(Ql + gq);
    }
    __syncthreads();
    uint32_t qfh[4][4], qfl[4][4];
    {
        const int ar = warp * 16 + (lane & 15);
        const int ac = (lane >> 4) * 8;
#pragma unroll
        for (int kf = 0; kf < 4; kf++) {
            const uint32_t off = (uint32_t)(ar * KSTR + kf * 16 + ac) * 2;
            ldsm_x4(qfh[kf], kh_b + off);
            ldsm_x4(qfl[kf], kl_b + off);
        }
    }

    float m0 = -1e30f, m1 = -1e30f, l0 = 0.f, l1 = 0.f;
    float o[8][4];
#pragma unroll
    for (int n = 0; n < 8; n++)
#pragma unroll
        for (int q = 0; q < 4; q++) o[n][q] = 0.f;

    const int r0g = b * Sv + qb + warp * 16 + (lane >> 2);  // global row (incl. b*Sv)
    const int* mr0 = mask + (size_t)r0g * Sv;
    const int* mr1 = mask + (size_t)(r0g + 8) * Sv;
    const int mc = (lane & 3) * 2;

    // K (non-trans B-frag) address components: storage [kv][d]
    const int b_r = (lane & 7) + (lane >> 4) * 8;       // + u*16  (kv)
    const int b_c = ((lane >> 3) & 1) * 8;              // + kf*16 (d)
    // V (trans B-frag): storage [kv][d]; row=kv(k), col=d(n)
    const int v_r = (lane & 7) + ((lane >> 3) & 1) * 8; // + kf*16 (kv)
    const int v_c = (lane >> 4) * 8;                    // + u*16  (d)

    for (int kv = 0; kv < Sv; kv += 64) {
        __syncthreads();  // previous iteration finished reading smem
#pragma unroll
        for (int i = 0; i < 4; i++) {
            const int r = sr + i * 16;
            const size_t gk = (size_t)(b * Sv + kv + r) * Ev + hb + sj;
            *(uint4*)(sKh + r * KSTR + sj) = *(const uint4*)(Kh + gk);
            *(uint4*)(sKl + r * KSTR + sj) = *(const uint4*)(Kl + gk);
            *(uint4*)(sVh + r * KSTR + sj) = *(const uint4*)(Vh + gk);
            *(uint4*)(sVl + r * KSTR + sj) = *(const uint4*)(Vl + gk);
        }
        __syncthreads();

        // ---- S = Q K^T (16x64 per warp), 3 split passes ----
        float s[8][4];
#pragma unroll
        for (int n = 0; n < 8; n++)
#pragma unroll
            for (int q = 0; q < 4; q++) s[n][q] = 0.f;

#pragma unroll
        for (int kf = 0; kf < 4; kf++) {
            uint32_t bh[8][2], bl[8][2];
#pragma unroll
            for (int u = 0; u < 4; u++) {
                const uint32_t off =
                    (uint32_t)((b_r + u * 16) * KSTR + b_c + kf * 16) * 2;
                uint32_t t[4];
                ldsm_x4(t, kh_b + off);
                bh[2 * u][0] = t[0]; bh[2 * u][1] = t[1];
                bh[2 * u + 1][0] = t[2]; bh[2 * u + 1][1] = t[3];
                ldsm_x4(t, kl_b + off);
                bl[2 * u][0] = t[0]; bl[2 * u][1] = t[1];
                bl[2 * u + 1][0] = t[2]; bl[2 * u + 1][1] = t[3];
            }
#pragma unroll
            for (int n = 0; n < 8; n++) {
                mma_f16(s[n], qfh[kf], bh[n]);
                mma_f16(s[n], qfh[kf], bl[n]);
                mma_f16(s[n], qfl[kf], bh[n]);
            }
        }

        // ---- mask + scale + online softmax (rows r0g, r0g+8) ----
        float mx0 = -1e30f, mx1 = -1e30f;
#pragma unroll
        for (int n = 0; n < 8; n++) {
            const int c = kv + n * 8 + mc;
            const int2 k0 = *(const int2*)(mr0 + c);
            const int2 k1 = *(const int2*)(mr1 + c);
            s[n][0] = k0.x ? s[n][0] * 0.125f : -1e9f;
            s[n][1] = k0.y ? s[n][1] * 0.125f : -1e9f;
            s[n][2] = k1.x ? s[n][2] * 0.125f : -1e9f;
            s[n][3] = k1.y ? s[n][3] * 0.125f : -1e9f;
            mx0 = fmaxf(mx0, fmaxf(s[n][0], s[n][1]));
            mx1 = fmaxf(mx1, fmaxf(s[n][2], s[n][3]));
        }
        mx0 = fmaxf(mx0, __shfl_xor_sync(0xffffffffu, mx0, 1));
        mx0 = fmaxf(mx0, __shfl_xor_sync(0xffffffffu, mx0, 2));
        mx1 = fmaxf(mx1, __shfl_xor_sync(0xffffffffu, mx1, 1));
        mx1 = fmaxf(mx1, __shfl_xor_sync(0xffffffffu, mx1, 2));
        const float mn0 = fmaxf(m0, mx0), mn1 = fmaxf(m1, mx1);
        const float c0 = __expf(m0 - mn0), c1 = __expf(m1 - mn1);
        m0 = mn0; m1 = mn1;

        float rs0 = 0.f, rs1 = 0.f;
#pragma unroll
        for (int n = 0; n < 8; n++) {
            s[n][0] = __expf(s[n][0] - mn0); s[n][1] = __expf(s[n][1] - mn0);
            s[n][2] = __expf(s[n][2] - mn1); s[n][3] = __expf(s[n][3] - mn1);
            rs0 += s[n][0] + s[n][1];
            rs1 += s[n][2] + s[n][3];
            o[n][0] *= c0; o[n][1] *= c0; o[n][2] *= c1; o[n][3] *= c1;
        }
        rs0 += __shfl_xor_sync(0xffffffffu, rs0, 1);
        rs0 += __shfl_xor_sync(0xffffffffu, rs0, 2);
        rs1 += __shfl_xor_sync(0xffffffffu, rs1, 1);
        rs1 += __shfl_xor_sync(0xffffffffu, rs1, 2);
        l0 = l0 * c0 + rs0;
        l1 = l1 * c1 + rs1;

        // ---- pack P into fp16 A-fragments ----
        uint32_t pf[4][4];
#pragma unroll
        for (int kf = 0; kf < 4; kf++) {
            const int n0 = 2 * kf, n1 = 2 * kf + 1;
            pf[kf][0] = h2u(__halves2half2(__float2half_rn(s[n0][0]), __float2half_rn(s[n0][1])));
            pf[kf][1] = h2u(__halves2half2(__float2half_rn(s[n0][2]), __float2half_rn(s[n0][3])));
            pf[kf][2] = h2u(__halves2half2(__float2half_rn(s[n1][0]), __float2half_rn(s[n1][1])));
            pf[kf][3] = h2u(__halves2half2(__float2half_rn(s[n1][2]), __float2half_rn(s[n1][3])));
        }

        // ---- O += P V (2 split passes), V frags via ldmatrix.trans ----
#pragma unroll
        for (int kf = 0; kf < 4; kf++) {
            uint32_t wh[8][2], wl[8][2];
#pragma unroll
            for (int u = 0; u < 4; u++) {
                const uint32_t off =
                    (uint32_t)((v_r + kf * 16) * KSTR + v_c + u * 16) * 2;
                uint32_t t[4];
                ldsm_x4_t(t, vh_b + off);
                wh[2 * u][0] = t[0]; wh[2 * u][1] = t[1];
                wh[2 * u + 1][0] = t[2]; wh[2 * u + 1][1] = t[3];
                ldsm_x4_t(t, vl_b + off);
                wl[2 * u][0] = t[0]; wl[2 * u][1] = t[1];
                wl[2 * u + 1][0] = t[2]; wl[2 * u + 1][1] = t[3];
            }
#pragma unroll
            for (int n = 0; n < 8; n++) {
                mma_f16(o[n], pf[kf], wh[n]);
                mma_f16(o[n], pf[kf], wl[n]);
            }
        }
    }

    // ---- normalize, split fp16 hi/lo, write ----
    const float i0 = 1.f / l0, i1 = 1.f / l1;
#pragma unroll
    for (int n = 0; n < 8; n++) {
        const int col = hb + n * 8 + mc;
        const float v00 = o[n][0] * i0, v01 = o[n][1] * i0;
        const float v10 = o[n][2] * i1, v11 = o[n][3] * i1;
        const __half h00 = __float2half_rn(v00), h01 = __float2half_rn(v01);
        const __half h10 = __float2half_rn(v10), h11 = __float2half_rn(v11);
        const __half q00 = __float2half_rn(v00 - __half2float(h00));
        const __half q01 = __float2half_rn(v01 - __half2float(h01));
        const __half q10 = __float2half_rn(v10 - __half2float(h10));
        const __half q11 = __float2half_rn(v11 - __half2float(h11));
        *(__half2*)(Oh + (size_t)r0g * Ev + col)       = __halves2half2(h00, h01);
        *(__half2*)(Oh + (size_t)(r0g + 8) * Ev + col) = __halves2half2(h10, h11);
        *(__half2*)(Ol + (size_t)r0g * Ev + col)       = __halves2half2(q00, q01);
        *(__half2*)(Ol + (size_t)(r0g + 8) * Ev + col) = __halves2half2(q10, q11);
    }
}

// ---------------------------------------------------------------------------
extern "C" void kernel_launch(void* const* d_in, const int* in_sizes, int n_in,
                              void* d_out, int out_size)
{
    (void)in_sizes; (void)n_in; (void)out_size;
    const float* query = (const float*)d_in[0];
    const float* key   = (const float*)d_in[1];
    const float* value = (const float*)d_in[2];
    const int*   mask  = (const int*)  d_in[3];
    const float* Wq = (const float*)d_in[4];
    const float* bq = (const float*)d_in[5];
    const float* Wk = (const float*)d_in[6];
    const float* bk = (const float*)d_in[7];
    const float* Wv = (const float*)d_in[8];
    const float* bv = (const float*)d_in[9];
    const float* Wo = (const float*)d_in[10];
    const float* bo = (const float*)d_in[11];
    float* out = (float*)d_out;

    __half *xh, *xl, *wh, *wl, *qh, *ql, *kh, *kl, *vh, *vl, *oh, *ol;
    cudaGetSymbolAddress((void**)&xh, g_xh);
    cudaGetSymbolAddress((void**)&xl, g_xl);
    cudaGetSymbolAddress((void**)&wh, g_wh);
    cudaGetSymbolAddress((void**)&wl, g_wl);
    cudaGetSymbolAddress((void**)&qh, g_qh);
    cudaGetSymbolAddress((void**)&ql, g_ql);
    cudaGetSymbolAddress((void**)&kh, g_kh);
    cudaGetSymbolAddress((void**)&kl, g_kl);
    cudaGetSymbolAddress((void**)&vh, g_vh);
    cudaGetSymbolAddress((void**)&vl, g_vl);
    cudaGetSymbolAddress((void**)&oh, g_oh);
    cudaGetSymbolAddress((void**)&ol, g_ol);

    const int nA4 = (Mv * Ev) / 4;
    const int nW4 = (Ev * Ev) / 4;
    const dim3 ggrid(GN / 128, Mv / 128);  // (8, 32)

    // Q projection (fp16 hi/lo output)
    split_f16<<<nA4 / 256, 256>>>((const float4*)query, (uint2*)xh, (uint2*)xl, nA4);
    split_f16<<<nW4 / 256, 256>>>((const float4*)Wq, (uint2*)wh, (uint2*)wl, nW4);
    gemm_f16<<<ggrid, 256>>>(xh, xl, wh, wl, bq, nullptr, qh, ql, 1);
    // K projection
    split_f16<<<nA4 / 256, 256>>>((const float4*)key, (uint2*)xh, (uint2*)xl, nA4);
    split_f16<<<nW4 / 256, 256>>>((const float4*)Wk, (uint2*)wh, (uint2*)wl, nW4);
    gemm_f16<<<ggrid, 256>>>(xh, xl, wh, wl, bk, nullptr, kh, kl, 1);
    // V projection
    split_f16<<<nA4 / 256, 256>>>((const float4*)value, (uint2*)xh, (uint2*)xl, nA4);
    split_f16<<<nW4 / 256, 256>>>((const float4*)Wv, (uint2*)wh, (uint2*)wl, nW4);
    gemm_f16<<<ggrid, 256>>>(xh, xl, wh, wl, bv, nullptr, vh, vl, 1);

    // Attention (HMMA flash, fp16 hi/lo in and out)
    flash_mma<<<dim3(Sv / 64, Hv, Bv), 128>>>(qh, ql, kh, kl, vh, vl, mask, oh, ol);

    // Output projection (fp32 output + bias)
    split_f16<<<nW4 / 256, 256>>>((const float4*)Wo, (uint2*)wh, (uint2*)wl, nW4);
    gemm_f16<<<ggrid, 256>>>(oh, ol, wh, wl, bo, out, nullptr, nullptr, 0);
}

// round 5
// speedup vs baseline: 2.6136x; 1.0414x over previous
#include <cuda_runtime.h>
#include <cuda_fp16.h>
#include <cstdint>

// Shapes are fixed by the problem.
#define Bv 2
#define Sv 2048
#define Ev 1024
#define Hv 16
#define Dv 64
#define Mv (Bv * Sv) /* 4096 */

// Scratch (allocation-free rule: __device__ globals), all fp16 hi/lo pairs.
__device__ __half g_xh[3][(size_t)Mv * Ev];  // q/k/v activation splits
__device__ __half g_xl[3][(size_t)Mv * Ev];
__device__ __half g_wh[3][(size_t)Ev * Ev];  // Wq/Wk/Wv splits
__device__ __half g_wl[3][(size_t)Ev * Ev];
__device__ __half g_woh[(size_t)Ev * Ev];    // Wo split
__device__ __half g_wol[(size_t)Ev * Ev];
__device__ __half g_qh[(size_t)Mv * Ev];
__device__ __half g_ql[(size_t)Mv * Ev];
__device__ __half g_kh[(size_t)Mv * Ev];
__device__ __half g_kl[(size_t)Mv * Ev];
__device__ __half g_vh[(size_t)Mv * Ev];
__device__ __half g_vl[(size_t)Mv * Ev];
__device__ __half g_oh[(size_t)Mv * Ev];
__device__ __half g_ol[(size_t)Mv * Ev];

// ---------------------------------------------------------------------------
// Family-portable tensor-core helpers (HMMA / LDSM / LDGSTS — legal on sm_103)
// ---------------------------------------------------------------------------
__device__ __forceinline__ uint32_t smem_u32(const void* p) {
    uint32_t a;
    asm("{ .reg .u64 t; cvta.to.shared.u64 t, %1; cvt.u32.u64 %0, t; }"
        : "=r"(a) : "l"(p));
    return a;
}

__device__ __forceinline__ void ldsm_x4(uint32_t* r, uint32_t addr) {
    asm volatile("ldmatrix.sync.aligned.m8n8.x4.shared.b16 {%0,%1,%2,%3}, [%4];"
                 : "=r"(r[0]), "=r"(r[1]), "=r"(r[2]), "=r"(r[3]) : "r"(addr));
}

__device__ __forceinline__ void ldsm_x4_t(uint32_t* r, uint32_t addr) {
    asm volatile("ldmatrix.sync.aligned.m8n8.x4.trans.shared.b16 {%0,%1,%2,%3}, [%4];"
                 : "=r"(r[0]), "=r"(r[1]), "=r"(r[2]), "=r"(r[3]) : "r"(addr));
}

__device__ __forceinline__ void mma_f16(float* c, const uint32_t* a, const uint32_t* b) {
    asm volatile(
        "mma.sync.aligned.m16n8k16.row.col.f32.f16.f16.f32 "
        "{%0,%1,%2,%3}, {%4,%5,%6,%7}, {%8,%9}, {%0,%1,%2,%3};"
        : "+f"(c[0]), "+f"(c[1]), "+f"(c[2]), "+f"(c[3])
        : "r"(a[0]), "r"(a[1]), "r"(a[2]), "r"(a[3]), "r"(b[0]), "r"(b[1]));
}

__device__ __forceinline__ void cp16(uint32_t dst, const void* src) {
    asm volatile("cp.async.cg.shared.global [%0], [%1], 16;"
                 :: "r"(dst), "l"(src));
}
#define CP_COMMIT() asm volatile("cp.async.commit_group;" ::: "memory")
#define CP_WAIT1()  asm volatile("cp.async.wait_group 1;" ::: "memory")
#define CP_WAIT0()  asm volatile("cp.async.wait_group 0;" ::: "memory")

__device__ __forceinline__ uint32_t h2u(__half2 v) {
    return *reinterpret_cast<uint32_t*>(&v);
}

// ---------------------------------------------------------------------------
// Split fp32 -> fp16 hi/lo, float4-vectorized
// ---------------------------------------------------------------------------
__global__ void __launch_bounds__(256)
split_f16(const float4* __restrict__ x, uint2* __restrict__ hi,
          uint2* __restrict__ lo, int n4)
{
    int i = blockIdx.x * 256 + threadIdx.x;
    if (i >= n4) return;
    const float4 v = x[i];
    float f[4] = {v.x, v.y, v.z, v.w};
    unsigned short h[4], l[4];
#pragma unroll
    for (int j = 0; j < 4; j++) {
        __half hb = __float2half_rn(f[j]);
        __half lb = __float2half_rn(f[j] - __half2float(hb));
        h[j] = __half_as_ushort(hb);
        l[j] = __half_as_ushort(lb);
    }
    uint2 ho, loo;
    ho.x  = (uint32_t)h[0] | ((uint32_t)h[1] << 16);
    ho.y  = (uint32_t)h[2] | ((uint32_t)h[3] << 16);
    loo.x = (uint32_t)l[0] | ((uint32_t)l[1] << 16);
    loo.y = (uint32_t)l[2] | ((uint32_t)l[3] << 16);
    hi[i] = ho;
    lo[i] = loo;
}

// ---------------------------------------------------------------------------
// HMMA GEMM mainloop, cp.async 2-stage double buffer.
// C[M,N] = A[M,K] @ W[N,K]^T, fp16x3 split, fp32 accum.
// 128x128 CTA tile, BK=32, 8 warps (2m x 4n), warp tile 64x32.
// Dynamic smem: 2 stages x 4 arrays x 128 x SSTR halves = 80KB.
// ---------------------------------------------------------------------------
#define GK 1024
#define GN 1024
#define SSTR 40
#define TILEB (128 * SSTR * 2)            /* bytes per array per stage */
#define STGB  (4 * TILEB)                 /* bytes per stage */
#define GEMM_SMEM (2 * STGB)              /* 81920 */

struct QKVParams {
    const float* bias0; const float* bias1; const float* bias2;
    __half* Ch0; __half* Ch1; __half* Ch2;
    __half* Cl0; __half* Cl1; __half* Cl2;
};

// Shared mainloop: fills acc[4][4][4]. smem_base = dynamic smem u32 address.
__device__ __forceinline__ void gemm_core(
    const __half* __restrict__ Ahg, const __half* __restrict__ Alg,
    const __half* __restrict__ Bhg, const __half* __restrict__ Blg,
    uint32_t smem_base, int bm, int bn, int tid, float acc[4][4][4])
{
    const int lane = tid & 31;
    const int wid  = tid >> 5;
    const int wm   = (wid & 1) * 64;
    const int wn   = (wid >> 1) * 32;

    // copy slice: rows r0, r0+64; 16B chunk col c8 (halves)
    const int r0 = tid >> 2;
    const int c8 = (tid & 3) * 8;
    const uint32_t dst_off = (uint32_t)(r0 * SSTR + c8) * 2;
    const uint32_t dst_off2 = (uint32_t)((r0 + 64) * SSTR + c8) * 2;

    const __half* gA = Ahg + (size_t)(bm + r0) * GK + c8;
    const __half* gA2 = Ahg + (size_t)(bm + r0 + 64) * GK + c8;
    const __half* gAl = Alg + (size_t)(bm + r0) * GK + c8;
    const __half* gAl2 = Alg + (size_t)(bm + r0 + 64) * GK + c8;
    const __half* gB = Bhg + (size_t)(bn + r0) * GK + c8;
    const __half* gB2 = Bhg + (size_t)(bn + r0 + 64) * GK + c8;
    const __half* gBl = Blg + (size_t)(bn + r0) * GK + c8;
    const __half* gBl2 = Blg + (size_t)(bn + r0 + 64) * GK + c8;

    const int a_row = wm + (lane & 15);
    const int a_col = (lane >> 4) * 8;
    const int g     = lane >> 3;
    const int b_row = wn + (lane & 7) + (g >> 1) * 8;
    const int b_col = (g & 1) * 8;

    auto issue = [&](int kt, int stg) {
        const int ko = kt * 32;
        const uint32_t sb = smem_base + stg * STGB;
        cp16(sb + dst_off,              gA  + ko);
        cp16(sb + dst_off2,             gA2 + ko);
        cp16(sb + TILEB + dst_off,      gAl + ko);
        cp16(sb + TILEB + dst_off2,     gAl2 + ko);
        cp16(sb + 2 * TILEB + dst_off,  gB  + ko);
        cp16(sb + 2 * TILEB + dst_off2, gB2 + ko);
        cp16(sb + 3 * TILEB + dst_off,  gBl + ko);
        cp16(sb + 3 * TILEB + dst_off2, gBl2 + ko);
    };

    issue(0, 0);
    CP_COMMIT();

#pragma unroll 1
    for (int it = 0; it < GK / 32; it++) {
        const int stg = it & 1;
        if (it < GK / 32 - 1) {
            issue(it + 1, (it + 1) & 1);
            CP_COMMIT();
            CP_WAIT1();
        } else {
            CP_WAIT0();
        }
        __syncthreads();

        const uint32_t ah_b = smem_base + stg * STGB;
        const uint32_t al_b = ah_b + TILEB;
        const uint32_t bh_b = ah_b + 2 * TILEB;
        const uint32_t bl_b = ah_b + 3 * TILEB;

#pragma unroll
        for (int ks = 0; ks < 2; ks++) {
            uint32_t afh[4][4], afl[4][4];
#pragma unroll
            for (int i = 0; i < 4; i++) {
                const uint32_t off = ((a_row + i * 16) * SSTR + ks * 16 + a_col) * 2;
                ldsm_x4(afh[i], ah_b + off);
                ldsm_x4(afl[i], al_b + off);
            }
            uint32_t bfh[4][2], bfl[4][2];
#pragma unroll
            for (int j = 0; j < 2; j++) {
                const uint32_t off = ((b_row + j * 16) * SSTR + ks * 16 + b_col) * 2;
                uint32_t r[4];
                ldsm_x4(r, bh_b + off);
                bfh[2 * j][0] = r[0]; bfh[2 * j][1] = r[1];
                bfh[2 * j + 1][0] = r[2]; bfh[2 * j + 1][1] = r[3];
                ldsm_x4(r, bl_b + off);
                bfl[2 * j][0] = r[0]; bfl[2 * j][1] = r[1];
                bfl[2 * j + 1][0] = r[2]; bfl[2 * j + 1][1] = r[3];
            }
#pragma unroll
            for (int i = 0; i < 4; i++)
#pragma unroll
                for (int j = 0; j < 4; j++) {
                    mma_f16(acc[i][j], afh[i], bfh[j]);
                    mma_f16(acc[i][j], afh[i], bfl[j]);
                    mma_f16(acc[i][j], afl[i], bfh[j]);
                }
        }
        __syncthreads();
    }
}

// Merged Q/K/V projection: gridDim.z selects which projection.
__global__ void __launch_bounds__(256, 2)
gemm_qkv(const __half* __restrict__ Xh, const __half* __restrict__ Xl,
         const __half* __restrict__ Wh, const __half* __restrict__ Wl,
         QKVParams p)
{
    extern __shared__ char dynsm[];
    const uint32_t smem_base = smem_u32(dynsm);
    const int z = blockIdx.z;
    const int tid = threadIdx.x, lane = tid & 31, wid = tid >> 5;
    const int bm = blockIdx.y << 7, bn = blockIdx.x << 7;

    const __half* Ahg = Xh + (size_t)z * Mv * Ev;
    const __half* Alg = Xl + (size_t)z * Mv * Ev;
    const __half* Bhg = Wh + (size_t)z * Ev * Ev;
    const __half* Blg = Wl + (size_t)z * Ev * Ev;
    const float* bias = (z == 0) ? p.bias0 : (z == 1) ? p.bias1 : p.bias2;
    __half* Ch = (z == 0) ? p.Ch0 : (z == 1) ? p.Ch1 : p.Ch2;
    __half* Cl = (z == 0) ? p.Cl0 : (z == 1) ? p.Cl1 : p.Cl2;

    float acc[4][4][4];
#pragma unroll
    for (int i = 0; i < 4; i++)
#pragma unroll
        for (int j = 0; j < 4; j++)
#pragma unroll
            for (int q = 0; q < 4; q++) acc[i][j][q] = 0.f;

    gemm_core(Ahg, Alg, Bhg, Blg, smem_base, bm, bn, tid, acc);

    const int wm = (wid & 1) * 64, wn = (wid >> 1) * 32;
#pragma unroll
    for (int i = 0; i < 4; i++) {
        const int grow = bm + wm + i * 16 + (lane >> 2);
#pragma unroll
        for (int j = 0; j < 4; j++) {
            const int gcol = bn + wn + j * 8 + (lane & 3) * 2;
            const float b0 = bias[gcol], b1 = bias[gcol + 1];
            const float v00 = acc[i][j][0] + b0, v01 = acc[i][j][1] + b1;
            const float v10 = acc[i][j][2] + b0, v11 = acc[i][j][3] + b1;
            const __half h00 = __float2half_rn(v00), h01 = __float2half_rn(v01);
            const __half h10 = __float2half_rn(v10), h11 = __float2half_rn(v11);
            const __half l00 = __float2half_rn(v00 - __half2float(h00));
            const __half l01 = __float2half_rn(v01 - __half2float(h01));
            const __half l10 = __float2half_rn(v10 - __half2float(h10));
            const __half l11 = __float2half_rn(v11 - __half2float(h11));
            *(__half2*)(Ch + (size_t)grow * GN + gcol)       = __halves2half2(h00, h01);
            *(__half2*)(Ch + (size_t)(grow + 8) * GN + gcol) = __halves2half2(h10, h11);
            *(__half2*)(Cl + (size_t)grow * GN + gcol)       = __halves2half2(l00, l01);
            *(__half2*)(Cl + (size_t)(grow + 8) * GN + gcol) = __halves2half2(l10, l11);
        }
    }
}

// Output projection: fp32 result + bias.
__global__ void __launch_bounds__(256, 2)
gemm_out(const __half* __restrict__ Ahg, const __half* __restrict__ Alg,
         const __half* __restrict__ Bhg, const __half* __restrict__ Blg,
         const float* __restrict__ bias, float* __restrict__ Cf)
{
    extern __shared__ char dynsm[];
    const uint32_t smem_base = smem_u32(dynsm);
    const int tid = threadIdx.x, lane = tid & 31, wid = tid >> 5;
    const int bm = blockIdx.y << 7, bn = blockIdx.x << 7;

    float acc[4][4][4];
#pragma unroll
    for (int i = 0; i < 4; i++)
#pragma unroll
        for (int j = 0; j < 4; j++)
#pragma unroll
            for (int q = 0; q < 4; q++) acc[i][j][q] = 0.f;

    gemm_core(Ahg, Alg, Bhg, Blg, smem_base, bm, bn, tid, acc);

    const int wm = (wid & 1) * 64, wn = (wid >> 1) * 32;
#pragma unroll
    for (int i = 0; i < 4; i++) {
        const int grow = bm + wm + i * 16 + (lane >> 2);
#pragma unroll
        for (int j = 0; j < 4; j++) {
            const int gcol = bn + wn + j * 8 + (lane & 3) * 2;
            const float b0 = bias[gcol], b1 = bias[gcol + 1];
            float2 v0, v1;
            v0.x = acc[i][j][0] + b0; v0.y = acc[i][j][1] + b1;
            v1.x = acc[i][j][2] + b0; v1.y = acc[i][j][3] + b1;
            *(float2*)(Cf + (size_t)grow * GN + gcol) = v0;
            *(float2*)(Cf + (size_t)(grow + 8) * GN + gcol) = v1;
        }
    }
}

// ---------------------------------------------------------------------------
// Flash attention on HMMA, split-fp16, online softmax (unchanged from R4).
// ---------------------------------------------------------------------------
#define KSTR 72

__global__ void __launch_bounds__(128)
flash_mma(const __half* __restrict__ Qh, const __half* __restrict__ Ql,
          const __half* __restrict__ Kh, const __half* __restrict__ Kl,
          const __half* __restrict__ Vh, const __half* __restrict__ Vl,
          const int* __restrict__ mask,
          __half* __restrict__ Oh, __half* __restrict__ Ol)
{
    __shared__ __half sKh[64 * KSTR], sKl[64 * KSTR];
    __shared__ __half sVh[64 * KSTR], sVl[64 * KSTR];

    const int tid = threadIdx.x, lane = tid & 31, warp = tid >> 5;
    const int b = blockIdx.z, h = blockIdx.y;
    const int qb = blockIdx.x << 6, hb = h << 6;

    const uint32_t kh_b = smem_u32(sKh), kl_b = smem_u32(sKl);
    const uint32_t vh_b = smem_u32(sVh), vl_b = smem_u32(sVl);

    const int sr = tid >> 3;
    const int sj = (tid & 7) * 8;

#pragma unroll
    for (int i = 0; i < 4; i++) {
        const int r = sr + i * 16;
        const size_t gq = (size_t)(b * Sv + qb + r) * Ev + hb + sj;
        *(uint4*)(sKh + r * KSTR + sj) = *(const uint4*)(Qh + gq);
        *(uint4*)(sKl + r * KSTR + sj) = *(const uint4*)(Ql + gq);
    }
    __syncthreads();
    uint32_t qfh[4][4], qfl[4][4];
    {
        const int ar = warp * 16 + (lane & 15);
        const int ac = (lane >> 4) * 8;
#pragma unroll
        for (int kf = 0; kf < 4; kf++) {
            const uint32_t off = (uint32_t)(ar * KSTR + kf * 16 + ac) * 2;
            ldsm_x4(qfh[kf], kh_b + off);
            ldsm_x4(qfl[kf], kl_b + off);
        }
    }

    float m0 = -1e30f, m1 = -1e30f, l0 = 0.f, l1 = 0.f;
    float o[8][4];
#pragma unroll
    for (int n = 0; n < 8; n++)
#pragma unroll
        for (int q = 0; q < 4; q++) o[n][q] = 0.f;

    const int r0g = b * Sv + qb + warp * 16 + (lane >> 2);
    const int* mr0 = mask + (size_t)r0g * Sv;
    const int* mr1 = mask + (size_t)(r0g + 8) * Sv;
    const int mc = (lane & 3) * 2;

    const int b_r = (lane & 7) + (lane >> 4) * 8;
    const int b_c = ((lane >> 3) & 1) * 8;
    const int v_r = (lane & 7) + ((lane >> 3) & 1) * 8;
    const int v_c = (lane >> 4) * 8;

    for (int kv = 0; kv < Sv; kv += 64) {
        __syncthreads();
#pragma unroll
        for (int i = 0; i < 4; i++) {
            const int r = sr + i * 16;
            const size_t gk = (size_t)(b * Sv + kv + r) * Ev + hb + sj;
            *(uint4*)(sKh + r * KSTR + sj) = *(const uint4*)(Kh + gk);
            *(uint4*)(sKl + r * KSTR + sj) = *(const uint4*)(Kl + gk);
            *(uint4*)(sVh + r * KSTR + sj) = *(const uint4*)(Vh + gk);
            *(uint4*)(sVl + r * KSTR + sj) = *(const uint4*)(Vl + gk);
        }
        __syncthreads();

        float s[8][4];
#pragma unroll
        for (int n = 0; n < 8; n++)
#pragma unroll
            for (int q = 0; q < 4; q++) s[n][q] = 0.f;

#pragma unroll
        for (int kf = 0; kf < 4; kf++) {
            uint32_t bh[8][2], bl[8][2];
#pragma unroll
            for (int u = 0; u < 4; u++) {
                const uint32_t off =
                    (uint32_t)((b_r + u * 16) * KSTR + b_c + kf * 16) * 2;
                uint32_t t[4];
                ldsm_x4(t, kh_b + off);
                bh[2 * u][0] = t[0]; bh[2 * u][1] = t[1];
                bh[2 * u + 1][0] = t[2]; bh[2 * u + 1][1] = t[3];
                ldsm_x4(t, kl_b + off);
                bl[2 * u][0] = t[0]; bl[2 * u][1] = t[1];
                bl[2 * u + 1][0] = t[2]; bl[2 * u + 1][1] = t[3];
            }
#pragma unroll
            for (int n = 0; n < 8; n++) {
                mma_f16(s[n], qfh[kf], bh[n]);
                mma_f16(s[n], qfh[kf], bl[n]);
                mma_f16(s[n], qfl[kf], bh[n]);
            }
        }

        float mx0 = -1e30f, mx1 = -1e30f;
#pragma unroll
        for (int n = 0; n < 8; n++) {
            const int c = kv + n * 8 + mc;
            const int2 k0 = *(const int2*)(mr0 + c);
            const int2 k1 = *(const int2*)(mr1 + c);
            s[n][0] = k0.x ? s[n][0] * 0.125f : -1e9f;
            s[n][1] = k0.y ? s[n][1] * 0.125f : -1e9f;
            s[n][2] = k1.x ? s[n][2] * 0.125f : -1e9f;
            s[n][3] = k1.y ? s[n][3] * 0.125f : -1e9f;
            mx0 = fmaxf(mx0, fmaxf(s[n][0], s[n][1]));
            mx1 = fmaxf(mx1, fmaxf(s[n][2], s[n][3]));
        }
        mx0 = fmaxf(mx0, __shfl_xor_sync(0xffffffffu, mx0, 1));
        mx0 = fmaxf(mx0, __shfl_xor_sync(0xffffffffu, mx0, 2));
        mx1 = fmaxf(mx1, __shfl_xor_sync(0xffffffffu, mx1, 1));
        mx1 = fmaxf(mx1, __shfl_xor_sync(0xffffffffu, mx1, 2));
        const float mn0 = fmaxf(m0, mx0), mn1 = fmaxf(m1, mx1);
        const float c0 = __expf(m0 - mn0), c1 = __expf(m1 - mn1);
        m0 = mn0; m1 = mn1;

        float rs0 = 0.f, rs1 = 0.f;
#pragma unroll
        for (int n = 0; n < 8; n++) {
            s[n][0] = __expf(s[n][0] - mn0); s[n][1] = __expf(s[n][1] - mn0);
            s[n][2] = __expf(s[n][2] - mn1); s[n][3] = __expf(s[n][3] - mn1);
            rs0 += s[n][0] + s[n][1];
            rs1 += s[n][2] + s[n][3];
            o[n][0] *= c0; o[n][1] *= c0; o[n][2] *= c1; o[n][3] *= c1;
        }
        rs0 += __shfl_xor_sync(0xffffffffu, rs0, 1);
        rs0 += __shfl_xor_sync(0xffffffffu, rs0, 2);
        rs1 += __shfl_xor_sync(0xffffffffu, rs1, 1);
        rs1 += __shfl_xor_sync(0xffffffffu, rs1, 2);
        l0 = l0 * c0 + rs0;
        l1 = l1 * c1 + rs1;

        uint32_t pf[4][4];
#pragma unroll
        for (int kf = 0; kf < 4; kf++) {
            const int n0 = 2 * kf, n1 = 2 * kf + 1;
            pf[kf][0] = h2u(__halves2half2(__float2half_rn(s[n0][0]), __float2half_rn(s[n0][1])));
            pf[kf][1] = h2u(__halves2half2(__float2half_rn(s[n0][2]), __float2half_rn(s[n0][3])));
            pf[kf][2] = h2u(__halves2half2(__float2half_rn(s[n1][0]), __float2half_rn(s[n1][1])));
            pf[kf][3] = h2u(__halves2half2(__float2half_rn(s[n1][2]), __float2half_rn(s[n1][3])));
        }

#pragma unroll
        for (int kf = 0; kf < 4; kf++) {
            uint32_t wh[8][2], wl[8][2];
#pragma unroll
            for (int u = 0; u < 4; u++) {
                const uint32_t off =
                    (uint32_t)((v_r + kf * 16) * KSTR + v_c + u * 16) * 2;
                uint32_t t[4];
                ldsm_x4_t(t, vh_b + off);
                wh[2 * u][0] = t[0]; wh[2 * u][1] = t[1];
                wh[2 * u + 1][0] = t[2]; wh[2 * u + 1][1] = t[3];
                ldsm_x4_t(t, vl_b + off);
                wl[2 * u][0] = t[0]; wl[2 * u][1] = t[1];
                wl[2 * u + 1][0] = t[2]; wl[2 * u + 1][1] = t[3];
            }
#pragma unroll
            for (int n = 0; n < 8; n++) {
                mma_f16(o[n], pf[kf], wh[n]);
                mma_f16(o[n], pf[kf], wl[n]);
            }
        }
    }

    const float i0 = 1.f / l0, i1 = 1.f / l1;
#pragma unroll
    for (int n = 0; n < 8; n++) {
        const int col = hb + n * 8 + mc;
        const float v00 = o[n][0] * i0, v01 = o[n][1] * i0;
        const float v10 = o[n][2] * i1, v11 = o[n][3] * i1;
        const __half h00 = __float2half_rn(v00), h01 = __float2half_rn(v01);
        const __half h10 = __float2half_rn(v10), h11 = __float2half_rn(v11);
        const __half q00 = __float2half_rn(v00 - __half2float(h00));
        const __half q01 = __float2half_rn(v01 - __half2float(h01));
        const __half q10 = __float2half_rn(v10 - __half2float(h10));
        const __half q11 = __float2half_rn(v11 - __half2float(h11));
        *(__half2*)(Oh + (size_t)r0g * Ev + col)       = __halves2half2(h00, h01);
        *(__half2*)(Oh + (size_t)(r0g + 8) * Ev + col) = __halves2half2(h10, h11);
        *(__half2*)(Ol + (size_t)r0g * Ev + col)       = __halves2half2(q00, q01);
        *(__half2*)(Ol + (size_t)(r0g + 8) * Ev + col) = __halves2half2(q10, q11);
    }
}

// ---------------------------------------------------------------------------
extern "C" void kernel_launch(void* const* d_in, const int* in_sizes, int n_in,
                              void* d_out, int out_size)
{
    (void)in_sizes; (void)n_in; (void)out_size;
    const float* query = (const float*)d_in[0];
    const float* key   = (const float*)d_in[1];
    const float* value = (const float*)d_in[2];
    const int*   mask  = (const int*)  d_in[3];
    const float* Wq = (const float*)d_in[4];
    const float* bq = (const float*)d_in[5];
    const float* Wk = (const float*)d_in[6];
    const float* bk = (const float*)d_in[7];
    const float* Wv = (const float*)d_in[8];
    const float* bv = (const float*)d_in[9];
    const float* Wo = (const float*)d_in[10];
    const float* bo = (const float*)d_in[11];
    float* out = (float*)d_out;

    __half *xh, *xl, *wh, *wl, *woh, *wol;
    __half *qh, *ql, *kh, *kl, *vh, *vl, *oh, *ol;
    cudaGetSymbolAddress((void**)&xh, g_xh);
    cudaGetSymbolAddress((void**)&xl, g_xl);
    cudaGetSymbolAddress((void**)&wh, g_wh);
    cudaGetSymbolAddress((void**)&wl, g_wl);
    cudaGetSymbolAddress((void**)&woh, g_woh);
    cudaGetSymbolAddress((void**)&wol, g_wol);
    cudaGetSymbolAddress((void**)&qh, g_qh);
    cudaGetSymbolAddress((void**)&ql, g_ql);
    cudaGetSymbolAddress((void**)&kh, g_kh);
    cudaGetSymbolAddress((void**)&kl, g_kl);
    cudaGetSymbolAddress((void**)&vh, g_vh);
    cudaGetSymbolAddress((void**)&vl, g_vl);
    cudaGetSymbolAddress((void**)&oh, g_oh);
    cudaGetSymbolAddress((void**)&ol, g_ol);

    cudaFuncSetAttribute(gemm_qkv,
                         cudaFuncAttributeMaxDynamicSharedMemorySize, GEMM_SMEM);
    cudaFuncSetAttribute(gemm_out,
                         cudaFuncAttributeMaxDynamicSharedMemorySize, GEMM_SMEM);

    const int nA4 = (Mv * Ev) / 4;
    const int nW4 = (Ev * Ev) / 4;
    const size_t AE = (size_t)Mv * Ev;
    const size_t WE = (size_t)Ev * Ev;

    // Splits: 3 activations + 4 weights
    split_f16<<<nA4 / 256, 256>>>((const float4*)query, (uint2*)xh, (uint2*)xl, nA4);
    split_f16<<<nA4 / 256, 256>>>((const float4*)key,
                                  (uint2*)(xh + AE), (uint2*)(xl + AE), nA4);
    split_f16<<<nA4 / 256, 256>>>((const float4*)value,
                                  (uint2*)(xh + 2 * AE), (uint2*)(xl + 2 * AE), nA4);
    split_f16<<<nW4 / 256, 256>>>((const float4*)Wq, (uint2*)wh, (uint2*)wl, nW4);
    split_f16<<<nW4 / 256, 256>>>((const float4*)Wk,
                                  (uint2*)(wh + WE), (uint2*)(wl + WE), nW4);
    split_f16<<<nW4 / 256, 256>>>((const float4*)Wv,
                                  (uint2*)(wh + 2 * WE), (uint2*)(wl + 2 * WE), nW4);
    split_f16<<<nW4 / 256, 256>>>((const float4*)Wo, (uint2*)woh, (uint2*)wol, nW4);

    // Merged QKV projections
    QKVParams p;
    p.bias0 = bq; p.bias1 = bk; p.bias2 = bv;
    p.Ch0 = qh; p.Ch1 = kh; p.Ch2 = vh;
    p.Cl0 = ql; p.Cl1 = kl; p.Cl2 = vl;
    gemm_qkv<<<dim3(GN / 128, Mv / 128, 3), 256, GEMM_SMEM>>>(xh, xl, wh, wl, p);

    // Attention
    flash_mma<<<dim3(Sv / 64, Hv, Bv), 128>>>(qh, ql, kh, kl, vh, vl, mask, oh, ol);

    // Output projection (fp32 + bias)
    gemm_out<<<dim3(GN / 128, Mv / 128), 256, GEMM_SMEM>>>(oh, ol, woh, wol, bo, out);
}

// round 6
// speedup vs baseline: 3.5190x; 1.3464x over previous
#include <cuda_runtime.h>
#include <cuda_fp16.h>
#include <cstdint>

// Shapes are fixed by the problem.
#define Bv 2
#define Sv 2048
#define Ev 1024
#define Hv 16
#define Dv 64
#define Mv (Bv * Sv) /* 4096 */

// Scratch (allocation-free rule: __device__ globals).
__device__ __half g_xh[3][(size_t)Mv * Ev];  // q/k/v activations, fp16 hi only
__device__ __half g_wh[3][(size_t)Ev * Ev];  // Wq/Wk/Wv hi
__device__ __half g_wl[3][(size_t)Ev * Ev];  // Wq/Wk/Wv lo
__device__ __half g_woh[(size_t)Ev * Ev];    // Wo hi
__device__ __half g_wol[(size_t)Ev * Ev];    // Wo lo
__device__ __half g_qh[(size_t)Mv * Ev];     // Q hi (lo never needed)
__device__ __half g_kh[(size_t)Mv * Ev];
__device__ __half g_kl[(size_t)Mv * Ev];
__device__ __half g_vh[(size_t)Mv * Ev];
__device__ __half g_vl[(size_t)Mv * Ev];
__device__ __half g_oh[(size_t)Mv * Ev];     // attention out hi only

// ---------------------------------------------------------------------------
// Family-portable tensor-core helpers (HMMA / LDSM / LDGSTS — legal on sm_103)
// ---------------------------------------------------------------------------
__device__ __forceinline__ uint32_t smem_u32(const void* p) {
    uint32_t a;
    asm("{ .reg .u64 t; cvta.to.shared.u64 t, %1; cvt.u32.u64 %0, t; }"
        : "=r"(a) : "l"(p));
    return a;
}

__device__ __forceinline__ void ldsm_x4(uint32_t* r, uint32_t addr) {
    asm volatile("ldmatrix.sync.aligned.m8n8.x4.shared.b16 {%0,%1,%2,%3}, [%4];"
                 : "=r"(r[0]), "=r"(r[1]), "=r"(r[2]), "=r"(r[3]) : "r"(addr));
}

__device__ __forceinline__ void ldsm_x4_t(uint32_t* r, uint32_t addr) {
    asm volatile("ldmatrix.sync.aligned.m8n8.x4.trans.shared.b16 {%0,%1,%2,%3}, [%4];"
                 : "=r"(r[0]), "=r"(r[1]), "=r"(r[2]), "=r"(r[3]) : "r"(addr));
}

__device__ __forceinline__ void mma_f16(float* c, const uint32_t* a, const uint32_t* b) {
    asm volatile(
        "mma.sync.aligned.m16n8k16.row.col.f32.f16.f16.f32 "
        "{%0,%1,%2,%3}, {%4,%5,%6,%7}, {%8,%9}, {%0,%1,%2,%3};"
        : "+f"(c[0]), "+f"(c[1]), "+f"(c[2]), "+f"(c[3])
        : "r"(a[0]), "r"(a[1]), "r"(a[2]), "r"(a[3]), "r"(b[0]), "r"(b[1]));
}

__device__ __forceinline__ void cp16(uint32_t dst, const void* src) {
    asm volatile("cp.async.cg.shared.global [%0], [%1], 16;"
                 :: "r"(dst), "l"(src));
}
#define CP_COMMIT() asm volatile("cp.async.commit_group;" ::: "memory")
#define CP_WAIT1()  asm volatile("cp.async.wait_group 1;" ::: "memory")
#define CP_WAIT0()  asm volatile("cp.async.wait_group 0;" ::: "memory")

__device__ __forceinline__ uint32_t h2u(__half2 v) {
    return *reinterpret_cast<uint32_t*>(&v);
}

// ---------------------------------------------------------------------------
// Activation convert: fp32 -> fp16 hi only. blockIdx.y selects tensor (0..2).
// ---------------------------------------------------------------------------
__global__ void __launch_bounds__(256)
conv_acts(const float4* __restrict__ q, const float4* __restrict__ k,
          const float4* __restrict__ v, uint2* __restrict__ dst, int n4)
{
    const int z = blockIdx.y;
    const float4* src = (z == 0) ? q : (z == 1) ? k : v;
    const int i = blockIdx.x * 256 + threadIdx.x;
    if (i >= n4) return;
    const float4 w = src[i];
    uint2 o;
    o.x = (uint32_t)__half_as_ushort(__float2half_rn(w.x))
        | ((uint32_t)__half_as_ushort(__float2half_rn(w.y)) << 16);
    o.y = (uint32_t)__half_as_ushort(__float2half_rn(w.z))
        | ((uint32_t)__half_as_ushort(__float2half_rn(w.w)) << 16);
    dst[(size_t)z * n4 + i] = o;
}

// ---------------------------------------------------------------------------
// Weight split: fp32 -> fp16 hi/lo. blockIdx.y selects weight (0..3).
// ---------------------------------------------------------------------------
struct WSplitPtrs {
    const float4* src[4];
    uint2* hi[4];
    uint2* lo[4];
};

__global__ void __launch_bounds__(256)
split_w(WSplitPtrs p, int n4)
{
    const int z = blockIdx.y;
    const int i = blockIdx.x * 256 + threadIdx.x;
    if (i >= n4) return;
    const float4 v = p.src[z][i];
    float f[4] = {v.x, v.y, v.z, v.w};
    unsigned short h[4], l[4];
#pragma unroll
    for (int j = 0; j < 4; j++) {
        __half hb = __float2half_rn(f[j]);
        __half lb = __float2half_rn(f[j] - __half2float(hb));
        h[j] = __half_as_ushort(hb);
        l[j] = __half_as_ushort(lb);
    }
    uint2 ho, lo;
    ho.x = (uint32_t)h[0] | ((uint32_t)h[1] << 16);
    ho.y = (uint32_t)h[2] | ((uint32_t)h[3] << 16);
    lo.x = (uint32_t)l[0] | ((uint32_t)l[1] << 16);
    lo.y = (uint32_t)l[2] | ((uint32_t)l[3] << 16);
    p.hi[z][i] = ho;
    p.lo[z][i] = lo;
}

// ---------------------------------------------------------------------------
// HMMA GEMM mainloop, cp.async 2-stage double buffer, 2-pass split:
// C = Ah @ (Wh + Wl)^T  (activations fp16-quantized, weights fp16x2).
// 128x128 CTA tile, BK=32, 8 warps (2m x 4n), warp tile 64x32.
// Dynamic smem: 2 stages x 3 arrays x 128 x SSTR halves = 60KB.
// ---------------------------------------------------------------------------
#define GK 1024
#define GN 1024
#define SSTR 40
#define TILEB (128 * SSTR * 2)            /* 10240 bytes per array per stage */
#define STGB  (3 * TILEB)                 /* bytes per stage */
#define GEMM_SMEM (2 * STGB)              /* 61440 */

struct QKVParams {
    const float* bias0; const float* bias1; const float* bias2;
    __half* Ch0; __half* Ch1; __half* Ch2;
    __half* Cl1; __half* Cl2;             // no Cl0: Q stores hi only
};

__device__ __forceinline__ void gemm_core(
    const __half* __restrict__ Ahg,
    const __half* __restrict__ Bhg, const __half* __restrict__ Blg,
    uint32_t smem_base, int bm, int bn, int tid, float acc[4][4][4])
{
    const int lane = tid & 31;
    const int wid  = tid >> 5;
    const int wm   = (wid & 1) * 64;
    const int wn   = (wid >> 1) * 32;

    const int r0 = tid >> 2;
    const int c8 = (tid & 3) * 8;
    const uint32_t dst_off  = (uint32_t)(r0 * SSTR + c8) * 2;
    const uint32_t dst_off2 = (uint32_t)((r0 + 64) * SSTR + c8) * 2;

    const __half* gA  = Ahg + (size_t)(bm + r0) * GK + c8;
    const __half* gA2 = Ahg + (size_t)(bm + r0 + 64) * GK + c8;
    const __half* gB  = Bhg + (size_t)(bn + r0) * GK + c8;
    const __half* gB2 = Bhg + (size_t)(bn + r0 + 64) * GK + c8;
    const __half* gBl  = Blg + (size_t)(bn + r0) * GK + c8;
    const __half* gBl2 = Blg + (size_t)(bn + r0 + 64) * GK + c8;

    const int a_row = wm + (lane & 15);
    const int a_col = (lane >> 4) * 8;
    const int g     = lane >> 3;
    const int b_row = wn + (lane & 7) + (g >> 1) * 8;
    const int b_col = (g & 1) * 8;

    auto issue = [&](int kt, int stg) {
        const int ko = kt * 32;
        const uint32_t sb = smem_base + stg * STGB;
        cp16(sb + dst_off,              gA   + ko);
        cp16(sb + dst_off2,             gA2  + ko);
        cp16(sb + TILEB + dst_off,      gB   + ko);
        cp16(sb + TILEB + dst_off2,     gB2  + ko);
        cp16(sb + 2 * TILEB + dst_off,  gBl  + ko);
        cp16(sb + 2 * TILEB + dst_off2, gBl2 + ko);
    };

    issue(0, 0);
    CP_COMMIT();

#pragma unroll 1
    for (int it = 0; it < GK / 32; it++) {
        const int stg = it & 1;
        if (it < GK / 32 - 1) {
            issue(it + 1, (it + 1) & 1);
            CP_COMMIT();
            CP_WAIT1();
        } else {
            CP_WAIT0();
        }
        __syncthreads();

        const uint32_t ah_b = smem_base + stg * STGB;
        const uint32_t bh_b = ah_b + TILEB;
        const uint32_t bl_b = ah_b + 2 * TILEB;

#pragma unroll
        for (int ks = 0; ks < 2; ks++) {
            uint32_t afh[4][4];
#pragma unroll
            for (int i = 0; i < 4; i++) {
                const uint32_t off = ((a_row + i * 16) * SSTR + ks * 16 + a_col) * 2;
                ldsm_x4(afh[i], ah_b + off);
            }
            uint32_t bfh[4][2], bfl[4][2];
#pragma unroll
            for (int j = 0; j < 2; j++) {
                const uint32_t off = ((b_row + j * 16) * SSTR + ks * 16 + b_col) * 2;
                uint32_t r[4];
                ldsm_x4(r, bh_b + off);
                bfh[2 * j][0] = r[0]; bfh[2 * j][1] = r[1];
                bfh[2 * j + 1][0] = r[2]; bfh[2 * j + 1][1] = r[3];
                ldsm_x4(r, bl_b + off);
                bfl[2 * j][0] = r[0]; bfl[2 * j][1] = r[1];
                bfl[2 * j + 1][0] = r[2]; bfl[2 * j + 1][1] = r[3];
            }
#pragma unroll
            for (int i = 0; i < 4; i++)
#pragma unroll
                for (int j = 0; j < 4; j++) {
                    mma_f16(acc[i][j], afh[i], bfh[j]);
                    mma_f16(acc[i][j], afh[i], bfl[j]);
                }
        }
        __syncthreads();
    }
}

// Merged Q/K/V projection: gridDim.z selects which projection.
__global__ void __launch_bounds__(256, 2)
gemm_qkv(const __half* __restrict__ Xh,
         const __half* __restrict__ Wh, const __half* __restrict__ Wl,
         QKVParams p)
{
    extern __shared__ char dynsm[];
    const uint32_t smem_base = smem_u32(dynsm);
    const int z = blockIdx.z;
    const int tid = threadIdx.x, lane = tid & 31, wid = tid >> 5;
    const int bm = blockIdx.y << 7, bn = blockIdx.x << 7;

    const __half* Ahg = Xh + (size_t)z * Mv * Ev;
    const __half* Bhg = Wh + (size_t)z * Ev * Ev;
    const __half* Blg = Wl + (size_t)z * Ev * Ev;
    const float* bias = (z == 0) ? p.bias0 : (z == 1) ? p.bias1 : p.bias2;
    __half* Ch = (z == 0) ? p.Ch0 : (z == 1) ? p.Ch1 : p.Ch2;
    __half* Cl = (z == 1) ? p.Cl1 : (z == 2) ? p.Cl2 : nullptr;

    float acc[4][4][4];
#pragma unroll
    for (int i = 0; i < 4; i++)
#pragma unroll
        for (int j = 0; j < 4; j++)
#pragma unroll
            for (int q = 0; q < 4; q++) acc[i][j][q] = 0.f;

    gemm_core(Ahg, Bhg, Blg, smem_base, bm, bn, tid, acc);

    const int wm = (wid & 1) * 64, wn = (wid >> 1) * 32;
#pragma unroll
    for (int i = 0; i < 4; i++) {
        const int grow = bm + wm + i * 16 + (lane >> 2);
#pragma unroll
        for (int j = 0; j < 4; j++) {
            const int gcol = bn + wn + j * 8 + (lane & 3) * 2;
            const float b0 = bias[gcol], b1 = bias[gcol + 1];
            const float v00 = acc[i][j][0] + b0, v01 = acc[i][j][1] + b1;
            const float v10 = acc[i][j][2] + b0, v11 = acc[i][j][3] + b1;
            const __half h00 = __float2half_rn(v00), h01 = __float2half_rn(v01);
            const __half h10 = __float2half_rn(v10), h11 = __float2half_rn(v11);
            *(__half2*)(Ch + (size_t)grow * GN + gcol)       = __halves2half2(h00, h01);
            *(__half2*)(Ch + (size_t)(grow + 8) * GN + gcol) = __halves2half2(h10, h11);
            if (z != 0) {
                const __half l00 = __float2half_rn(v00 - __half2float(h00));
                const __half l01 = __float2half_rn(v01 - __half2float(h01));
                const __half l10 = __float2half_rn(v10 - __half2float(h10));
                const __half l11 = __float2half_rn(v11 - __half2float(h11));
                *(__half2*)(Cl + (size_t)grow * GN + gcol)       = __halves2half2(l00, l01);
                *(__half2*)(Cl + (size_t)(grow + 8) * GN + gcol) = __halves2half2(l10, l11);
            }
        }
    }
}

// Output projection: fp32 result + bias.
__global__ void __launch_bounds__(256, 2)
gemm_out(const __half* __restrict__ Ahg,
         const __half* __restrict__ Bhg, const __half* __restrict__ Blg,
         const float* __restrict__ bias, float* __restrict__ Cf)
{
    extern __shared__ char dynsm[];
    const uint32_t smem_base = smem_u32(dynsm);
    const int tid = threadIdx.x, lane = tid & 31, wid = tid >> 5;
    const int bm = blockIdx.y << 7, bn = blockIdx.x << 7;

    float acc[4][4][4];
#pragma unroll
    for (int i = 0; i < 4; i++)
#pragma unroll
        for (int j = 0; j < 4; j++)
#pragma unroll
            for (int q = 0; q < 4; q++) acc[i][j][q] = 0.f;

    gemm_core(Ahg, Bhg, Blg, smem_base, bm, bn, tid, acc);

    const int wm = (wid & 1) * 64, wn = (wid >> 1) * 32;
#pragma unroll
    for (int i = 0; i < 4; i++) {
        const int grow = bm + wm + i * 16 + (lane >> 2);
#pragma unroll
        for (int j = 0; j < 4; j++) {
            const int gcol = bn + wn + j * 8 + (lane & 3) * 2;
            const float b0 = bias[gcol], b1 = bias[gcol + 1];
            float2 v0, v1;
            v0.x = acc[i][j][0] + b0; v0.y = acc[i][j][1] + b1;
            v1.x = acc[i][j][2] + b0; v1.y = acc[i][j][3] + b1;
            *(float2*)(Cf + (size_t)grow * GN + gcol) = v0;
            *(float2*)(Cf + (size_t)(grow + 8) * GN + gcol) = v1;
        }
    }
}

// ---------------------------------------------------------------------------
// Flash attention on HMMA, online softmax.
// S = Qh (Kh + Kl)^T  (2 passes, Q fp16-quantized); O = Ph (Vh + Vl).
// CTA: 128 threads = 4 warps, q-tile 64 (16 rows/warp), kv chunk 64.
// ---------------------------------------------------------------------------
#define KSTR 72

__global__ void __launch_bounds__(128)
flash_mma(const __half* __restrict__ Qh,
          const __half* __restrict__ Kh, const __half* __restrict__ Kl,
          const __half* __restrict__ Vh, const __half* __restrict__ Vl,
          const int* __restrict__ mask, __half* __restrict__ Oh)
{
    __shared__ __half sKh[64 * KSTR], sKl[64 * KSTR];
    __shared__ __half sVh[64 * KSTR], sVl[64 * KSTR];

    const int tid = threadIdx.x, lane = tid & 31, warp = tid >> 5;
    const int b = blockIdx.z, h = blockIdx.y;
    const int qb = blockIdx.x << 6, hb = h << 6;

    const uint32_t kh_b = smem_u32(sKh), kl_b = smem_u32(sKl);
    const uint32_t vh_b = smem_u32(sVh), vl_b = smem_u32(sVl);

    const int sr = tid >> 3;
    const int sj = (tid & 7) * 8;

    // stage Q hi into sKh, pull A-fragments
#pragma unroll
    for (int i = 0; i < 4; i++) {
        const int r = sr + i * 16;
        const size_t gq = (size_t)(b * Sv + qb + r) * Ev + hb + sj;
        *(uint4*)(sKh + r * KSTR + sj) = *(const uint4*)(Qh + gq);
    }
    __syncthreads();
    uint32_t qfh[4][4];
    {
        const int ar = warp * 16 + (lane & 15);
        const int ac = (lane >> 4) * 8;
#pragma unroll
        for (int kf = 0; kf < 4; kf++) {
            const uint32_t off = (uint32_t)(ar * KSTR + kf * 16 + ac) * 2;
            ldsm_x4(qfh[kf], kh_b + off);
        }
    }

    float m0 = -1e30f, m1 = -1e30f, l0 = 0.f, l1 = 0.f;
    float o[8][4];
#pragma unroll
    for (int n = 0; n < 8; n++)
#pragma unroll
        for (int q = 0; q < 4; q++) o[n][q] = 0.f;

    const int r0g = b * Sv + qb + warp * 16 + (lane >> 2);
    const int* mr0 = mask + (size_t)r0g * Sv;
    const int* mr1 = mask + (size_t)(r0g + 8) * Sv;
    const int mc = (lane & 3) * 2;

    const int b_r = (lane & 7) + (lane >> 4) * 8;
    const int b_c = ((lane >> 3) & 1) * 8;
    const int v_r = (lane & 7) + ((lane >> 3) & 1) * 8;
    const int v_c = (lane >> 4) * 8;

    for (int kv = 0; kv < Sv; kv += 64) {
        __syncthreads();
#pragma unroll
        for (int i = 0; i < 4; i++) {
            const int r = sr + i * 16;
            const size_t gk = (size_t)(b * Sv + kv + r) * Ev + hb + sj;
            *(uint4*)(sKh + r * KSTR + sj) = *(const uint4*)(Kh + gk);
            *(uint4*)(sKl + r * KSTR + sj) = *(const uint4*)(Kl + gk);
            *(uint4*)(sVh + r * KSTR + sj) = *(const uint4*)(Vh + gk);
            *(uint4*)(sVl + r * KSTR + sj) = *(const uint4*)(Vl + gk);
        }
        __syncthreads();

        float s[8][4];
#pragma unroll
        for (int n = 0; n < 8; n++)
#pragma unroll
            for (int q = 0; q < 4; q++) s[n][q] = 0.f;

#pragma unroll
        for (int kf = 0; kf < 4; kf++) {
            uint32_t bh[8][2], bl[8][2];
#pragma unroll
            for (int u = 0; u < 4; u++) {
                const uint32_t off =
                    (uint32_t)((b_r + u * 16) * KSTR + b_c + kf * 16) * 2;
                uint32_t t[4];
                ldsm_x4(t, kh_b + off);
                bh[2 * u][0] = t[0]; bh[2 * u][1] = t[1];
                bh[2 * u + 1][0] = t[2]; bh[2 * u + 1][1] = t[3];
                ldsm_x4(t, kl_b + off);
                bl[2 * u][0] = t[0]; bl[2 * u][1] = t[1];
                bl[2 * u + 1][0] = t[2]; bl[2 * u + 1][1] = t[3];
            }
#pragma unroll
            for (int n = 0; n < 8; n++) {
                mma_f16(s[n], qfh[kf], bh[n]);
                mma_f16(s[n], qfh[kf], bl[n]);
            }
        }

        float mx0 = -1e30f, mx1 = -1e30f;
#pragma unroll
        for (int n = 0; n < 8; n++) {
            const int c = kv + n * 8 + mc;
            const int2 k0 = *(const int2*)(mr0 + c);
            const int2 k1 = *(const int2*)(mr1 + c);
            s[n][0] = k0.x ? s[n][0] * 0.125f : -1e9f;
            s[n][1] = k0.y ? s[n][1] * 0.125f : -1e9f;
            s[n][2] = k1.x ? s[n][2] * 0.125f : -1e9f;
            s[n][3] = k1.y ? s[n][3] * 0.125f : -1e9f;
            mx0 = fmaxf(mx0, fmaxf(s[n][0], s[n][1]));
            mx1 = fmaxf(mx1, fmaxf(s[n][2], s[n][3]));
        }
        mx0 = fmaxf(mx0, __shfl_xor_sync(0xffffffffu, mx0, 1));
        mx0 = fmaxf(mx0, __shfl_xor_sync(0xffffffffu, mx0, 2));
        mx1 = fmaxf(mx1, __shfl_xor_sync(0xffffffffu, mx1, 1));
        mx1 = fmaxf(mx1, __shfl_xor_sync(0xffffffffu, mx1, 2));
        const float mn0 = fmaxf(m0, mx0), mn1 = fmaxf(m1, mx1);
        const float c0 = __expf(m0 - mn0), c1 = __expf(m1 - mn1);
        m0 = mn0; m1 = mn1;

        float rs0 = 0.f, rs1 = 0.f;
#pragma unroll
        for (int n = 0; n < 8; n++) {
            s[n][0] = __expf(s[n][0] - mn0); s[n][1] = __expf(s[n][1] - mn0);
            s[n][2] = __expf(s[n][2] - mn1); s[n][3] = __expf(s[n][3] - mn1);
            rs0 += s[n][0] + s[n][1];
            rs1 += s[n][2] + s[n][3];
            o[n][0] *= c0; o[n][1] *= c0; o[n][2] *= c1; o[n][3] *= c1;
        }
        rs0 += __shfl_xor_sync(0xffffffffu, rs0, 1);
        rs0 += __shfl_xor_sync(0xffffffffu, rs0, 2);
        rs1 += __shfl_xor_sync(0xffffffffu, rs1, 1);
        rs1 += __shfl_xor_sync(0xffffffffu, rs1, 2);
        l0 = l0 * c0 + rs0;
        l1 = l1 * c1 + rs1;

        uint32_t pf[4][4];
#pragma unroll
        for (int kf = 0; kf < 4; kf++) {
            const int n0 = 2 * kf, n1 = 2 * kf + 1;
            pf[kf][0] = h2u(__halves2half2(__float2half_rn(s[n0][0]), __float2half_rn(s[n0][1])));
            pf[kf][1] = h2u(__halves2half2(__float2half_rn(s[n0][2]), __float2half_rn(s[n0][3])));
            pf[kf][2] = h2u(__halves2half2(__float2half_rn(s[n1][0]), __float2half_rn(s[n1][1])));
            pf[kf][3] = h2u(__halves2half2(__float2half_rn(s[n1][2]), __float2half_rn(s[n1][3])));
        }

#pragma unroll
        for (int kf = 0; kf < 4; kf++) {
            uint32_t wh[8][2], wl[8][2];
#pragma unroll
            for (int u = 0; u < 4; u++) {
                const uint32_t off =
                    (uint32_t)((v_r + kf * 16) * KSTR + v_c + u * 16) * 2;
                uint32_t t[4];
                ldsm_x4_t(t, vh_b + off);
                wh[2 * u][0] = t[0]; wh[2 * u][1] = t[1];
                wh[2 * u + 1][0] = t[2]; wh[2 * u + 1][1] = t[3];
                ldsm_x4_t(t, vl_b + off);
                wl[2 * u][0] = t[0]; wl[2 * u][1] = t[1];
                wl[2 * u + 1][0] = t[2]; wl[2 * u + 1][1] = t[3];
            }
#pragma unroll
            for (int n = 0; n < 8; n++) {
                mma_f16(o[n], pf[kf], wh[n]);
                mma_f16(o[n], pf[kf], wl[n]);
            }
        }
    }

    const float i0 = 1.f / l0, i1 = 1.f / l1;
#pragma unroll
    for (int n = 0; n < 8; n++) {
        const int col = hb + n * 8 + mc;
        const __half h00 = __float2half_rn(o[n][0] * i0);
        const __half h01 = __float2half_rn(o[n][1] * i0);
        const __half h10 = __float2half_rn(o[n][2] * i1);
        const __half h11 = __float2half_rn(o[n][3] * i1);
        *(__half2*)(Oh + (size_t)r0g * Ev + col)       = __halves2half2(h00, h01);
        *(__half2*)(Oh + (size_t)(r0g + 8) * Ev + col) = __halves2half2(h10, h11);
    }
}

// ---------------------------------------------------------------------------
extern "C" void kernel_launch(void* const* d_in, const int* in_sizes, int n_in,
                              void* d_out, int out_size)
{
    (void)in_sizes; (void)n_in; (void)out_size;
    const float* query = (const float*)d_in[0];
    const float* key   = (const float*)d_in[1];
    const float* value = (const float*)d_in[2];
    const int*   mask  = (const int*)  d_in[3];
    const float* Wq = (const float*)d_in[4];
    const float* bq = (const float*)d_in[5];
    const float* Wk = (const float*)d_in[6];
    const float* bk = (const float*)d_in[7];
    const float* Wv = (const float*)d_in[8];
    const float* bv = (const float*)d_in[9];
    const float* Wo = (const float*)d_in[10];
    const float* bo = (const float*)d_in[11];
    float* out = (float*)d_out;

    __half *xh, *wh, *wl, *woh, *wol, *qh, *kh, *kl, *vh, *vl, *oh;
    cudaGetSymbolAddress((void**)&xh, g_xh);
    cudaGetSymbolAddress((void**)&wh, g_wh);
    cudaGetSymbolAddress((void**)&wl, g_wl);
    cudaGetSymbolAddress((void**)&woh, g_woh);
    cudaGetSymbolAddress((void**)&wol, g_wol);
    cudaGetSymbolAddress((void**)&qh, g_qh);
    cudaGetSymbolAddress((void**)&kh, g_kh);
    cudaGetSymbolAddress((void**)&kl, g_kl);
    cudaGetSymbolAddress((void**)&vh, g_vh);
    cudaGetSymbolAddress((void**)&vl, g_vl);
    cudaGetSymbolAddress((void**)&oh, g_oh);

    cudaFuncSetAttribute(gemm_qkv,
                         cudaFuncAttributeMaxDynamicSharedMemorySize, GEMM_SMEM);
    cudaFuncSetAttribute(gemm_out,
                         cudaFuncAttributeMaxDynamicSharedMemorySize, GEMM_SMEM);

    const int nA4 = (Mv * Ev) / 4;    // 1048576
    const int nW4 = (Ev * Ev) / 4;    // 262144
    const size_t WE = (size_t)Ev * Ev;

    // Activation converts (hi only), one launch for q/k/v
    conv_acts<<<dim3(nA4 / 256, 3), 256>>>((const float4*)query, (const float4*)key,
                                           (const float4*)value, (uint2*)xh, nA4);
    // Weight splits (hi/lo), one launch for Wq/Wk/Wv/Wo
    WSplitPtrs wp;
    wp.src[0] = (const float4*)Wq; wp.src[1] = (const float4*)Wk;
    wp.src[2] = (const float4*)Wv; wp.src[3] = (const float4*)Wo;
    wp.hi[0] = (uint2*)wh;            wp.lo[0] = (uint2*)wl;
    wp.hi[1] = (uint2*)(wh + WE);     wp.lo[1] = (uint2*)(wl + WE);
    wp.hi[2] = (uint2*)(wh + 2 * WE); wp.lo[2] = (uint2*)(wl + 2 * WE);
    wp.hi[3] = (uint2*)woh;           wp.lo[3] = (uint2*)wol;
    split_w<<<dim3(nW4 / 256, 4), 256>>>(wp, nW4);

    // Merged QKV projections (2-pass split GEMM)
    QKVParams p;
    p.bias0 = bq; p.bias1 = bk; p.bias2 = bv;
    p.Ch0 = qh; p.Ch1 = kh; p.Ch2 = vh;
    p.Cl1 = kl; p.Cl2 = vl;
    gemm_qkv<<<dim3(GN / 128, Mv / 128, 3), 256, GEMM_SMEM>>>(xh, wh, wl, p);

    // Attention
    flash_mma<<<dim3(Sv / 64, Hv, Bv), 128>>>(qh, kh, kl, vh, vl, mask, oh);

    // Output projection (fp32 + bias)
    gemm_out<<<dim3(GN / 128, Mv / 128), 256, GEMM_SMEM>>>(oh, woh, wol, bo, out);
}

// round 7
// speedup vs baseline: 3.9623x; 1.1260x over previous
#include <cuda_runtime.h>
#include <cuda_fp16.h>
#include <cstdint>

// Shapes are fixed by the problem.
#define Bv 2
#define Sv 2048
#define Ev 1024
#define Hv 16
#define Dv 64
#define Mv (Bv * Sv) /* 4096 */

// Scratch (allocation-free rule: __device__ globals).
__device__ __half g_xh[3][(size_t)Mv * Ev];  // q/k/v activations, fp16 hi only
__device__ __half g_wh[3][(size_t)Ev * Ev];  // Wq/Wk/Wv hi
__device__ __half g_wl[3][(size_t)Ev * Ev];  // Wq/Wk/Wv lo
__device__ __half g_woh[(size_t)Ev * Ev];    // Wo hi
__device__ __half g_wol[(size_t)Ev * Ev];    // Wo lo
__device__ __half g_qh[(size_t)Mv * Ev];     // Q hi
__device__ __half g_kh[(size_t)Mv * Ev];     // K hi
__device__ __half g_kl[(size_t)Mv * Ev];     // K lo
__device__ __half g_vh[(size_t)Mv * Ev];     // V hi (lo dropped)
__device__ __half g_oh[(size_t)Mv * Ev];     // attention out hi only

// ---------------------------------------------------------------------------
// Family-portable tensor-core helpers (HMMA / LDSM / LDGSTS — legal on sm_103)
// ---------------------------------------------------------------------------
__device__ __forceinline__ uint32_t smem_u32(const void* p) {
    uint32_t a;
    asm("{ .reg .u64 t; cvta.to.shared.u64 t, %1; cvt.u32.u64 %0, t; }"
        : "=r"(a) : "l"(p));
    return a;
}

__device__ __forceinline__ void ldsm_x4(uint32_t* r, uint32_t addr) {
    asm volatile("ldmatrix.sync.aligned.m8n8.x4.shared.b16 {%0,%1,%2,%3}, [%4];"
                 : "=r"(r[0]), "=r"(r[1]), "=r"(r[2]), "=r"(r[3]) : "r"(addr));
}

__device__ __forceinline__ void ldsm_x4_t(uint32_t* r, uint32_t addr) {
    asm volatile("ldmatrix.sync.aligned.m8n8.x4.trans.shared.b16 {%0,%1,%2,%3}, [%4];"
                 : "=r"(r[0]), "=r"(r[1]), "=r"(r[2]), "=r"(r[3]) : "r"(addr));
}

__device__ __forceinline__ void mma_f16(float* c, const uint32_t* a, const uint32_t* b) {
    asm volatile(
        "mma.sync.aligned.m16n8k16.row.col.f32.f16.f16.f32 "
        "{%0,%1,%2,%3}, {%4,%5,%6,%7}, {%8,%9}, {%0,%1,%2,%3};"
        : "+f"(c[0]), "+f"(c[1]), "+f"(c[2]), "+f"(c[3])
        : "r"(a[0]), "r"(a[1]), "r"(a[2]), "r"(a[3]), "r"(b[0]), "r"(b[1]));
}

__device__ __forceinline__ void cp16(uint32_t dst, const void* src) {
    asm volatile("cp.async.cg.shared.global [%0], [%1], 16;"
                 :: "r"(dst), "l"(src));
}
#define CP_COMMIT() asm volatile("cp.async.commit_group;" ::: "memory")
#define CP_WAIT1()  asm volatile("cp.async.wait_group 1;" ::: "memory")
#define CP_WAIT0()  asm volatile("cp.async.wait_group 0;" ::: "memory")

__device__ __forceinline__ uint32_t h2u(__half2 v) {
    return *reinterpret_cast<uint32_t*>(&v);
}

// ---------------------------------------------------------------------------
// Activation convert: fp32 -> fp16 hi only. blockIdx.y selects tensor (0..2).
// ---------------------------------------------------------------------------
__global__ void __launch_bounds__(256)
conv_acts(const float4* __restrict__ q, const float4* __restrict__ k,
          const float4* __restrict__ v, uint2* __restrict__ dst, int n4)
{
    const int z = blockIdx.y;
    const float4* src = (z == 0) ? q : (z == 1) ? k : v;
    const int i = blockIdx.x * 256 + threadIdx.x;
    if (i >= n4) return;
    const float4 w = src[i];
    uint2 o;
    o.x = (uint32_t)__half_as_ushort(__float2half_rn(w.x))
        | ((uint32_t)__half_as_ushort(__float2half_rn(w.y)) << 16);
    o.y = (uint32_t)__half_as_ushort(__float2half_rn(w.z))
        | ((uint32_t)__half_as_ushort(__float2half_rn(w.w)) << 16);
    dst[(size_t)z * n4 + i] = o;
}

// ---------------------------------------------------------------------------
// Weight split: fp32 -> fp16 hi/lo. blockIdx.y selects weight (0..3).
// ---------------------------------------------------------------------------
struct WSplitPtrs {
    const float4* src[4];
    uint2* hi[4];
    uint2* lo[4];
};

__global__ void __launch_bounds__(256)
split_w(WSplitPtrs p, int n4)
{
    const int z = blockIdx.y;
    const int i = blockIdx.x * 256 + threadIdx.x;
    if (i >= n4) return;
    const float4 v = p.src[z][i];
    float f[4] = {v.x, v.y, v.z, v.w};
    unsigned short h[4], l[4];
#pragma unroll
    for (int j = 0; j < 4; j++) {
        __half hb = __float2half_rn(f[j]);
        __half lb = __float2half_rn(f[j] - __half2float(hb));
        h[j] = __half_as_ushort(hb);
        l[j] = __half_as_ushort(lb);
    }
    uint2 ho, lo;
    ho.x = (uint32_t)h[0] | ((uint32_t)h[1] << 16);
    ho.y = (uint32_t)h[2] | ((uint32_t)h[3] << 16);
    lo.x = (uint32_t)l[0] | ((uint32_t)l[1] << 16);
    lo.y = (uint32_t)l[2] | ((uint32_t)l[3] << 16);
    p.hi[z][i] = ho;
    p.lo[z][i] = lo;
}

// ---------------------------------------------------------------------------
// HMMA GEMM mainloop, cp.async 2-stage double buffer, 2-pass split:
// C = Ah @ (Wh + Wl)^T.  128x128 CTA tile, BK=32, 8 warps, warp tile 64x32.
// ---------------------------------------------------------------------------
#define GK 1024
#define GN 1024
#define SSTR 40
#define TILEB (128 * SSTR * 2)
#define STGB  (3 * TILEB)
#define GEMM_SMEM (2 * STGB)              /* 61440 */

struct QKVParams {
    const float* bias0; const float* bias1; const float* bias2;
    __half* Ch0; __half* Ch1; __half* Ch2;
    __half* Cl1;                          // K lo only
};

__device__ __forceinline__ void gemm_core(
    const __half* __restrict__ Ahg,
    const __half* __restrict__ Bhg, const __half* __restrict__ Blg,
    uint32_t smem_base, int bm, int bn, int tid, float acc[4][4][4])
{
    const int lane = tid & 31;
    const int wid  = tid >> 5;
    const int wm   = (wid & 1) * 64;
    const int wn   = (wid >> 1) * 32;

    const int r0 = tid >> 2;
    const int c8 = (tid & 3) * 8;
    const uint32_t dst_off  = (uint32_t)(r0 * SSTR + c8) * 2;
    const uint32_t dst_off2 = (uint32_t)((r0 + 64) * SSTR + c8) * 2;

    const __half* gA  = Ahg + (size_t)(bm + r0) * GK + c8;
    const __half* gA2 = Ahg + (size_t)(bm + r0 + 64) * GK + c8;
    const __half* gB  = Bhg + (size_t)(bn + r0) * GK + c8;
    const __half* gB2 = Bhg + (size_t)(bn + r0 + 64) * GK + c8;
    const __half* gBl  = Blg + (size_t)(bn + r0) * GK + c8;
    const __half* gBl2 = Blg + (size_t)(bn + r0 + 64) * GK + c8;

    const int a_row = wm + (lane & 15);
    const int a_col = (lane >> 4) * 8;
    const int g     = lane >> 3;
    const int b_row = wn + (lane & 7) + (g >> 1) * 8;
    const int b_col = (g & 1) * 8;

    auto issue = [&](int kt, int stg) {
        const int ko = kt * 32;
        const uint32_t sb = smem_base + stg * STGB;
        cp16(sb + dst_off,              gA   + ko);
        cp16(sb + dst_off2,             gA2  + ko);
        cp16(sb + TILEB + dst_off,      gB   + ko);
        cp16(sb + TILEB + dst_off2,     gB2  + ko);
        cp16(sb + 2 * TILEB + dst_off,  gBl  + ko);
        cp16(sb + 2 * TILEB + dst_off2, gBl2 + ko);
    };

    issue(0, 0);
    CP_COMMIT();

#pragma unroll 1
    for (int it = 0; it < GK / 32; it++) {
        const int stg = it & 1;
        if (it < GK / 32 - 1) {
            issue(it + 1, (it + 1) & 1);
            CP_COMMIT();
            CP_WAIT1();
        } else {
            CP_WAIT0();
        }
        __syncthreads();

        const uint32_t ah_b = smem_base + stg * STGB;
        const uint32_t bh_b = ah_b + TILEB;
        const uint32_t bl_b = ah_b + 2 * TILEB;

#pragma unroll
        for (int ks = 0; ks < 2; ks++) {
            uint32_t afh[4][4];
#pragma unroll
            for (int i = 0; i < 4; i++) {
                const uint32_t off = ((a_row + i * 16) * SSTR + ks * 16 + a_col) * 2;
                ldsm_x4(afh[i], ah_b + off);
            }
            uint32_t bfh[4][2], bfl[4][2];
#pragma unroll
            for (int j = 0; j < 2; j++) {
                const uint32_t off = ((b_row + j * 16) * SSTR + ks * 16 + b_col) * 2;
                uint32_t r[4];
                ldsm_x4(r, bh_b + off);
                bfh[2 * j][0] = r[0]; bfh[2 * j][1] = r[1];
                bfh[2 * j + 1][0] = r[2]; bfh[2 * j + 1][1] = r[3];
                ldsm_x4(r, bl_b + off);
                bfl[2 * j][0] = r[0]; bfl[2 * j][1] = r[1];
                bfl[2 * j + 1][0] = r[2]; bfl[2 * j + 1][1] = r[3];
            }
#pragma unroll
            for (int i = 0; i < 4; i++)
#pragma unroll
                for (int j = 0; j < 4; j++) {
                    mma_f16(acc[i][j], afh[i], bfh[j]);
                    mma_f16(acc[i][j], afh[i], bfl[j]);
                }
        }
        __syncthreads();
    }
}

// Merged Q/K/V projection: gridDim.z selects which projection.
__global__ void __launch_bounds__(256, 2)
gemm_qkv(const __half* __restrict__ Xh,
         const __half* __restrict__ Wh, const __half* __restrict__ Wl,
         QKVParams p)
{
    extern __shared__ char dynsm[];
    const uint32_t smem_base = smem_u32(dynsm);
    const int z = blockIdx.z;
    const int tid = threadIdx.x, lane = tid & 31, wid = tid >> 5;
    const int bm = blockIdx.y << 7, bn = blockIdx.x << 7;

    const __half* Ahg = Xh + (size_t)z * Mv * Ev;
    const __half* Bhg = Wh + (size_t)z * Ev * Ev;
    const __half* Blg = Wl + (size_t)z * Ev * Ev;
    const float* bias = (z == 0) ? p.bias0 : (z == 1) ? p.bias1 : p.bias2;
    __half* Ch = (z == 0) ? p.Ch0 : (z == 1) ? p.Ch1 : p.Ch2;

    float acc[4][4][4];
#pragma unroll
    for (int i = 0; i < 4; i++)
#pragma unroll
        for (int j = 0; j < 4; j++)
#pragma unroll
            for (int q = 0; q < 4; q++) acc[i][j][q] = 0.f;

    gemm_core(Ahg, Bhg, Blg, smem_base, bm, bn, tid, acc);

    const int wm = (wid & 1) * 64, wn = (wid >> 1) * 32;
#pragma unroll
    for (int i = 0; i < 4; i++) {
        const int grow = bm + wm + i * 16 + (lane >> 2);
#pragma unroll
        for (int j = 0; j < 4; j++) {
            const int gcol = bn + wn + j * 8 + (lane & 3) * 2;
            const float b0 = bias[gcol], b1 = bias[gcol + 1];
            const float v00 = acc[i][j][0] + b0, v01 = acc[i][j][1] + b1;
            const float v10 = acc[i][j][2] + b0, v11 = acc[i][j][3] + b1;
            const __half h00 = __float2half_rn(v00), h01 = __float2half_rn(v01);
            const __half h10 = __float2half_rn(v10), h11 = __float2half_rn(v11);
            *(__half2*)(Ch + (size_t)grow * GN + gcol)       = __halves2half2(h00, h01);
            *(__half2*)(Ch + (size_t)(grow + 8) * GN + gcol) = __halves2half2(h10, h11);
            if (z == 1) {
                const __half l00 = __float2half_rn(v00 - __half2float(h00));
                const __half l01 = __float2half_rn(v01 - __half2float(h01));
                const __half l10 = __float2half_rn(v10 - __half2float(h10));
                const __half l11 = __float2half_rn(v11 - __half2float(h11));
                *(__half2*)(p.Cl1 + (size_t)grow * GN + gcol)       = __halves2half2(l00, l01);
                *(__half2*)(p.Cl1 + (size_t)(grow + 8) * GN + gcol) = __halves2half2(l10, l11);
            }
        }
    }
}

// Output projection: fp32 result + bias.
__global__ void __launch_bounds__(256, 2)
gemm_out(const __half* __restrict__ Ahg,
         const __half* __restrict__ Bhg, const __half* __restrict__ Blg,
         const float* __restrict__ bias, float* __restrict__ Cf)
{
    extern __shared__ char dynsm[];
    const uint32_t smem_base = smem_u32(dynsm);
    const int tid = threadIdx.x, lane = tid & 31, wid = tid >> 5;
    const int bm = blockIdx.y << 7, bn = blockIdx.x << 7;

    float acc[4][4][4];
#pragma unroll
    for (int i = 0; i < 4; i++)
#pragma unroll
        for (int j = 0; j < 4; j++)
#pragma unroll
            for (int q = 0; q < 4; q++) acc[i][j][q] = 0.f;

    gemm_core(Ahg, Bhg, Blg, smem_base, bm, bn, tid, acc);

    const int wm = (wid & 1) * 64, wn = (wid >> 1) * 32;
#pragma unroll
    for (int i = 0; i < 4; i++) {
        const int grow = bm + wm + i * 16 + (lane >> 2);
#pragma unroll
        for (int j = 0; j < 4; j++) {
            const int gcol = bn + wn + j * 8 + (lane & 3) * 2;
            const float b0 = bias[gcol], b1 = bias[gcol + 1];
            float2 v0, v1;
            v0.x = acc[i][j][0] + b0; v0.y = acc[i][j][1] + b1;
            v1.x = acc[i][j][2] + b0; v1.y = acc[i][j][3] + b1;
            *(float2*)(Cf + (size_t)grow * GN + gcol) = v0;
            *(float2*)(Cf + (size_t)(grow + 8) * GN + gcol) = v1;
        }
    }
}

// ---------------------------------------------------------------------------
// Flash attention on HMMA, online softmax. q-tile 128 per CTA (32 rows/warp,
// two A-fragment sets per warp; K/V fragments reused across both m-halves).
// S = Qh (Kh + Kl)^T (2 passes); O = Ph Vh (1 pass).
// Grid: (S/128, H, B) = (16, 16, 2). Block 128 = 4 warps.
// ---------------------------------------------------------------------------
#define KSTR 72

__global__ void __launch_bounds__(128)
flash_mma(const __half* __restrict__ Qh,
          const __half* __restrict__ Kh, const __half* __restrict__ Kl,
          const __half* __restrict__ Vh,
          const int* __restrict__ mask, __half* __restrict__ Oh)
{
    __shared__ __half sKh[64 * KSTR], sKl[64 * KSTR], sVh[64 * KSTR];

    const int tid = threadIdx.x, lane = tid & 31, warp = tid >> 5;
    const int b = blockIdx.z, h = blockIdx.y;
    const int qb = blockIdx.x << 7, hb = h << 6;

    const uint32_t kh_b = smem_u32(sKh), kl_b = smem_u32(sKl), vh_b = smem_u32(sVh);

    const int sr = tid >> 3;          // staging rows 0..15 (+16*i)
    const int sj = (tid & 7) * 8;

    // ---- stage Q (128 rows: 0-63 in sKh, 64-127 in sKl), pull A-frags ----
#pragma unroll
    for (int i = 0; i < 4; i++) {
        const int r = sr + i * 16;
        const size_t gq  = (size_t)(b * Sv + qb + r) * Ev + hb + sj;
        const size_t gq2 = (size_t)(b * Sv + qb + 64 + r) * Ev + hb + sj;
        *(uint4*)(sKh + r * KSTR + sj) = *(const uint4*)(Qh + gq);
        *(uint4*)(sKl + r * KSTR + sj) = *(const uint4*)(Qh + gq2);
    }
    __syncthreads();
    uint32_t qf0[4][4], qf1[4][4];
    {
        const uint32_t qbase = (warp < 2) ? kh_b : kl_b;
        const int lr = (warp & 1) * 32 + (lane & 15);
        const int ac = (lane >> 4) * 8;
#pragma unroll
        for (int kf = 0; kf < 4; kf++) {
            ldsm_x4(qf0[kf], qbase + (uint32_t)(lr * KSTR + kf * 16 + ac) * 2);
            ldsm_x4(qf1[kf], qbase + (uint32_t)((lr + 16) * KSTR + kf * 16 + ac) * 2);
        }
    }

    float m[4], l[4];
#pragma unroll
    for (int i = 0; i < 4; i++) { m[i] = -1e30f; l[i] = 0.f; }
    float o0[8][4], o1[8][4];
#pragma unroll
    for (int n = 0; n < 8; n++)
#pragma unroll
        for (int q = 0; q < 4; q++) { o0[n][q] = 0.f; o1[n][q] = 0.f; }

    // warp handles q rows [warp*32, warp*32+32)
    const int r_base = b * Sv + qb + warp * 32 + (lane >> 2);
    const int* mr0 = mask + (size_t)r_base * Sv;
    const int* mr1 = mask + (size_t)(r_base + 8) * Sv;
    const int* mr2 = mask + (size_t)(r_base + 16) * Sv;
    const int* mr3 = mask + (size_t)(r_base + 24) * Sv;
    const int mc = (lane & 3) * 2;

    const int b_r = (lane & 7) + (lane >> 4) * 8;
    const int b_c = ((lane >> 3) & 1) * 8;
    const int v_r = (lane & 7) + ((lane >> 3) & 1) * 8;
    const int v_c = (lane >> 4) * 8;

    for (int kv = 0; kv < Sv; kv += 64) {
        __syncthreads();
#pragma unroll
        for (int i = 0; i < 4; i++) {
            const int r = sr + i * 16;
            const size_t gk = (size_t)(b * Sv + kv + r) * Ev + hb + sj;
            *(uint4*)(sKh + r * KSTR + sj) = *(const uint4*)(Kh + gk);
            *(uint4*)(sKl + r * KSTR + sj) = *(const uint4*)(Kl + gk);
            *(uint4*)(sVh + r * KSTR + sj) = *(const uint4*)(Vh + gk);
        }
        __syncthreads();

        // ---- S = Q K^T for both m-halves, K frags loaded once ----
        float s0[8][4], s1[8][4];
#pragma unroll
        for (int n = 0; n < 8; n++)
#pragma unroll
            for (int q = 0; q < 4; q++) { s0[n][q] = 0.f; s1[n][q] = 0.f; }

#pragma unroll
        for (int kf = 0; kf < 4; kf++) {
            uint32_t bh[8][2], bl[8][2];
#pragma unroll
            for (int u = 0; u < 4; u++) {
                const uint32_t off =
                    (uint32_t)((b_r + u * 16) * KSTR + b_c + kf * 16) * 2;
                uint32_t t[4];
                ldsm_x4(t, kh_b + off);
                bh[2 * u][0] = t[0]; bh[2 * u][1] = t[1];
                bh[2 * u + 1][0] = t[2]; bh[2 * u + 1][1] = t[3];
                ldsm_x4(t, kl_b + off);
                bl[2 * u][0] = t[0]; bl[2 * u][1] = t[1];
                bl[2 * u + 1][0] = t[2]; bl[2 * u + 1][1] = t[3];
            }
#pragma unroll
            for (int n = 0; n < 8; n++) {
                mma_f16(s0[n], qf0[kf], bh[n]);
                mma_f16(s0[n], qf0[kf], bl[n]);
                mma_f16(s1[n], qf1[kf], bh[n]);
                mma_f16(s1[n], qf1[kf], bl[n]);
            }
        }

        // ---- mask + scale + online softmax (4 row groups) ----
        float mx[4] = {-1e30f, -1e30f, -1e30f, -1e30f};
#pragma unroll
        for (int n = 0; n < 8; n++) {
            const int c = kv + n * 8 + mc;
            const int2 k0 = *(const int2*)(mr0 + c);
            const int2 k1 = *(const int2*)(mr1 + c);
            const int2 k2 = *(const int2*)(mr2 + c);
            const int2 k3 = *(const int2*)(mr3 + c);
            s0[n][0] = k0.x ? s0[n][0] * 0.125f : -1e9f;
            s0[n][1] = k0.y ? s0[n][1] * 0.125f : -1e9f;
            s0[n][2] = k1.x ? s0[n][2] * 0.125f : -1e9f;
            s0[n][3] = k1.y ? s0[n][3] * 0.125f : -1e9f;
            s1[n][0] = k2.x ? s1[n][0] * 0.125f : -1e9f;
            s1[n][1] = k2.y ? s1[n][1] * 0.125f : -1e9f;
            s1[n][2] = k3.x ? s1[n][2] * 0.125f : -1e9f;
            s1[n][3] = k3.y ? s1[n][3] * 0.125f : -1e9f;
            mx[0] = fmaxf(mx[0], fmaxf(s0[n][0], s0[n][1]));
            mx[1] = fmaxf(mx[1], fmaxf(s0[n][2], s0[n][3]));
            mx[2] = fmaxf(mx[2], fmaxf(s1[n][0], s1[n][1]));
            mx[3] = fmaxf(mx[3], fmaxf(s1[n][2], s1[n][3]));
        }
        float corr[4];
#pragma unroll
        for (int i = 0; i < 4; i++) {
            mx[i] = fmaxf(mx[i], __shfl_xor_sync(0xffffffffu, mx[i], 1));
            mx[i] = fmaxf(mx[i], __shfl_xor_sync(0xffffffffu, mx[i], 2));
            const float mn = fmaxf(m[i], mx[i]);
            corr[i] = __expf(m[i] - mn);
            m[i] = mn;
        }

        float rs[4] = {0.f, 0.f, 0.f, 0.f};
#pragma unroll
        for (int n = 0; n < 8; n++) {
            s0[n][0] = __expf(s0[n][0] - m[0]); s0[n][1] = __expf(s0[n][1] - m[0]);
            s0[n][2] = __expf(s0[n][2] - m[1]); s0[n][3] = __expf(s0[n][3] - m[1]);
            s1[n][0] = __expf(s1[n][0] - m[2]); s1[n][1] = __expf(s1[n][1] - m[2]);
            s1[n][2] = __expf(s1[n][2] - m[3]); s1[n][3] = __expf(s1[n][3] - m[3]);
            rs[0] += s0[n][0] + s0[n][1];
            rs[1] += s0[n][2] + s0[n][3];
            rs[2] += s1[n][0] + s1[n][1];
            rs[3] += s1[n][2] + s1[n][3];
            o0[n][0] *= corr[0]; o0[n][1] *= corr[0];
            o0[n][2] *= corr[1]; o0[n][3] *= corr[1];
            o1[n][0] *= corr[2]; o1[n][1] *= corr[2];
            o1[n][2] *= corr[3]; o1[n][3] *= corr[3];
        }
#pragma unroll
        for (int i = 0; i < 4; i++) {
            rs[i] += __shfl_xor_sync(0xffffffffu, rs[i], 1);
            rs[i] += __shfl_xor_sync(0xffffffffu, rs[i], 2);
            l[i] = l[i] * corr[i] + rs[i];
        }

        // ---- pack P fragments (both halves) ----
        uint32_t pf0[4][4], pf1[4][4];
#pragma unroll
        for (int kf = 0; kf < 4; kf++) {
            const int n0 = 2 * kf, n1 = 2 * kf + 1;
            pf0[kf][0] = h2u(__halves2half2(__float2half_rn(s0[n0][0]), __float2half_rn(s0[n0][1])));
            pf0[kf][1] = h2u(__halves2half2(__float2half_rn(s0[n0][2]), __float2half_rn(s0[n0][3])));
            pf0[kf][2] = h2u(__halves2half2(__float2half_rn(s0[n1][0]), __float2half_rn(s0[n1][1])));
            pf0[kf][3] = h2u(__halves2half2(__float2half_rn(s0[n1][2]), __float2half_rn(s0[n1][3])));
            pf1[kf][0] = h2u(__halves2half2(__float2half_rn(s1[n0][0]), __float2half_rn(s1[n0][1])));
            pf1[kf][1] = h2u(__halves2half2(__float2half_rn(s1[n0][2]), __float2half_rn(s1[n0][3])));
            pf1[kf][2] = h2u(__halves2half2(__float2half_rn(s1[n1][0]), __float2half_rn(s1[n1][1])));
            pf1[kf][3] = h2u(__halves2half2(__float2half_rn(s1[n1][2]), __float2half_rn(s1[n1][3])));
        }

        // ---- O += P V (V hi only), V frags loaded once, used by both halves ----
#pragma unroll
        for (int kf = 0; kf < 4; kf++) {
            uint32_t wh[8][2];
#pragma unroll
            for (int u = 0; u < 4; u++) {
                const uint32_t off =
                    (uint32_t)((v_r + kf * 16) * KSTR + v_c + u * 16) * 2;
                uint32_t t[4];
                ldsm_x4_t(t, vh_b + off);
                wh[2 * u][0] = t[0]; wh[2 * u][1] = t[1];
                wh[2 * u + 1][0] = t[2]; wh[2 * u + 1][1] = t[3];
            }
#pragma unroll
            for (int n = 0; n < 8; n++) {
                mma_f16(o0[n], pf0[kf], wh[n]);
                mma_f16(o1[n], pf1[kf], wh[n]);
            }
        }
    }

    // ---- normalize and write (4 row groups x 8 n-blocks) ----
    const float i0 = 1.f / l[0], i1 = 1.f / l[1];
    const float i2 = 1.f / l[2], i3 = 1.f / l[3];
#pragma unroll
    for (int n = 0; n < 8; n++) {
        const int col = hb + n * 8 + mc;
        *(__half2*)(Oh + (size_t)r_base * Ev + col) =
            __halves2half2(__float2half_rn(o0[n][0] * i0), __float2half_rn(o0[n][1] * i0));
        *(__half2*)(Oh + (size_t)(r_base + 8) * Ev + col) =
            __halves2half2(__float2half_rn(o0[n][2] * i1), __float2half_rn(o0[n][3] * i1));
        *(__half2*)(Oh + (size_t)(r_base + 16) * Ev + col) =
            __halves2half2(__float2half_rn(o1[n][0] * i2), __float2half_rn(o1[n][1] * i2));
        *(__half2*)(Oh + (size_t)(r_base + 24) * Ev + col) =
            __halves2half2(__float2half_rn(o1[n][2] * i3), __float2half_rn(o1[n][3] * i3));
    }
}

// ---------------------------------------------------------------------------
extern "C" void kernel_launch(void* const* d_in, const int* in_sizes, int n_in,
                              void* d_out, int out_size)
{
    (void)in_sizes; (void)n_in; (void)out_size;
    const float* query = (const float*)d_in[0];
    const float* key   = (const float*)d_in[1];
    const float* value = (const float*)d_in[2];
    const int*   mask  = (const int*)  d_in[3];
    const float* Wq = (const float*)d_in[4];
    const float* bq = (const float*)d_in[5];
    const float* Wk = (const float*)d_in[6];
    const float* bk = (const float*)d_in[7];
    const float* Wv = (const float*)d_in[8];
    const float* bv = (const float*)d_in[9];
    const float* Wo = (const float*)d_in[10];
    const float* bo = (const float*)d_in[11];
    float* out = (float*)d_out;

    __half *xh, *wh, *wl, *woh, *wol, *qh, *kh, *kl, *vh, *oh;
    cudaGetSymbolAddress((void**)&xh, g_xh);
    cudaGetSymbolAddress((void**)&wh, g_wh);
    cudaGetSymbolAddress((void**)&wl, g_wl);
    cudaGetSymbolAddress((void**)&woh, g_woh);
    cudaGetSymbolAddress((void**)&wol, g_wol);
    cudaGetSymbolAddress((void**)&qh, g_qh);
    cudaGetSymbolAddress((void**)&kh, g_kh);
    cudaGetSymbolAddress((void**)&kl, g_kl);
    cudaGetSymbolAddress((void**)&vh, g_vh);
    cudaGetSymbolAddress((void**)&oh, g_oh);

    cudaFuncSetAttribute(gemm_qkv,
                         cudaFuncAttributeMaxDynamicSharedMemorySize, GEMM_SMEM);
    cudaFuncSetAttribute(gemm_out,
                         cudaFuncAttributeMaxDynamicSharedMemorySize, GEMM_SMEM);

    const int nA4 = (Mv * Ev) / 4;
    const int nW4 = (Ev * Ev) / 4;
    const size_t WE = (size_t)Ev * Ev;

    conv_acts<<<dim3(nA4 / 256, 3), 256>>>((const float4*)query, (const float4*)key,
                                           (const float4*)value, (uint2*)xh, nA4);
    WSplitPtrs wp;
    wp.src[0] = (const float4*)Wq; wp.src[1] = (const float4*)Wk;
    wp.src[2] = (const float4*)Wv; wp.src[3] = (const float4*)Wo;
    wp.hi[0] = (uint2*)wh;            wp.lo[0] = (uint2*)wl;
    wp.hi[1] = (uint2*)(wh + WE);     wp.lo[1] = (uint2*)(wl + WE);
    wp.hi[2] = (uint2*)(wh + 2 * WE); wp.lo[2] = (uint2*)(wl + 2 * WE);
    wp.hi[3] = (uint2*)woh;           wp.lo[3] = (uint2*)wol;
    split_w<<<dim3(nW4 / 256, 4), 256>>>(wp, nW4);

    QKVParams p;
    p.bias0 = bq; p.bias1 = bk; p.bias2 = bv;
    p.Ch0 = qh; p.Ch1 = kh; p.Ch2 = vh;
    p.Cl1 = kl;
    gemm_qkv<<<dim3(GN / 128, Mv / 128, 3), 256, GEMM_SMEM>>>(xh, wh, wl, p);

    flash_mma<<<dim3(Sv / 128, Hv, Bv), 128>>>(qh, kh, kl, vh, mask, oh);

    gemm_out<<<dim3(GN / 128, Mv / 128), 256, GEMM_SMEM>>>(oh, woh, wol, bo, out);
}

// round 8
// speedup vs baseline: 4.6927x; 1.1843x over previous
#include <cuda_runtime.h>
#include <cuda_fp16.h>
#include <cstdint>

// Shapes are fixed by the problem.
#define Bv 2
#define Sv 2048
#define Ev 1024
#define Hv 16
#define Dv 64
#define Mv (Bv * Sv) /* 4096 */

// Scratch (allocation-free rule: __device__ globals).
__device__ __half g_xh[3][(size_t)Mv * Ev];  // q/k/v activations, fp16 hi only
__device__ __half g_wh[3][(size_t)Ev * Ev];  // Wq/Wk/Wv hi
__device__ __half g_wl[3][(size_t)Ev * Ev];  // Wq/Wk/Wv lo
__device__ __half g_woh[(size_t)Ev * Ev];    // Wo hi
__device__ __half g_wol[(size_t)Ev * Ev];    // Wo lo
__device__ __half g_qh[(size_t)Mv * Ev];     // Q hi
__device__ __half g_kh[(size_t)Mv * Ev];     // K hi (lo dropped)
__device__ __half g_vh[(size_t)Mv * Ev];     // V hi
__device__ __half g_oh[(size_t)Mv * Ev];     // attention out hi

// ---------------------------------------------------------------------------
// Family-portable tensor-core helpers (HMMA / LDSM / LDGSTS — legal on sm_103)
// ---------------------------------------------------------------------------
__device__ __forceinline__ uint32_t smem_u32(const void* p) {
    uint32_t a;
    asm("{ .reg .u64 t; cvta.to.shared.u64 t, %1; cvt.u32.u64 %0, t; }"
        : "=r"(a) : "l"(p));
    return a;
}

__device__ __forceinline__ void ldsm_x4(uint32_t* r, uint32_t addr) {
    asm volatile("ldmatrix.sync.aligned.m8n8.x4.shared.b16 {%0,%1,%2,%3}, [%4];"
                 : "=r"(r[0]), "=r"(r[1]), "=r"(r[2]), "=r"(r[3]) : "r"(addr));
}

__device__ __forceinline__ void ldsm_x4_t(uint32_t* r, uint32_t addr) {
    asm volatile("ldmatrix.sync.aligned.m8n8.x4.trans.shared.b16 {%0,%1,%2,%3}, [%4];"
                 : "=r"(r[0]), "=r"(r[1]), "=r"(r[2]), "=r"(r[3]) : "r"(addr));
}

__device__ __forceinline__ void mma_f16(float* c, const uint32_t* a, const uint32_t* b) {
    asm volatile(
        "mma.sync.aligned.m16n8k16.row.col.f32.f16.f16.f32 "
        "{%0,%1,%2,%3}, {%4,%5,%6,%7}, {%8,%9}, {%0,%1,%2,%3};"
        : "+f"(c[0]), "+f"(c[1]), "+f"(c[2]), "+f"(c[3])
        : "r"(a[0]), "r"(a[1]), "r"(a[2]), "r"(a[3]), "r"(b[0]), "r"(b[1]));
}

__device__ __forceinline__ void cp16(uint32_t dst, const void* src) {
    asm volatile("cp.async.cg.shared.global [%0], [%1], 16;"
                 :: "r"(dst), "l"(src));
}
#define CP_COMMIT() asm volatile("cp.async.commit_group;" ::: "memory")
#define CP_WAIT1()  asm volatile("cp.async.wait_group 1;" ::: "memory")
#define CP_WAIT0()  asm volatile("cp.async.wait_group 0;" ::: "memory")

__device__ __forceinline__ uint32_t h2u(__half2 v) {
    return *reinterpret_cast<uint32_t*>(&v);
}

// ---------------------------------------------------------------------------
// Activation convert: fp32 -> fp16 hi only. blockIdx.y selects tensor (0..2).
// ---------------------------------------------------------------------------
__global__ void __launch_bounds__(256)
conv_acts(const float4* __restrict__ q, const float4* __restrict__ k,
          const float4* __restrict__ v, uint2* __restrict__ dst, int n4)
{
    const int z = blockIdx.y;
    const float4* src = (z == 0) ? q : (z == 1) ? k : v;
    const int i = blockIdx.x * 256 + threadIdx.x;
    if (i >= n4) return;
    const float4 w = src[i];
    uint2 o;
    o.x = (uint32_t)__half_as_ushort(__float2half_rn(w.x))
        | ((uint32_t)__half_as_ushort(__float2half_rn(w.y)) << 16);
    o.y = (uint32_t)__half_as_ushort(__float2half_rn(w.z))
        | ((uint32_t)__half_as_ushort(__float2half_rn(w.w)) << 16);
    dst[(size_t)z * n4 + i] = o;
}

// ---------------------------------------------------------------------------
// Weight split: fp32 -> fp16 hi/lo. blockIdx.y selects weight (0..3).
// ---------------------------------------------------------------------------
struct WSplitPtrs {
    const float4* src[4];
    uint2* hi[4];
    uint2* lo[4];
};

__global__ void __launch_bounds__(256)
split_w(WSplitPtrs p, int n4)
{
    const int z = blockIdx.y;
    const int i = blockIdx.x * 256 + threadIdx.x;
    if (i >= n4) return;
    const float4 v = p.src[z][i];
    float f[4] = {v.x, v.y, v.z, v.w};
    unsigned short h[4], l[4];
#pragma unroll
    for (int j = 0; j < 4; j++) {
        __half hb = __float2half_rn(f[j]);
        __half lb = __float2half_rn(f[j] - __half2float(hb));
        h[j] = __half_as_ushort(hb);
        l[j] = __half_as_ushort(lb);
    }
    uint2 ho, lo;
    ho.x = (uint32_t)h[0] | ((uint32_t)h[1] << 16);
    ho.y = (uint32_t)h[2] | ((uint32_t)h[3] << 16);
    lo.x = (uint32_t)l[0] | ((uint32_t)l[1] << 16);
    lo.y = (uint32_t)l[2] | ((uint32_t)l[3] << 16);
    p.hi[z][i] = ho;
    p.lo[z][i] = lo;
}

// ---------------------------------------------------------------------------
// HMMA GEMM mainloop, cp.async 2-stage double buffer, 2-pass split:
// C = Ah @ (Wh + Wl)^T.  128x128 CTA tile, BK=32, 8 warps, warp tile 64x32.
// ---------------------------------------------------------------------------
#define GK 1024
#define GN 1024
#define SSTR 40
#define TILEB (128 * SSTR * 2)
#define STGB  (3 * TILEB)
#define GEMM_SMEM (2 * STGB)              /* 61440 */

struct QKVParams {
    const float* bias0; const float* bias1; const float* bias2;
    __half* Ch0; __half* Ch1; __half* Ch2;
};

__device__ __forceinline__ void gemm_core(
    const __half* __restrict__ Ahg,
    const __half* __restrict__ Bhg, const __half* __restrict__ Blg,
    uint32_t smem_base, int bm, int bn, int tid, float acc[4][4][4])
{
    const int lane = tid & 31;
    const int wid  = tid >> 5;
    const int wm   = (wid & 1) * 64;
    const int wn   = (wid >> 1) * 32;

    const int r0 = tid >> 2;
    const int c8 = (tid & 3) * 8;
    const uint32_t dst_off  = (uint32_t)(r0 * SSTR + c8) * 2;
    const uint32_t dst_off2 = (uint32_t)((r0 + 64) * SSTR + c8) * 2;

    const __half* gA  = Ahg + (size_t)(bm + r0) * GK + c8;
    const __half* gA2 = Ahg + (size_t)(bm + r0 + 64) * GK + c8;
    const __half* gB  = Bhg + (size_t)(bn + r0) * GK + c8;
    const __half* gB2 = Bhg + (size_t)(bn + r0 + 64) * GK + c8;
    const __half* gBl  = Blg + (size_t)(bn + r0) * GK + c8;
    const __half* gBl2 = Blg + (size_t)(bn + r0 + 64) * GK + c8;

    const int a_row = wm + (lane & 15);
    const int a_col = (lane >> 4) * 8;
    const int g     = lane >> 3;
    const int b_row = wn + (lane & 7) + (g >> 1) * 8;
    const int b_col = (g & 1) * 8;

    auto issue = [&](int kt, int stg) {
        const int ko = kt * 32;
        const uint32_t sb = smem_base + stg * STGB;
        cp16(sb + dst_off,              gA   + ko);
        cp16(sb + dst_off2,             gA2  + ko);
        cp16(sb + TILEB + dst_off,      gB   + ko);
        cp16(sb + TILEB + dst_off2,     gB2  + ko);
        cp16(sb + 2 * TILEB + dst_off,  gBl  + ko);
        cp16(sb + 2 * TILEB + dst_off2, gBl2 + ko);
    };

    issue(0, 0);
    CP_COMMIT();

#pragma unroll 1
    for (int it = 0; it < GK / 32; it++) {
        const int stg = it & 1;
        if (it < GK / 32 - 1) {
            issue(it + 1, (it + 1) & 1);
            CP_COMMIT();
            CP_WAIT1();
        } else {
            CP_WAIT0();
        }
        __syncthreads();

        const uint32_t ah_b = smem_base + stg * STGB;
        const uint32_t bh_b = ah_b + TILEB;
        const uint32_t bl_b = ah_b + 2 * TILEB;

#pragma unroll
        for (int ks = 0; ks < 2; ks++) {
            uint32_t afh[4][4];
#pragma unroll
            for (int i = 0; i < 4; i++) {
                const uint32_t off = ((a_row + i * 16) * SSTR + ks * 16 + a_col) * 2;
                ldsm_x4(afh[i], ah_b + off);
            }
            uint32_t bfh[4][2], bfl[4][2];
#pragma unroll
            for (int j = 0; j < 2; j++) {
                const uint32_t off = ((b_row + j * 16) * SSTR + ks * 16 + b_col) * 2;
                uint32_t r[4];
                ldsm_x4(r, bh_b + off);
                bfh[2 * j][0] = r[0]; bfh[2 * j][1] = r[1];
                bfh[2 * j + 1][0] = r[2]; bfh[2 * j + 1][1] = r[3];
                ldsm_x4(r, bl_b + off);
                bfl[2 * j][0] = r[0]; bfl[2 * j][1] = r[1];
                bfl[2 * j + 1][0] = r[2]; bfl[2 * j + 1][1] = r[3];
            }
#pragma unroll
            for (int i = 0; i < 4; i++)
#pragma unroll
                for (int j = 0; j < 4; j++) {
                    mma_f16(acc[i][j], afh[i], bfh[j]);
                    mma_f16(acc[i][j], afh[i], bfl[j]);
                }
        }
        __syncthreads();
    }
}

// Merged Q/K/V projection: gridDim.z selects which projection. fp16 hi out.
__global__ void __launch_bounds__(256, 2)
gemm_qkv(const __half* __restrict__ Xh,
         const __half* __restrict__ Wh, const __half* __restrict__ Wl,
         QKVParams p)
{
    extern __shared__ char dynsm[];
    const uint32_t smem_base = smem_u32(dynsm);
    const int z = blockIdx.z;
    const int tid = threadIdx.x, lane = tid & 31, wid = tid >> 5;
    const int bm = blockIdx.y << 7, bn = blockIdx.x << 7;

    const __half* Ahg = Xh + (size_t)z * Mv * Ev;
    const __half* Bhg = Wh + (size_t)z * Ev * Ev;
    const __half* Blg = Wl + (size_t)z * Ev * Ev;
    const float* bias = (z == 0) ? p.bias0 : (z == 1) ? p.bias1 : p.bias2;
    __half* Ch = (z == 0) ? p.Ch0 : (z == 1) ? p.Ch1 : p.Ch2;

    float acc[4][4][4];
#pragma unroll
    for (int i = 0; i < 4; i++)
#pragma unroll
        for (int j = 0; j < 4; j++)
#pragma unroll
            for (int q = 0; q < 4; q++) acc[i][j][q] = 0.f;

    gemm_core(Ahg, Bhg, Blg, smem_base, bm, bn, tid, acc);

    const int wm = (wid & 1) * 64, wn = (wid >> 1) * 32;
#pragma unroll
    for (int i = 0; i < 4; i++) {
        const int grow = bm + wm + i * 16 + (lane >> 2);
#pragma unroll
        for (int j = 0; j < 4; j++) {
            const int gcol = bn + wn + j * 8 + (lane & 3) * 2;
            const float b0 = bias[gcol], b1 = bias[gcol + 1];
            *(__half2*)(Ch + (size_t)grow * GN + gcol) =
                __halves2half2(__float2half_rn(acc[i][j][0] + b0),
                               __float2half_rn(acc[i][j][1] + b1));
            *(__half2*)(Ch + (size_t)(grow + 8) * GN + gcol) =
                __halves2half2(__float2half_rn(acc[i][j][2] + b0),
                               __float2half_rn(acc[i][j][3] + b1));
        }
    }
}

// Output projection: fp32 result + bias.
__global__ void __launch_bounds__(256, 2)
gemm_out(const __half* __restrict__ Ahg,
         const __half* __restrict__ Bhg, const __half* __restrict__ Blg,
         const float* __restrict__ bias, float* __restrict__ Cf)
{
    extern __shared__ char dynsm[];
    const uint32_t smem_base = smem_u32(dynsm);
    const int tid = threadIdx.x, lane = tid & 31, wid = tid >> 5;
    const int bm = blockIdx.y << 7, bn = blockIdx.x << 7;

    float acc[4][4][4];
#pragma unroll
    for (int i = 0; i < 4; i++)
#pragma unroll
        for (int j = 0; j < 4; j++)
#pragma unroll
            for (int q = 0; q < 4; q++) acc[i][j][q] = 0.f;

    gemm_core(Ahg, Bhg, Blg, smem_base, bm, bn, tid, acc);

    const int wm = (wid & 1) * 64, wn = (wid >> 1) * 32;
#pragma unroll
    for (int i = 0; i < 4; i++) {
        const int grow = bm + wm + i * 16 + (lane >> 2);
#pragma unroll
        for (int j = 0; j < 4; j++) {
            const int gcol = bn + wn + j * 8 + (lane & 3) * 2;
            const float b0 = bias[gcol], b1 = bias[gcol + 1];
            float2 v0, v1;
            v0.x = acc[i][j][0] + b0; v0.y = acc[i][j][1] + b1;
            v1.x = acc[i][j][2] + b0; v1.y = acc[i][j][3] + b1;
            *(float2*)(Cf + (size_t)grow * GN + gcol) = v0;
            *(float2*)(Cf + (size_t)(grow + 8) * GN + gcol) = v1;
        }
    }
}

// ---------------------------------------------------------------------------
// Flash attention on HMMA, online softmax, cp.async double-buffered K/V.
// q-tile 128 per CTA (32 rows/warp, two A-fragment sets; K/V frags reused).
// S = Qh Kh^T (1 pass, pure fp16); O = Ph Vh (1 pass).
// Grid: (S/128, H, B) = (16, 16, 2). Block 128 = 4 warps.
// ---------------------------------------------------------------------------
#define KSTR 72

__global__ void __launch_bounds__(128)
flash_mma(const __half* __restrict__ Qh,
          const __half* __restrict__ Kh, const __half* __restrict__ Vh,
          const int* __restrict__ mask, __half* __restrict__ Oh)
{
    __shared__ __half sK[2][64 * KSTR], sV[2][64 * KSTR];

    const int tid = threadIdx.x, lane = tid & 31, warp = tid >> 5;
    const int b = blockIdx.z, h = blockIdx.y;
    const int qb = blockIdx.x << 7, hb = h << 6;

    const uint32_t k_b[2] = {smem_u32(sK[0]), smem_u32(sK[1])};
    const uint32_t v_b[2] = {smem_u32(sV[0]), smem_u32(sV[1])};

    const int sr = tid >> 3;          // staging rows 0..15 (+16*i)
    const int sj = (tid & 7) * 8;

    // ---- stage Q (rows 0-63 in sK[0], 64-127 in sK[1]), pull A-frags ----
#pragma unroll
    for (int i = 0; i < 4; i++) {
        const int r = sr + i * 16;
        const size_t gq  = (size_t)(b * Sv + qb + r) * Ev + hb + sj;
        const size_t gq2 = (size_t)(b * Sv + qb + 64 + r) * Ev + hb + sj;
        *(uint4*)(sK[0] + r * KSTR + sj) = *(const uint4*)(Qh + gq);
        *(uint4*)(sK[1] + r * KSTR + sj) = *(const uint4*)(Qh + gq2);
    }
    __syncthreads();
    uint32_t qf0[4][4], qf1[4][4];
    {
        const uint32_t qbase = k_b[warp >> 1];
        const int lr = (warp & 1) * 32 + (lane & 15);
        const int ac = (lane >> 4) * 8;
#pragma unroll
        for (int kf = 0; kf < 4; kf++) {
            ldsm_x4(qf0[kf], qbase + (uint32_t)(lr * KSTR + kf * 16 + ac) * 2);
            ldsm_x4(qf1[kf], qbase + (uint32_t)((lr + 16) * KSTR + kf * 16 + ac) * 2);
        }
    }
    __syncthreads();  // all Q frags read before stage buffers are overwritten

    float m[4], l[4];
#pragma unroll
    for (int i = 0; i < 4; i++) { m[i] = -1e30f; l[i] = 0.f; }
    float o0[8][4], o1[8][4];
#pragma unroll
    for (int n = 0; n < 8; n++)
#pragma unroll
        for (int q = 0; q < 4; q++) { o0[n][q] = 0.f; o1[n][q] = 0.f; }

    const int r_base = b * Sv + qb + warp * 32 + (lane >> 2);
    const int* mr0 = mask + (size_t)r_base * Sv;
    const int* mr1 = mask + (size_t)(r_base + 8) * Sv;
    const int* mr2 = mask + (size_t)(r_base + 16) * Sv;
    const int* mr3 = mask + (size_t)(r_base + 24) * Sv;
    const int mc = (lane & 3) * 2;

    const int b_r = (lane & 7) + (lane >> 4) * 8;
    const int b_c = ((lane >> 3) & 1) * 8;
    const int v_r = (lane & 7) + ((lane >> 3) & 1) * 8;
    const int v_c = (lane >> 4) * 8;

    const uint32_t stg_off = (uint32_t)(sr * KSTR + sj) * 2;

    auto issueKV = [&](int kvt, int stg) {
        const int kv = kvt * 64;
#pragma unroll
        for (int i = 0; i < 4; i++) {
            const int r = sr + i * 16;
            const size_t gk = (size_t)(b * Sv + kv + r) * Ev + hb + sj;
            const uint32_t doff = stg_off + (uint32_t)(i * 16 * KSTR) * 2;
            cp16(k_b[stg] + doff, Kh + gk);
            cp16(v_b[stg] + doff, Vh + gk);
        }
    };

    issueKV(0, 0);
    CP_COMMIT();

#pragma unroll 1
    for (int it = 0; it < Sv / 64; it++) {
        const int stg = it & 1;
        const int kv = it * 64;
        if (it < Sv / 64 - 1) {
            issueKV(it + 1, stg ^ 1);
            CP_COMMIT();
            CP_WAIT1();
        } else {
            CP_WAIT0();
        }
        __syncthreads();

        // ---- S = Q K^T for both m-halves, K frags loaded once ----
        float s0[8][4], s1[8][4];
#pragma unroll
        for (int n = 0; n < 8; n++)
#pragma unroll
            for (int q = 0; q < 4; q++) { s0[n][q] = 0.f; s1[n][q] = 0.f; }

#pragma unroll
        for (int kf = 0; kf < 4; kf++) {
            uint32_t bh[8][2];
#pragma unroll
            for (int u = 0; u < 4; u++) {
                const uint32_t off =
                    (uint32_t)((b_r + u * 16) * KSTR + b_c + kf * 16) * 2;
                uint32_t t[4];
                ldsm_x4(t, k_b[stg] + off);
                bh[2 * u][0] = t[0]; bh[2 * u][1] = t[1];
                bh[2 * u + 1][0] = t[2]; bh[2 * u + 1][1] = t[3];
            }
#pragma unroll
            for (int n = 0; n < 8; n++) {
                mma_f16(s0[n], qf0[kf], bh[n]);
                mma_f16(s1[n], qf1[kf], bh[n]);
            }
        }

        // ---- mask + scale + online softmax (4 row groups) ----
        float mx[4] = {-1e30f, -1e30f, -1e30f, -1e30f};
#pragma unroll
        for (int n = 0; n < 8; n++) {
            const int c = kv + n * 8 + mc;
            const int2 k0 = *(const int2*)(mr0 + c);
            const int2 k1 = *(const int2*)(mr1 + c);
            const int2 k2 = *(const int2*)(mr2 + c);
            const int2 k3 = *(const int2*)(mr3 + c);
            s0[n][0] = k0.x ? s0[n][0] * 0.125f : -1e9f;
            s0[n][1] = k0.y ? s0[n][1] * 0.125f : -1e9f;
            s0[n][2] = k1.x ? s0[n][2] * 0.125f : -1e9f;
            s0[n][3] = k1.y ? s0[n][3] * 0.125f : -1e9f;
            s1[n][0] = k2.x ? s1[n][0] * 0.125f : -1e9f;
            s1[n][1] = k2.y ? s1[n][1] * 0.125f : -1e9f;
            s1[n][2] = k3.x ? s1[n][2] * 0.125f : -1e9f;
            s1[n][3] = k3.y ? s1[n][3] * 0.125f : -1e9f;
            mx[0] = fmaxf(mx[0], fmaxf(s0[n][0], s0[n][1]));
            mx[1] = fmaxf(mx[1], fmaxf(s0[n][2], s0[n][3]));
            mx[2] = fmaxf(mx[2], fmaxf(s1[n][0], s1[n][1]));
            mx[3] = fmaxf(mx[3], fmaxf(s1[n][2], s1[n][3]));
        }
        float corr[4];
#pragma unroll
        for (int i = 0; i < 4; i++) {
            mx[i] = fmaxf(mx[i], __shfl_xor_sync(0xffffffffu, mx[i], 1));
            mx[i] = fmaxf(mx[i], __shfl_xor_sync(0xffffffffu, mx[i], 2));
            const float mn = fmaxf(m[i], mx[i]);
            corr[i] = __expf(m[i] - mn);
            m[i] = mn;
        }

        float rs[4] = {0.f, 0.f, 0.f, 0.f};
#pragma unroll
        for (int n = 0; n < 8; n++) {
            s0[n][0] = __expf(s0[n][0] - m[0]); s0[n][1] = __expf(s0[n][1] - m[0]);
            s0[n][2] = __expf(s0[n][2] - m[1]); s0[n][3] = __expf(s0[n][3] - m[1]);
            s1[n][0] = __expf(s1[n][0] - m[2]); s1[n][1] = __expf(s1[n][1] - m[2]);
            s1[n][2] = __expf(s1[n][2] - m[3]); s1[n][3] = __expf(s1[n][3] - m[3]);
            rs[0] += s0[n][0] + s0[n][1];
            rs[1] += s0[n][2] + s0[n][3];
            rs[2] += s1[n][0] + s1[n][1];
            rs[3] += s1[n][2] + s1[n][3];
            o0[n][0] *= corr[0]; o0[n][1] *= corr[0];
            o0[n][2] *= corr[1]; o0[n][3] *= corr[1];
            o1[n][0] *= corr[2]; o1[n][1] *= corr[2];
            o1[n][2] *= corr[3]; o1[n][3] *= corr[3];
        }
#pragma unroll
        for (int i = 0; i < 4; i++) {
            rs[i] += __shfl_xor_sync(0xffffffffu, rs[i], 1);
            rs[i] += __shfl_xor_sync(0xffffffffu, rs[i], 2);
            l[i] = l[i] * corr[i] + rs[i];
        }

        // ---- pack P fragments (both halves) ----
        uint32_t pf0[4][4], pf1[4][4];
#pragma unroll
        for (int kf = 0; kf < 4; kf++) {
            const int n0 = 2 * kf, n1 = 2 * kf + 1;
            pf0[kf][0] = h2u(__halves2half2(__float2half_rn(s0[n0][0]), __float2half_rn(s0[n0][1])));
            pf0[kf][1] = h2u(__halves2half2(__float2half_rn(s0[n0][2]), __float2half_rn(s0[n0][3])));
            pf0[kf][2] = h2u(__halves2half2(__float2half_rn(s0[n1][0]), __float2half_rn(s0[n1][1])));
            pf0[kf][3] = h2u(__halves2half2(__float2half_rn(s0[n1][2]), __float2half_rn(s0[n1][3])));
            pf1[kf][0] = h2u(__halves2half2(__float2half_rn(s1[n0][0]), __float2half_rn(s1[n0][1])));
            pf1[kf][1] = h2u(__halves2half2(__float2half_rn(s1[n0][2]), __float2half_rn(s1[n0][3])));
            pf1[kf][2] = h2u(__halves2half2(__float2half_rn(s1[n1][0]), __float2half_rn(s1[n1][1])));
            pf1[kf][3] = h2u(__halves2half2(__float2half_rn(s1[n1][2]), __float2half_rn(s1[n1][3])));
        }

        // ---- O += P V, V frags loaded once, used by both halves ----
#pragma unroll
        for (int kf = 0; kf < 4; kf++) {
            uint32_t wh[8][2];
#pragma unroll
            for (int u = 0; u < 4; u++) {
                const uint32_t off =
                    (uint32_t)((v_r + kf * 16) * KSTR + v_c + u * 16) * 2;
                uint32_t t[4];
                ldsm_x4_t(t, v_b[stg] + off);
                wh[2 * u][0] = t[0]; wh[2 * u][1] = t[1];
                wh[2 * u + 1][0] = t[2]; wh[2 * u + 1][1] = t[3];
            }
#pragma unroll
            for (int n = 0; n < 8; n++) {
                mma_f16(o0[n], pf0[kf], wh[n]);
                mma_f16(o1[n], pf1[kf], wh[n]);
            }
        }
        __syncthreads();  // stage reads done before next issue overwrites
    }

    // ---- normalize and write (4 row groups x 8 n-blocks) ----
    const float i0 = 1.f / l[0], i1 = 1.f / l[1];
    const float i2 = 1.f / l[2], i3 = 1.f / l[3];
#pragma unroll
    for (int n = 0; n < 8; n++) {
        const int col = hb + n * 8 + mc;
        *(__half2*)(Oh + (size_t)r_base * Ev + col) =
            __halves2half2(__float2half_rn(o0[n][0] * i0), __float2half_rn(o0[n][1] * i0));
        *(__half2*)(Oh + (size_t)(r_base + 8) * Ev + col) =
            __halves2half2(__float2half_rn(o0[n][2] * i1), __float2half_rn(o0[n][3] * i1));
        *(__half2*)(Oh + (size_t)(r_base + 16) * Ev + col) =
            __halves2half2(__float2half_rn(o1[n][0] * i2), __float2half_rn(o1[n][1] * i2));
        *(__half2*)(Oh + (size_t)(r_base + 24) * Ev + col) =
            __halves2half2(__float2half_rn(o1[n][2] * i3), __float2half_rn(o1[n][3] * i3));
    }
}

// ---------------------------------------------------------------------------
extern "C" void kernel_launch(void* const* d_in, const int* in_sizes, int n_in,
                              void* d_out, int out_size)
{
    (void)in_sizes; (void)n_in; (void)out_size;
    const float* query = (const float*)d_in[0];
    const float* key   = (const float*)d_in[1];
    const float* value = (const float*)d_in[2];
    const int*   mask  = (const int*)  d_in[3];
    const float* Wq = (const float*)d_in[4];
    const float* bq = (const float*)d_in[5];
    const float* Wk = (const float*)d_in[6];
    const float* bk = (const float*)d_in[7];
    const float* Wv = (const float*)d_in[8];
    const float* bv = (const float*)d_in[9];
    const float* Wo = (const float*)d_in[10];
    const float* bo = (const float*)d_in[11];
    float* out = (float*)d_out;

    __half *xh, *wh, *wl, *woh, *wol, *qh, *kh, *vh, *oh;
    cudaGetSymbolAddress((void**)&xh, g_xh);
    cudaGetSymbolAddress((void**)&wh, g_wh);
    cudaGetSymbolAddress((void**)&wl, g_wl);
    cudaGetSymbolAddress((void**)&woh, g_woh);
    cudaGetSymbolAddress((void**)&wol, g_wol);
    cudaGetSymbolAddress((void**)&qh, g_qh);
    cudaGetSymbolAddress((void**)&kh, g_kh);
    cudaGetSymbolAddress((void**)&vh, g_vh);
    cudaGetSymbolAddress((void**)&oh, g_oh);

    cudaFuncSetAttribute(gemm_qkv,
                         cudaFuncAttributeMaxDynamicSharedMemorySize, GEMM_SMEM);
    cudaFuncSetAttribute(gemm_out,
                         cudaFuncAttributeMaxDynamicSharedMemorySize, GEMM_SMEM);

    const int nA4 = (Mv * Ev) / 4;
    const int nW4 = (Ev * Ev) / 4;
    const size_t WE = (size_t)Ev * Ev;

    conv_acts<<<dim3(nA4 / 256, 3), 256>>>((const float4*)query, (const float4*)key,
                                           (const float4*)value, (uint2*)xh, nA4);
    WSplitPtrs wp;
    wp.src[0] = (const float4*)Wq; wp.src[1] = (const float4*)Wk;
    wp.src[2] = (const float4*)Wv; wp.src[3] = (const float4*)Wo;
    wp.hi[0] = (uint2*)wh;            wp.lo[0] = (uint2*)wl;
    wp.hi[1] = (uint2*)(wh + WE);     wp.lo[1] = (uint2*)(wl + WE);
    wp.hi[2] = (uint2*)(wh + 2 * WE); wp.lo[2] = (uint2*)(wl + 2 * WE);
    wp.hi[3] = (uint2*)woh;           wp.lo[3] = (uint2*)wol;
    split_w<<<dim3(nW4 / 256, 4), 256>>>(wp, nW4);

    QKVParams p;
    p.bias0 = bq; p.bias1 = bk; p.bias2 = bv;
    p.Ch0 = qh; p.Ch1 = kh; p.Ch2 = vh;
    gemm_qkv<<<dim3(GN / 128, Mv / 128, 3), 256, GEMM_SMEM>>>(xh, wh, wl, p);

    flash_mma<<<dim3(Sv / 128, Hv, Bv), 128>>>(qh, kh, vh, mask, oh);

    gemm_out<<<dim3(GN / 128, Mv / 128), 256, GEMM_SMEM>>>(oh, woh, wol, bo, out);
}

// round 9
// speedup vs baseline: 5.3337x; 1.1366x over previous
#include <cuda_runtime.h>
#include <cuda_fp16.h>
#include <cstdint>

// Shapes are fixed by the problem.
#define Bv 2
#define Sv 2048
#define Ev 1024
#define Hv 16
#define Dv 64
#define Mv (Bv * Sv) /* 4096 */

// Scratch (allocation-free rule: __device__ globals).
__device__ __half g_xh[3][(size_t)Mv * Ev];  // q/k/v activations, fp16 hi
__device__ __half g_wh[3][(size_t)Ev * Ev];  // Wq/Wk/Wv hi (lo dropped)
__device__ __half g_woh[(size_t)Ev * Ev];    // Wo hi
__device__ __half g_wol[(size_t)Ev * Ev];    // Wo lo
__device__ __half g_qh[(size_t)Mv * Ev];     // Q hi
__device__ __half g_kh[(size_t)Mv * Ev];     // K hi
__device__ __half g_vh[(size_t)Mv * Ev];     // V hi
__device__ __half g_oh[(size_t)Mv * Ev];     // attention out hi
__device__ __half g_mb[(size_t)Bv * Sv * Sv];// mask bias: 0 or -30000 (fp16)

// ---------------------------------------------------------------------------
// Family-portable tensor-core helpers (HMMA / LDSM / LDGSTS — legal on sm_103)
// ---------------------------------------------------------------------------
__device__ __forceinline__ uint32_t smem_u32(const void* p) {
    uint32_t a;
    asm("{ .reg .u64 t; cvta.to.shared.u64 t, %1; cvt.u32.u64 %0, t; }"
        : "=r"(a) : "l"(p));
    return a;
}

__device__ __forceinline__ void ldsm_x4(uint32_t* r, uint32_t addr) {
    asm volatile("ldmatrix.sync.aligned.m8n8.x4.shared.b16 {%0,%1,%2,%3}, [%4];"
                 : "=r"(r[0]), "=r"(r[1]), "=r"(r[2]), "=r"(r[3]) : "r"(addr));
}

__device__ __forceinline__ void ldsm_x4_t(uint32_t* r, uint32_t addr) {
    asm volatile("ldmatrix.sync.aligned.m8n8.x4.trans.shared.b16 {%0,%1,%2,%3}, [%4];"
                 : "=r"(r[0]), "=r"(r[1]), "=r"(r[2]), "=r"(r[3]) : "r"(addr));
}

__device__ __forceinline__ void mma_f16(float* c, const uint32_t* a, const uint32_t* b) {
    asm volatile(
        "mma.sync.aligned.m16n8k16.row.col.f32.f16.f16.f32 "
        "{%0,%1,%2,%3}, {%4,%5,%6,%7}, {%8,%9}, {%0,%1,%2,%3};"
        : "+f"(c[0]), "+f"(c[1]), "+f"(c[2]), "+f"(c[3])
        : "r"(a[0]), "r"(a[1]), "r"(a[2]), "r"(a[3]), "r"(b[0]), "r"(b[1]));
}

__device__ __forceinline__ void cp16(uint32_t dst, const void* src) {
    asm volatile("cp.async.cg.shared.global [%0], [%1], 16;"
                 :: "r"(dst), "l"(src));
}
#define CP_COMMIT() asm volatile("cp.async.commit_group;" ::: "memory")
#define CP_WAIT1()  asm volatile("cp.async.wait_group 1;" ::: "memory")
#define CP_WAIT0()  asm volatile("cp.async.wait_group 0;" ::: "memory")

__device__ __forceinline__ uint32_t h2u(__half2 v) {
    return *reinterpret_cast<uint32_t*>(&v);
}

__device__ __forceinline__ float ex2f(float x) {
    float r;
    asm("ex2.approx.f32 %0, %1;" : "=f"(r) : "f"(x));
    return r;
}

// scale = 1/8 (1/sqrt(64)) folded with log2(e): softmax done in base-2 domain
#define KSC 0.1803368801111f

// ---------------------------------------------------------------------------
// Activation convert: fp32 -> fp16 hi only. blockIdx.y selects tensor (0..2).
// ---------------------------------------------------------------------------
__global__ void __launch_bounds__(256)
conv_acts(const float4* __restrict__ q, const float4* __restrict__ k,
          const float4* __restrict__ v, uint2* __restrict__ dst, int n4)
{
    const int z = blockIdx.y;
    const float4* src = (z == 0) ? q : (z == 1) ? k : v;
    const int i = blockIdx.x * 256 + threadIdx.x;
    if (i >= n4) return;
    const float4 w = src[i];
    uint2 o;
    o.x = (uint32_t)__half_as_ushort(__float2half_rn(w.x))
        | ((uint32_t)__half_as_ushort(__float2half_rn(w.y)) << 16);
    o.y = (uint32_t)__half_as_ushort(__float2half_rn(w.z))
        | ((uint32_t)__half_as_ushort(__float2half_rn(w.w)) << 16);
    dst[(size_t)z * n4 + i] = o;
}

// ---------------------------------------------------------------------------
// Mask convert: int32 0/1 -> fp16 additive bias (-30000 masked, 0 pass).
// ---------------------------------------------------------------------------
__global__ void __launch_bounds__(256)
conv_mask(const int4* __restrict__ m, uint2* __restrict__ out, int n4)
{
    const int i = blockIdx.x * 256 + threadIdx.x;
    if (i >= n4) return;
    const int4 v = m[i];
    const __half z = __ushort_as_half(0), ng = __float2half(-30000.f);
    uint2 o;
    o.x = h2u(__halves2half2(v.x ? z : ng, v.y ? z : ng));
    o.y = h2u(__halves2half2(v.z ? z : ng, v.w ? z : ng));
    out[i] = o;
}

// ---------------------------------------------------------------------------
// Weight split: hi for all 4 weights; lo only for Wo (z==3).
// ---------------------------------------------------------------------------
struct WSplitPtrs {
    const float4* src[4];
    uint2* hi[4];
    uint2* lo;   // Wo lo only
};

__global__ void __launch_bounds__(256)
split_w(WSplitPtrs p, int n4)
{
    const int z = blockIdx.y;
    const int i = blockIdx.x * 256 + threadIdx.x;
    if (i >= n4) return;
    const float4 v = p.src[z][i];
    float f[4] = {v.x, v.y, v.z, v.w};
    unsigned short h[4], l[4];
#pragma unroll
    for (int j = 0; j < 4; j++) {
        __half hb = __float2half_rn(f[j]);
        __half lb = __float2half_rn(f[j] - __half2float(hb));
        h[j] = __half_as_ushort(hb);
        l[j] = __half_as_ushort(lb);
    }
    uint2 ho;
    ho.x = (uint32_t)h[0] | ((uint32_t)h[1] << 16);
    ho.y = (uint32_t)h[2] | ((uint32_t)h[3] << 16);
    p.hi[z][i] = ho;
    if (z == 3) {
        uint2 lo;
        lo.x = (uint32_t)l[0] | ((uint32_t)l[1] << 16);
        lo.y = (uint32_t)l[2] | ((uint32_t)l[3] << 16);
        p.lo[i] = lo;
    }
}

// ---------------------------------------------------------------------------
// HMMA GEMM mainloop, cp.async 2-stage double buffer.
// TWO=true: C = Ah @ (Wh + Wl)^T (Wo projection); false: C = Ah @ Wh^T.
// 128x128 CTA tile, BK=32, 8 warps, warp tile 64x32.
// ---------------------------------------------------------------------------
#define GK 1024
#define GN 1024
#define SSTR 40
#define TILEB (128 * SSTR * 2)
#define QKV_SMEM (2 * 2 * TILEB)          /* 40960 */
#define OUT_SMEM (2 * 3 * TILEB)          /* 61440 */

struct QKVParams {
    const float* bias0; const float* bias1; const float* bias2;
    __half* Ch0; __half* Ch1; __half* Ch2;
};

template<bool TWO>
__device__ __forceinline__ void gemm_core(
    const __half* __restrict__ Ahg,
    const __half* __restrict__ Bhg, const __half* __restrict__ Blg,
    uint32_t smem_base, int bm, int bn, int tid, float acc[4][4][4])
{
    constexpr uint32_t STGB_T = (TWO ? 3u : 2u) * (uint32_t)TILEB;
    const int lane = tid & 31;
    const int wid  = tid >> 5;
    const int wm   = (wid & 1) * 64;
    const int wn   = (wid >> 1) * 32;

    const int r0 = tid >> 2;
    const int c8 = (tid & 3) * 8;
    const uint32_t dst_off  = (uint32_t)(r0 * SSTR + c8) * 2;
    const uint32_t dst_off2 = (uint32_t)((r0 + 64) * SSTR + c8) * 2;

    const __half* gA  = Ahg + (size_t)(bm + r0) * GK + c8;
    const __half* gA2 = Ahg + (size_t)(bm + r0 + 64) * GK + c8;
    const __half* gB  = Bhg + (size_t)(bn + r0) * GK + c8;
    const __half* gB2 = Bhg + (size_t)(bn + r0 + 64) * GK + c8;
    const __half* gBl  = Blg + (size_t)(bn + r0) * GK + c8;
    const __half* gBl2 = Blg + (size_t)(bn + r0 + 64) * GK + c8;

    const int a_row = wm + (lane & 15);
    const int a_col = (lane >> 4) * 8;
    const int g     = lane >> 3;
    const int b_row = wn + (lane & 7) + (g >> 1) * 8;
    const int b_col = (g & 1) * 8;

    auto issue = [&](int kt, int stg) {
        const int ko = kt * 32;
        const uint32_t sb = smem_base + stg * STGB_T;
        cp16(sb + dst_off,          gA  + ko);
        cp16(sb + dst_off2,         gA2 + ko);
        cp16(sb + TILEB + dst_off,  gB  + ko);
        cp16(sb + TILEB + dst_off2, gB2 + ko);
        if (TWO) {
            cp16(sb + 2 * TILEB + dst_off,  gBl  + ko);
            cp16(sb + 2 * TILEB + dst_off2, gBl2 + ko);
        }
    };

    issue(0, 0);
    CP_COMMIT();

#pragma unroll 1
    for (int it = 0; it < GK / 32; it++) {
        const int stg = it & 1;
        if (it < GK / 32 - 1) {
            issue(it + 1, (it + 1) & 1);
            CP_COMMIT();
            CP_WAIT1();
        } else {
            CP_WAIT0();
        }
        __syncthreads();

        const uint32_t ah_b = smem_base + stg * STGB_T;
        const uint32_t bh_b = ah_b + TILEB;
        const uint32_t bl_b = ah_b + 2 * TILEB;

#pragma unroll
        for (int ks = 0; ks < 2; ks++) {
            uint32_t afh[4][4];
#pragma unroll
            for (int i = 0; i < 4; i++) {
                const uint32_t off = ((a_row + i * 16) * SSTR + ks * 16 + a_col) * 2;
                ldsm_x4(afh[i], ah_b + off);
            }
            uint32_t bfh[4][2], bfl[4][2];
#pragma unroll
            for (int j = 0; j < 2; j++) {
                const uint32_t off = ((b_row + j * 16) * SSTR + ks * 16 + b_col) * 2;
                uint32_t r[4];
                ldsm_x4(r, bh_b + off);
                bfh[2 * j][0] = r[0]; bfh[2 * j][1] = r[1];
                bfh[2 * j + 1][0] = r[2]; bfh[2 * j + 1][1] = r[3];
                if (TWO) {
                    ldsm_x4(r, bl_b + off);
                    bfl[2 * j][0] = r[0]; bfl[2 * j][1] = r[1];
                    bfl[2 * j + 1][0] = r[2]; bfl[2 * j + 1][1] = r[3];
                }
            }
#pragma unroll
            for (int i = 0; i < 4; i++)
#pragma unroll
                for (int j = 0; j < 4; j++) {
                    mma_f16(acc[i][j], afh[i], bfh[j]);
                    if (TWO) mma_f16(acc[i][j], afh[i], bfl[j]);
                }
        }
        __syncthreads();
    }
}

// Merged Q/K/V projection (1-pass): gridDim.z selects projection. fp16 hi out.
__global__ void __launch_bounds__(256, 2)
gemm_qkv(const __half* __restrict__ Xh, const __half* __restrict__ Wh,
         QKVParams p)
{
    extern __shared__ char dynsm[];
    const uint32_t smem_base = smem_u32(dynsm);
    const int z = blockIdx.z;
    const int tid = threadIdx.x, lane = tid & 31, wid = tid >> 5;
    const int bm = blockIdx.y << 7, bn = blockIdx.x << 7;

    const __half* Ahg = Xh + (size_t)z * Mv * Ev;
    const __half* Bhg = Wh + (size_t)z * Ev * Ev;
    const float* bias = (z == 0) ? p.bias0 : (z == 1) ? p.bias1 : p.bias2;
    __half* Ch = (z == 0) ? p.Ch0 : (z == 1) ? p.Ch1 : p.Ch2;

    float acc[4][4][4];
#pragma unroll
    for (int i = 0; i < 4; i++)
#pragma unroll
        for (int j = 0; j < 4; j++)
#pragma unroll
            for (int q = 0; q < 4; q++) acc[i][j][q] = 0.f;

    gemm_core<false>(Ahg, Bhg, Bhg, smem_base, bm, bn, tid, acc);

    const int wm = (wid & 1) * 64, wn = (wid >> 1) * 32;
#pragma unroll
    for (int i = 0; i < 4; i++) {
        const int grow = bm + wm + i * 16 + (lane >> 2);
#pragma unroll
        for (int j = 0; j < 4; j++) {
            const int gcol = bn + wn + j * 8 + (lane & 3) * 2;
            const float b0 = bias[gcol], b1 = bias[gcol + 1];
            *(__half2*)(Ch + (size_t)grow * GN + gcol) =
                __halves2half2(__float2half_rn(acc[i][j][0] + b0),
                               __float2half_rn(acc[i][j][1] + b1));
            *(__half2*)(Ch + (size_t)(grow + 8) * GN + gcol) =
                __halves2half2(__float2half_rn(acc[i][j][2] + b0),
                               __float2half_rn(acc[i][j][3] + b1));
        }
    }
}

// Output projection (2-pass split): fp32 result + bias.
__global__ void __launch_bounds__(256, 2)
gemm_out(const __half* __restrict__ Ahg,
         const __half* __restrict__ Bhg, const __half* __restrict__ Blg,
         const float* __restrict__ bias, float* __restrict__ Cf)
{
    extern __shared__ char dynsm[];
    const uint32_t smem_base = smem_u32(dynsm);
    const int tid = threadIdx.x, lane = tid & 31, wid = tid >> 5;
    const int bm = blockIdx.y << 7, bn = blockIdx.x << 7;

    float acc[4][4][4];
#pragma unroll
    for (int i = 0; i < 4; i++)
#pragma unroll
        for (int j = 0; j < 4; j++)
#pragma unroll
            for (int q = 0; q < 4; q++) acc[i][j][q] = 0.f;

    gemm_core<true>(Ahg, Bhg, Blg, smem_base, bm, bn, tid, acc);

    const int wm = (wid & 1) * 64, wn = (wid >> 1) * 32;
#pragma unroll
    for (int i = 0; i < 4; i++) {
        const int grow = bm + wm + i * 16 + (lane >> 2);
#pragma unroll
        for (int j = 0; j < 4; j++) {
            const int gcol = bn + wn + j * 8 + (lane & 3) * 2;
            const float b0 = bias[gcol], b1 = bias[gcol + 1];
            float2 v0, v1;
            v0.x = acc[i][j][0] + b0; v0.y = acc[i][j][1] + b1;
            v1.x = acc[i][j][2] + b0; v1.y = acc[i][j][3] + b1;
            *(float2*)(Cf + (size_t)grow * GN + gcol) = v0;
            *(float2*)(Cf + (size_t)(grow + 8) * GN + gcol) = v1;
        }
    }
}

// ---------------------------------------------------------------------------
// Flash attention on HMMA, base-2 online softmax, fp16 additive mask bias,
// cp.async double-buffered K/V. q-tile 128 per CTA (32 rows/warp).
// S2 = Qh Kh^T * KSC + bias; O = Ph Vh.
// Grid: (S/128, H, B) = (16, 16, 2). Block 128 = 4 warps.
// ---------------------------------------------------------------------------
#define KSTR 72

__global__ void __launch_bounds__(128)
flash_mma(const __half* __restrict__ Qh,
          const __half* __restrict__ Kh, const __half* __restrict__ Vh,
          const __half* __restrict__ mb, __half* __restrict__ Oh)
{
    __shared__ __half sK[2][64 * KSTR], sV[2][64 * KSTR];

    const int tid = threadIdx.x, lane = tid & 31, warp = tid >> 5;
    const int b = blockIdx.z, h = blockIdx.y;
    const int qb = blockIdx.x << 7, hb = h << 6;

    const uint32_t k_b[2] = {smem_u32(sK[0]), smem_u32(sK[1])};
    const uint32_t v_b[2] = {smem_u32(sV[0]), smem_u32(sV[1])};

    const int sr = tid >> 3;
    const int sj = (tid & 7) * 8;

    // ---- stage Q (rows 0-63 in sK[0], 64-127 in sK[1]), pull A-frags ----
#pragma unroll
    for (int i = 0; i < 4; i++) {
        const int r = sr + i * 16;
        const size_t gq  = (size_t)(b * Sv + qb + r) * Ev + hb + sj;
        const size_t gq2 = (size_t)(b * Sv + qb + 64 + r) * Ev + hb + sj;
        *(uint4*)(sK[0] + r * KSTR + sj) = *(const uint4*)(Qh + gq);
        *(uint4*)(sK[1] + r * KSTR + sj) = *(const uint4*)(Qh + gq2);
    }
    __syncthreads();
    uint32_t qf0[4][4], qf1[4][4];
    {
        const uint32_t qbase = k_b[warp >> 1];
        const int lr = (warp & 1) * 32 + (lane & 15);
        const int ac = (lane >> 4) * 8;
#pragma unroll
        for (int kf = 0; kf < 4; kf++) {
            ldsm_x4(qf0[kf], qbase + (uint32_t)(lr * KSTR + kf * 16 + ac) * 2);
            ldsm_x4(qf1[kf], qbase + (uint32_t)((lr + 16) * KSTR + kf * 16 + ac) * 2);
        }
    }
    __syncthreads();

    float m[4], l[4];
#pragma unroll
    for (int i = 0; i < 4; i++) { m[i] = -1e30f; l[i] = 0.f; }
    float o0[8][4], o1[8][4];
#pragma unroll
    for (int n = 0; n < 8; n++)
#pragma unroll
        for (int q = 0; q < 4; q++) { o0[n][q] = 0.f; o1[n][q] = 0.f; }

    const int r_base = b * Sv + qb + warp * 32 + (lane >> 2);
    const __half* mb0 = mb + (size_t)r_base * Sv;
    const __half* mb1 = mb + (size_t)(r_base + 8) * Sv;
    const __half* mb2 = mb + (size_t)(r_base + 16) * Sv;
    const __half* mb3 = mb + (size_t)(r_base + 24) * Sv;
    const int mc = (lane & 3) * 2;

    const int b_r = (lane & 7) + (lane >> 4) * 8;
    const int b_c = ((lane >> 3) & 1) * 8;
    const int v_r = (lane & 7) + ((lane >> 3) & 1) * 8;
    const int v_c = (lane >> 4) * 8;

    const uint32_t stg_off = (uint32_t)(sr * KSTR + sj) * 2;

    auto issueKV = [&](int kvt, int stg) {
        const int kv = kvt * 64;
#pragma unroll
        for (int i = 0; i < 4; i++) {
            const int r = sr + i * 16;
            const size_t gk = (size_t)(b * Sv + kv + r) * Ev + hb + sj;
            const uint32_t doff = stg_off + (uint32_t)(i * 16 * KSTR) * 2;
            cp16(k_b[stg] + doff, Kh + gk);
            cp16(v_b[stg] + doff, Vh + gk);
        }
    };

    issueKV(0, 0);
    CP_COMMIT();

#pragma unroll 1
    for (int it = 0; it < Sv / 64; it++) {
        const int stg = it & 1;
        const int kv = it * 64;
        if (it < Sv / 64 - 1) {
            issueKV(it + 1, stg ^ 1);
            CP_COMMIT();
            CP_WAIT1();
        } else {
            CP_WAIT0();
        }
        __syncthreads();

        // ---- S = Q K^T for both m-halves, K frags loaded once ----
        float s0[8][4], s1[8][4];
#pragma unroll
        for (int n = 0; n < 8; n++)
#pragma unroll
            for (int q = 0; q < 4; q++) { s0[n][q] = 0.f; s1[n][q] = 0.f; }

#pragma unroll
        for (int kf = 0; kf < 4; kf++) {
            uint32_t bh[8][2];
#pragma unroll
            for (int u = 0; u < 4; u++) {
                const uint32_t off =
                    (uint32_t)((b_r + u * 16) * KSTR + b_c + kf * 16) * 2;
                uint32_t t[4];
                ldsm_x4(t, k_b[stg] + off);
                bh[2 * u][0] = t[0]; bh[2 * u][1] = t[1];
                bh[2 * u + 1][0] = t[2]; bh[2 * u + 1][1] = t[3];
            }
#pragma unroll
            for (int n = 0; n < 8; n++) {
                mma_f16(s0[n], qf0[kf], bh[n]);
                mma_f16(s1[n], qf1[kf], bh[n]);
            }
        }

        // ---- scale into base-2 domain + additive mask bias + row maxes ----
        float mx[4] = {-1e30f, -1e30f, -1e30f, -1e30f};
#pragma unroll
        for (int n = 0; n < 8; n++) {
            const int c = kv + n * 8 + mc;
            const __half2 q0 = *(const __half2*)(mb0 + c);
            const __half2 q1 = *(const __half2*)(mb1 + c);
            const __half2 q2 = *(const __half2*)(mb2 + c);
            const __half2 q3 = *(const __half2*)(mb3 + c);
            s0[n][0] = fmaf(s0[n][0], KSC, __low2float(q0));
            s0[n][1] = fmaf(s0[n][1], KSC, __high2float(q0));
            s0[n][2] = fmaf(s0[n][2], KSC, __low2float(q1));
            s0[n][3] = fmaf(s0[n][3], KSC, __high2float(q1));
            s1[n][0] = fmaf(s1[n][0], KSC, __low2float(q2));
            s1[n][1] = fmaf(s1[n][1], KSC, __high2float(q2));
            s1[n][2] = fmaf(s1[n][2], KSC, __low2float(q3));
            s1[n][3] = fmaf(s1[n][3], KSC, __high2float(q3));
            mx[0] = fmaxf(mx[0], fmaxf(s0[n][0], s0[n][1]));
            mx[1] = fmaxf(mx[1], fmaxf(s0[n][2], s0[n][3]));
            mx[2] = fmaxf(mx[2], fmaxf(s1[n][0], s1[n][1]));
            mx[3] = fmaxf(mx[3], fmaxf(s1[n][2], s1[n][3]));
        }
        float corr[4];
#pragma unroll
        for (int i = 0; i < 4; i++) {
            mx[i] = fmaxf(mx[i], __shfl_xor_sync(0xffffffffu, mx[i], 1));
            mx[i] = fmaxf(mx[i], __shfl_xor_sync(0xffffffffu, mx[i], 2));
            const float mn = fmaxf(m[i], mx[i]);
            corr[i] = ex2f(m[i] - mn);
            m[i] = mn;
        }

        float rs[4] = {0.f, 0.f, 0.f, 0.f};
#pragma unroll
        for (int n = 0; n < 8; n++) {
            s0[n][0] = ex2f(s0[n][0] - m[0]); s0[n][1] = ex2f(s0[n][1] - m[0]);
            s0[n][2] = ex2f(s0[n][2] - m[1]); s0[n][3] = ex2f(s0[n][3] - m[1]);
            s1[n][0] = ex2f(s1[n][0] - m[2]); s1[n][1] = ex2f(s1[n][1] - m[2]);
            s1[n][2] = ex2f(s1[n][2] - m[3]); s1[n][3] = ex2f(s1[n][3] - m[3]);
            rs[0] += s0[n][0] + s0[n][1];
            rs[1] += s0[n][2] + s0[n][3];
            rs[2] += s1[n][0] + s1[n][1];
            rs[3] += s1[n][2] + s1[n][3];
            o0[n][0] *= corr[0]; o0[n][1] *= corr[0];
            o0[n][2] *= corr[1]; o0[n][3] *= corr[1];
            o1[n][0] *= corr[2]; o1[n][1] *= corr[2];
            o1[n][2] *= corr[3]; o1[n][3] *= corr[3];
        }
#pragma unroll
        for (int i = 0; i < 4; i++) {
            rs[i] += __shfl_xor_sync(0xffffffffu, rs[i], 1);
            rs[i] += __shfl_xor_sync(0xffffffffu, rs[i], 2);
            l[i] = l[i] * corr[i] + rs[i];
        }

        // ---- pack P fragments (both halves) ----
        uint32_t pf0[4][4], pf1[4][4];
#pragma unroll
        for (int kf = 0; kf < 4; kf++) {
            const int n0 = 2 * kf, n1 = 2 * kf + 1;
            pf0[kf][0] = h2u(__halves2half2(__float2half_rn(s0[n0][0]), __float2half_rn(s0[n0][1])));
            pf0[kf][1] = h2u(__halves2half2(__float2half_rn(s0[n0][2]), __float2half_rn(s0[n0][3])));
            pf0[kf][2] = h2u(__halves2half2(__float2half_rn(s0[n1][0]), __float2half_rn(s0[n1][1])));
            pf0[kf][3] = h2u(__halves2half2(__float2half_rn(s0[n1][2]), __float2half_rn(s0[n1][3])));
            pf1[kf][0] = h2u(__halves2half2(__float2half_rn(s1[n0][0]), __float2half_rn(s1[n0][1])));
            pf1[kf][1] = h2u(__halves2half2(__float2half_rn(s1[n0][2]), __float2half_rn(s1[n0][3])));
            pf1[kf][2] = h2u(__halves2half2(__float2half_rn(s1[n1][0]), __float2half_rn(s1[n1][1])));
            pf1[kf][3] = h2u(__halves2half2(__float2half_rn(s1[n1][2]), __float2half_rn(s1[n1][3])));
        }

        // ---- O += P V, V frags loaded once, used by both halves ----
#pragma unroll
        for (int kf = 0; kf < 4; kf++) {
            uint32_t wh[8][2];
#pragma unroll
            for (int u = 0; u < 4; u++) {
                const uint32_t off =
                    (uint32_t)((v_r + kf * 16) * KSTR + v_c + u * 16) * 2;
                uint32_t t[4];
                ldsm_x4_t(t, v_b[stg] + off);
                wh[2 * u][0] = t[0]; wh[2 * u][1] = t[1];
                wh[2 * u + 1][0] = t[2]; wh[2 * u + 1][1] = t[3];
            }
#pragma unroll
            for (int n = 0; n < 8; n++) {
                mma_f16(o0[n], pf0[kf], wh[n]);
                mma_f16(o1[n], pf1[kf], wh[n]);
            }
        }
        __syncthreads();
    }

    // ---- normalize and write (4 row groups x 8 n-blocks) ----
    const float i0 = 1.f / l[0], i1 = 1.f / l[1];
    const float i2 = 1.f / l[2], i3 = 1.f / l[3];
#pragma unroll
    for (int n = 0; n < 8; n++) {
        const int col = hb + n * 8 + mc;
        *(__half2*)(Oh + (size_t)r_base * Ev + col) =
            __halves2half2(__float2half_rn(o0[n][0] * i0), __float2half_rn(o0[n][1] * i0));
        *(__half2*)(Oh + (size_t)(r_base + 8) * Ev + col) =
            __halves2half2(__float2half_rn(o0[n][2] * i1), __float2half_rn(o0[n][3] * i1));
        *(__half2*)(Oh + (size_t)(r_base + 16) * Ev + col) =
            __halves2half2(__float2half_rn(o1[n][0] * i2), __float2half_rn(o1[n][1] * i2));
        *(__half2*)(Oh + (size_t)(r_base + 24) * Ev + col) =
            __halves2half2(__float2half_rn(o1[n][2] * i3), __float2half_rn(o1[n][3] * i3));
    }
}

// ---------------------------------------------------------------------------
extern "C" void kernel_launch(void* const* d_in, const int* in_sizes, int n_in,
                              void* d_out, int out_size)
{
    (void)in_sizes; (void)n_in; (void)out_size;
    const float* query = (const float*)d_in[0];
    const float* key   = (const float*)d_in[1];
    const float* value = (const float*)d_in[2];
    const int*   mask  = (const int*)  d_in[3];
    const float* Wq = (const float*)d_in[4];
    const float* bq = (const float*)d_in[5];
    const float* Wk = (const float*)d_in[6];
    const float* bk = (const float*)d_in[7];
    const float* Wv = (const float*)d_in[8];
    const float* bv = (const float*)d_in[9];
    const float* Wo = (const float*)d_in[10];
    const float* bo = (const float*)d_in[11];
    float* out = (float*)d_out;

    __half *xh, *wh, *woh, *wol, *qh, *kh, *vh, *oh, *mb;
    cudaGetSymbolAddress((void**)&xh, g_xh);
    cudaGetSymbolAddress((void**)&wh, g_wh);
    cudaGetSymbolAddress((void**)&woh, g_woh);
    cudaGetSymbolAddress((void**)&wol, g_wol);
    cudaGetSymbolAddress((void**)&qh, g_qh);
    cudaGetSymbolAddress((void**)&kh, g_kh);
    cudaGetSymbolAddress((void**)&vh, g_vh);
    cudaGetSymbolAddress((void**)&oh, g_oh);
    cudaGetSymbolAddress((void**)&mb, g_mb);

    cudaFuncSetAttribute(gemm_qkv,
                         cudaFuncAttributeMaxDynamicSharedMemorySize, QKV_SMEM);
    cudaFuncSetAttribute(gemm_out,
                         cudaFuncAttributeMaxDynamicSharedMemorySize, OUT_SMEM);

    const int nA4 = (Mv * Ev) / 4;
    const int nW4 = (Ev * Ev) / 4;
    const int nM4 = (Bv * Sv * Sv) / 4;
    const size_t WE = (size_t)Ev * Ev;

    conv_acts<<<dim3(nA4 / 256, 3), 256>>>((const float4*)query, (const float4*)key,
                                           (const float4*)value, (uint2*)xh, nA4);
    conv_mask<<<nM4 / 256, 256>>>((const int4*)mask, (uint2*)mb, nM4);

    WSplitPtrs wp;
    wp.src[0] = (const float4*)Wq; wp.src[1] = (const float4*)Wk;
    wp.src[2] = (const float4*)Wv; wp.src[3] = (const float4*)Wo;
    wp.hi[0] = (uint2*)wh;
    wp.hi[1] = (uint2*)(wh + WE);
    wp.hi[2] = (uint2*)(wh + 2 * WE);
    wp.hi[3] = (uint2*)woh;
    wp.lo = (uint2*)wol;
    split_w<<<dim3(nW4 / 256, 4), 256>>>(wp, nW4);

    QKVParams p;
    p.bias0 = bq; p.bias1 = bk; p.bias2 = bv;
    p.Ch0 = qh; p.Ch1 = kh; p.Ch2 = vh;
    gemm_qkv<<<dim3(GN / 128, Mv / 128, 3), 256, QKV_SMEM>>>(xh, wh, p);

    flash_mma<<<dim3(Sv / 128, Hv, Bv), 128>>>(qh, kh, vh, mb, oh);

    gemm_out<<<dim3(GN / 128, Mv / 128), 256, OUT_SMEM>>>(oh, woh, wol, bo, out);
}

// round 10
// speedup vs baseline: 5.3791x; 1.0085x over previous
#include <cuda_runtime.h>
#include <cuda_fp16.h>
#include <cstdint>

// Shapes are fixed by the problem.
#define Bv 2
#define Sv 2048
#define Ev 1024
#define Hv 16
#define Dv 64
#define Mv (Bv * Sv) /* 4096 */

// Scratch (allocation-free rule: __device__ globals).
__device__ __half g_xh[3][(size_t)Mv * Ev];  // q/k/v activations, fp16 hi
__device__ __half g_wh[3][(size_t)Ev * Ev];  // Wq/Wk/Wv hi
__device__ __half g_woh[(size_t)Ev * Ev];    // Wo hi
__device__ __half g_wol[(size_t)Ev * Ev];    // Wo lo
__device__ __half g_qh[(size_t)Mv * Ev];     // Q hi
__device__ __half g_kh[(size_t)Mv * Ev];     // K hi
__device__ __half g_vh[(size_t)Mv * Ev];     // V hi
__device__ __half g_oh[(size_t)Mv * Ev];     // attention out hi
__device__ __half g_mb[(size_t)Bv * Sv * Sv];// mask bias: 0 or -30000 (fp16)

// ---------------------------------------------------------------------------
// Family-portable tensor-core helpers (HMMA / LDSM / LDGSTS — legal on sm_103)
// ---------------------------------------------------------------------------
__device__ __forceinline__ uint32_t smem_u32(const void* p) {
    uint32_t a;
    asm("{ .reg .u64 t; cvta.to.shared.u64 t, %1; cvt.u32.u64 %0, t; }"
        : "=r"(a) : "l"(p));
    return a;
}

__device__ __forceinline__ void ldsm_x4(uint32_t* r, uint32_t addr) {
    asm volatile("ldmatrix.sync.aligned.m8n8.x4.shared.b16 {%0,%1,%2,%3}, [%4];"
                 : "=r"(r[0]), "=r"(r[1]), "=r"(r[2]), "=r"(r[3]) : "r"(addr));
}

__device__ __forceinline__ void ldsm_x4_t(uint32_t* r, uint32_t addr) {
    asm volatile("ldmatrix.sync.aligned.m8n8.x4.trans.shared.b16 {%0,%1,%2,%3}, [%4];"
                 : "=r"(r[0]), "=r"(r[1]), "=r"(r[2]), "=r"(r[3]) : "r"(addr));
}

__device__ __forceinline__ void mma_f16(float* c, const uint32_t* a, const uint32_t* b) {
    asm volatile(
        "mma.sync.aligned.m16n8k16.row.col.f32.f16.f16.f32 "
        "{%0,%1,%2,%3}, {%4,%5,%6,%7}, {%8,%9}, {%0,%1,%2,%3};"
        : "+f"(c[0]), "+f"(c[1]), "+f"(c[2]), "+f"(c[3])
        : "r"(a[0]), "r"(a[1]), "r"(a[2]), "r"(a[3]), "r"(b[0]), "r"(b[1]));
}

__device__ __forceinline__ void cp16(uint32_t dst, const void* src) {
    asm volatile("cp.async.cg.shared.global [%0], [%1], 16;"
                 :: "r"(dst), "l"(src));
}
#define CP_COMMIT() asm volatile("cp.async.commit_group;" ::: "memory")
#define CP_WAIT1()  asm volatile("cp.async.wait_group 1;" ::: "memory")
#define CP_WAIT0()  asm volatile("cp.async.wait_group 0;" ::: "memory")

__device__ __forceinline__ uint32_t h2u(__half2 v) {
    return *reinterpret_cast<uint32_t*>(&v);
}

__device__ __forceinline__ float ex2f(float x) {
    float r;
    asm("ex2.approx.f32 %0, %1;" : "=f"(r) : "f"(x));
    return r;
}

// scale = 1/8 (1/sqrt(64)) folded with log2(e): softmax done in base-2 domain
#define KSC 0.1803368801111f

// ---------------------------------------------------------------------------
// Activation convert: fp32 -> fp16 hi only. blockIdx.y selects tensor (0..2).
// ---------------------------------------------------------------------------
__global__ void __launch_bounds__(256)
conv_acts(const float4* __restrict__ q, const float4* __restrict__ k,
          const float4* __restrict__ v, uint2* __restrict__ dst, int n4)
{
    const int z = blockIdx.y;
    const float4* src = (z == 0) ? q : (z == 1) ? k : v;
    const int i = blockIdx.x * 256 + threadIdx.x;
    if (i >= n4) return;
    const float4 w = src[i];
    uint2 o;
    o.x = (uint32_t)__half_as_ushort(__float2half_rn(w.x))
        | ((uint32_t)__half_as_ushort(__float2half_rn(w.y)) << 16);
    o.y = (uint32_t)__half_as_ushort(__float2half_rn(w.z))
        | ((uint32_t)__half_as_ushort(__float2half_rn(w.w)) << 16);
    dst[(size_t)z * n4 + i] = o;
}

// ---------------------------------------------------------------------------
// Mask convert: int32 0/1 -> fp16 additive bias (-30000 masked, 0 pass).
// ---------------------------------------------------------------------------
__global__ void __launch_bounds__(256)
conv_mask(const int4* __restrict__ m, uint2* __restrict__ out, int n4)
{
    const int i = blockIdx.x * 256 + threadIdx.x;
    if (i >= n4) return;
    const int4 v = m[i];
    const __half z = __ushort_as_half(0), ng = __float2half(-30000.f);
    uint2 o;
    o.x = h2u(__halves2half2(v.x ? z : ng, v.y ? z : ng));
    o.y = h2u(__halves2half2(v.z ? z : ng, v.w ? z : ng));
    out[i] = o;
}

// ---------------------------------------------------------------------------
// Weight split: hi for all 4 weights; lo only for Wo (z==3).
// ---------------------------------------------------------------------------
struct WSplitPtrs {
    const float4* src[4];
    uint2* hi[4];
    uint2* lo;   // Wo lo only
};

__global__ void __launch_bounds__(256)
split_w(WSplitPtrs p, int n4)
{
    const int z = blockIdx.y;
    const int i = blockIdx.x * 256 + threadIdx.x;
    if (i >= n4) return;
    const float4 v = p.src[z][i];
    float f[4] = {v.x, v.y, v.z, v.w};
    unsigned short h[4], l[4];
#pragma unroll
    for (int j = 0; j < 4; j++) {
        __half hb = __float2half_rn(f[j]);
        __half lb = __float2half_rn(f[j] - __half2float(hb));
        h[j] = __half_as_ushort(hb);
        l[j] = __half_as_ushort(lb);
    }
    uint2 ho;
    ho.x = (uint32_t)h[0] | ((uint32_t)h[1] << 16);
    ho.y = (uint32_t)h[2] | ((uint32_t)h[3] << 16);
    p.hi[z][i] = ho;
    if (z == 3) {
        uint2 lo;
        lo.x = (uint32_t)l[0] | ((uint32_t)l[1] << 16);
        lo.y = (uint32_t)l[2] | ((uint32_t)l[3] << 16);
        p.lo[i] = lo;
    }
}

// ---------------------------------------------------------------------------
// HMMA GEMM mainloop, cp.async 3-stage pipeline, ONE barrier per iteration.
// TWO=true: C = Ah @ (Wh + Wl)^T (Wo projection); false: C = Ah @ Wh^T.
// 128x128 CTA tile, BK=32, 8 warps, warp tile 64x32.
// ---------------------------------------------------------------------------
#define GK 1024
#define GN 1024
#define SSTR 40
#define TILEB (128 * SSTR * 2)
#define QKV_SMEM (3 * 2 * TILEB)          /* 61440 */
#define OUT_SMEM (3 * 3 * TILEB)          /* 92160 */
#define GNIT (GK / 32)                    /* 32 */

struct QKVParams {
    const float* bias0; const float* bias1; const float* bias2;
    __half* Ch0; __half* Ch1; __half* Ch2;
};

template<bool TWO>
__device__ __forceinline__ void gemm_core(
    const __half* __restrict__ Ahg,
    const __half* __restrict__ Bhg, const __half* __restrict__ Blg,
    uint32_t smem_base, int bm, int bn, int tid, float acc[4][4][4])
{
    constexpr uint32_t STGB_T = (TWO ? 3u : 2u) * (uint32_t)TILEB;
    const int lane = tid & 31;
    const int wid  = tid >> 5;
    const int wm   = (wid & 1) * 64;
    const int wn   = (wid >> 1) * 32;

    const int r0 = tid >> 2;
    const int c8 = (tid & 3) * 8;
    const uint32_t dst_off  = (uint32_t)(r0 * SSTR + c8) * 2;
    const uint32_t dst_off2 = (uint32_t)((r0 + 64) * SSTR + c8) * 2;

    const __half* gA  = Ahg + (size_t)(bm + r0) * GK + c8;
    const __half* gA2 = Ahg + (size_t)(bm + r0 + 64) * GK + c8;
    const __half* gB  = Bhg + (size_t)(bn + r0) * GK + c8;
    const __half* gB2 = Bhg + (size_t)(bn + r0 + 64) * GK + c8;
    const __half* gBl  = Blg + (size_t)(bn + r0) * GK + c8;
    const __half* gBl2 = Blg + (size_t)(bn + r0 + 64) * GK + c8;

    const int a_row = wm + (lane & 15);
    const int a_col = (lane >> 4) * 8;
    const int g     = lane >> 3;
    const int b_row = wn + (lane & 7) + (g >> 1) * 8;
    const int b_col = (g & 1) * 8;

    auto issue = [&](int kt, int stg) {
        const int ko = kt * 32;
        const uint32_t sb = smem_base + stg * STGB_T;
        cp16(sb + dst_off,          gA  + ko);
        cp16(sb + dst_off2,         gA2 + ko);
        cp16(sb + TILEB + dst_off,  gB  + ko);
        cp16(sb + TILEB + dst_off2, gB2 + ko);
        if (TWO) {
            cp16(sb + 2 * TILEB + dst_off,  gBl  + ko);
            cp16(sb + 2 * TILEB + dst_off2, gBl2 + ko);
        }
    };

    issue(0, 0); CP_COMMIT();
    issue(1, 1); CP_COMMIT();

    int stg = 0;
#pragma unroll 1
    for (int it = 0; it < GNIT; it++) {
        if (it < GNIT - 1) CP_WAIT1(); else CP_WAIT0();
        __syncthreads();   // all warps done with compute(it-1); stage it ready
        if (it + 2 < GNIT) {
            // writes stage (it+2)%3 — disjoint from the stage read this iter
            issue(it + 2, (stg + 2 >= 3) ? stg - 1 : stg + 2);
            CP_COMMIT();
        }

        const uint32_t ah_b = smem_base + stg * STGB_T;
        const uint32_t bh_b = ah_b + TILEB;
        const uint32_t bl_b = ah_b + 2 * TILEB;

#pragma unroll
        for (int ks = 0; ks < 2; ks++) {
            uint32_t afh[4][4];
#pragma unroll
            for (int i = 0; i < 4; i++) {
                const uint32_t off = ((a_row + i * 16) * SSTR + ks * 16 + a_col) * 2;
                ldsm_x4(afh[i], ah_b + off);
            }
            uint32_t bfh[4][2], bfl[4][2];
#pragma unroll
            for (int j = 0; j < 2; j++) {
                const uint32_t off = ((b_row + j * 16) * SSTR + ks * 16 + b_col) * 2;
                uint32_t r[4];
                ldsm_x4(r, bh_b + off);
                bfh[2 * j][0] = r[0]; bfh[2 * j][1] = r[1];
                bfh[2 * j + 1][0] = r[2]; bfh[2 * j + 1][1] = r[3];
                if (TWO) {
                    ldsm_x4(r, bl_b + off);
                    bfl[2 * j][0] = r[0]; bfl[2 * j][1] = r[1];
                    bfl[2 * j + 1][0] = r[2]; bfl[2 * j + 1][1] = r[3];
                }
            }
#pragma unroll
            for (int i = 0; i < 4; i++)
#pragma unroll
                for (int j = 0; j < 4; j++) {
                    mma_f16(acc[i][j], afh[i], bfh[j]);
                    if (TWO) mma_f16(acc[i][j], afh[i], bfl[j]);
                }
        }
        stg = (stg + 1 == 3) ? 0 : stg + 1;
    }
}

// Merged Q/K/V projection (1-pass): gridDim.z selects projection. fp16 hi out.
__global__ void __launch_bounds__(256, 2)
gemm_qkv(const __half* __restrict__ Xh, const __half* __restrict__ Wh,
         QKVParams p)
{
    extern __shared__ char dynsm[];
    const uint32_t smem_base = smem_u32(dynsm);
    const int z = blockIdx.z;
    const int tid = threadIdx.x, lane = tid & 31, wid = tid >> 5;
    const int bm = blockIdx.y << 7, bn = blockIdx.x << 7;

    const __half* Ahg = Xh + (size_t)z * Mv * Ev;
    const __half* Bhg = Wh + (size_t)z * Ev * Ev;
    const float* bias = (z == 0) ? p.bias0 : (z == 1) ? p.bias1 : p.bias2;
    __half* Ch = (z == 0) ? p.Ch0 : (z == 1) ? p.Ch1 : p.Ch2;

    float acc[4][4][4];
#pragma unroll
    for (int i = 0; i < 4; i++)
#pragma unroll
        for (int j = 0; j < 4; j++)
#pragma unroll
            for (int q = 0; q < 4; q++) acc[i][j][q] = 0.f;

    gemm_core<false>(Ahg, Bhg, Bhg, smem_base, bm, bn, tid, acc);

    const int wm = (wid & 1) * 64, wn = (wid >> 1) * 32;
#pragma unroll
    for (int i = 0; i < 4; i++) {
        const int grow = bm + wm + i * 16 + (lane >> 2);
#pragma unroll
        for (int j = 0; j < 4; j++) {
            const int gcol = bn + wn + j * 8 + (lane & 3) * 2;
            const float b0 = bias[gcol], b1 = bias[gcol + 1];
            *(__half2*)(Ch + (size_t)grow * GN + gcol) =
                __halves2half2(__float2half_rn(acc[i][j][0] + b0),
                               __float2half_rn(acc[i][j][1] + b1));
            *(__half2*)(Ch + (size_t)(grow + 8) * GN + gcol) =
                __halves2half2(__float2half_rn(acc[i][j][2] + b0),
                               __float2half_rn(acc[i][j][3] + b1));
        }
    }
}

// Output projection (2-pass split): fp32 result + bias.
__global__ void __launch_bounds__(256, 2)
gemm_out(const __half* __restrict__ Ahg,
         const __half* __restrict__ Bhg, const __half* __restrict__ Blg,
         const float* __restrict__ bias, float* __restrict__ Cf)
{
    extern __shared__ char dynsm[];
    const uint32_t smem_base = smem_u32(dynsm);
    const int tid = threadIdx.x, lane = tid & 31, wid = tid >> 5;
    const int bm = blockIdx.y << 7, bn = blockIdx.x << 7;

    float acc[4][4][4];
#pragma unroll
    for (int i = 0; i < 4; i++)
#pragma unroll
        for (int j = 0; j < 4; j++)
#pragma unroll
            for (int q = 0; q < 4; q++) acc[i][j][q] = 0.f;

    gemm_core<true>(Ahg, Bhg, Blg, smem_base, bm, bn, tid, acc);

    const int wm = (wid & 1) * 64, wn = (wid >> 1) * 32;
#pragma unroll
    for (int i = 0; i < 4; i++) {
        const int grow = bm + wm + i * 16 + (lane >> 2);
#pragma unroll
        for (int j = 0; j < 4; j++) {
            const int gcol = bn + wn + j * 8 + (lane & 3) * 2;
            const float b0 = bias[gcol], b1 = bias[gcol + 1];
            float2 v0, v1;
            v0.x = acc[i][j][0] + b0; v0.y = acc[i][j][1] + b1;
            v1.x = acc[i][j][2] + b0; v1.y = acc[i][j][3] + b1;
            *(float2*)(Cf + (size_t)grow * GN + gcol) = v0;
            *(float2*)(Cf + (size_t)(grow + 8) * GN + gcol) = v1;
        }
    }
}

// ---------------------------------------------------------------------------
// Flash attention on HMMA, base-2 online softmax, fp16 additive mask bias,
// cp.async 3-stage K/V pipeline, ONE barrier per KV iteration.
// q-tile 128 per CTA (32 rows/warp). S2 = Qh Kh^T * KSC + bias; O = Ph Vh.
// Grid: (S/128, H, B) = (16, 16, 2). Block 128 = 4 warps.
// Dynamic smem: 3 stages x (K 9216 B + V 9216 B) = 55296 B.
// ---------------------------------------------------------------------------
#define KSTR 72
#define FSTAGE (2 * 64 * KSTR * 2)        /* 18432 bytes per stage (K+V) */
#define FLASH_SMEM (3 * FSTAGE)           /* 55296 */
#define FNIT (Sv / 64)                    /* 32 */

__global__ void __launch_bounds__(128)
flash_mma(const __half* __restrict__ Qh,
          const __half* __restrict__ Kh, const __half* __restrict__ Vh,
          const __half* __restrict__ mb, __half* __restrict__ Oh)
{
    extern __shared__ char dynsm[];
    __half* smh = (__half*)dynsm;
    const uint32_t sbase = smem_u32(dynsm);

    const int tid = threadIdx.x, lane = tid & 31, warp = tid >> 5;
    const int b = blockIdx.z, h = blockIdx.y;
    const int qb = blockIdx.x << 7, hb = h << 6;

    const uint32_t k_b[3] = {sbase, sbase + FSTAGE, sbase + 2 * FSTAGE};
    // v base = k base + 9216 within each stage

    const int sr = tid >> 3;
    const int sj = (tid & 7) * 8;

    // ---- stage Q (rows 0-63 in stage0 K-slot, 64-127 in stage1 K-slot) ----
#pragma unroll
    for (int i = 0; i < 4; i++) {
        const int r = sr + i * 16;
        const size_t gq  = (size_t)(b * Sv + qb + r) * Ev + hb + sj;
        const size_t gq2 = (size_t)(b * Sv + qb + 64 + r) * Ev + hb + sj;
        *(uint4*)(smh + r * KSTR + sj) = *(const uint4*)(Qh + gq);
        *(uint4*)(smh + (FSTAGE / 2) + r * KSTR + sj) = *(const uint4*)(Qh + gq2);
    }
    __syncthreads();
    uint32_t qf0[4][4], qf1[4][4];
    {
        const uint32_t qbase = k_b[warp >> 1];
        const int lr = (warp & 1) * 32 + (lane & 15);
        const int ac = (lane >> 4) * 8;
#pragma unroll
        for (int kf = 0; kf < 4; kf++) {
            ldsm_x4(qf0[kf], qbase + (uint32_t)(lr * KSTR + kf * 16 + ac) * 2);
            ldsm_x4(qf1[kf], qbase + (uint32_t)((lr + 16) * KSTR + kf * 16 + ac) * 2);
        }
    }
    __syncthreads();  // all Q frags read before stage buffers are overwritten

    float m[4], l[4];
#pragma unroll
    for (int i = 0; i < 4; i++) { m[i] = -1e30f; l[i] = 0.f; }
    float o0[8][4], o1[8][4];
#pragma unroll
    for (int n = 0; n < 8; n++)
#pragma unroll
        for (int q = 0; q < 4; q++) { o0[n][q] = 0.f; o1[n][q] = 0.f; }

    const int r_base = b * Sv + qb + warp * 32 + (lane >> 2);
    const __half* mb0 = mb + (size_t)r_base * Sv;
    const __half* mb1 = mb + (size_t)(r_base + 8) * Sv;
    const __half* mb2 = mb + (size_t)(r_base + 16) * Sv;
    const __half* mb3 = mb + (size_t)(r_base + 24) * Sv;
    const int mc = (lane & 3) * 2;

    const int b_r = (lane & 7) + (lane >> 4) * 8;
    const int b_c = ((lane >> 3) & 1) * 8;
    const int v_r = (lane & 7) + ((lane >> 3) & 1) * 8;
    const int v_c = (lane >> 4) * 8;

    const uint32_t stg_off = (uint32_t)(sr * KSTR + sj) * 2;

    auto issueKV = [&](int kvt, int stg) {
        const int kv = kvt * 64;
        const uint32_t kb = k_b[stg];
        const uint32_t vb = kb + FSTAGE / 2;
#pragma unroll
        for (int i = 0; i < 4; i++) {
            const int r = sr + i * 16;
            const size_t gk = (size_t)(b * Sv + kv + r) * Ev + hb + sj;
            const uint32_t doff = stg_off + (uint32_t)(i * 16 * KSTR) * 2;
            cp16(kb + doff, Kh + gk);
            cp16(vb + doff, Vh + gk);
        }
    };

    issueKV(0, 0); CP_COMMIT();
    issueKV(1, 1); CP_COMMIT();

    int stg = 0;
#pragma unroll 1
    for (int it = 0; it < FNIT; it++) {
        const int kv = it * 64;
        if (it < FNIT - 1) CP_WAIT1(); else CP_WAIT0();
        __syncthreads();   // all warps past compute(it-1); stage it ready
        if (it + 2 < FNIT) {
            issueKV(it + 2, (stg + 2 >= 3) ? stg - 1 : stg + 2);
            CP_COMMIT();
        }
        const uint32_t kb = k_b[stg];
        const uint32_t vb = kb + FSTAGE / 2;

        // ---- S = Q K^T for both m-halves, K frags loaded once ----
        float s0[8][4], s1[8][4];
#pragma unroll
        for (int n = 0; n < 8; n++)
#pragma unroll
            for (int q = 0; q < 4; q++) { s0[n][q] = 0.f; s1[n][q] = 0.f; }

#pragma unroll
        for (int kf = 0; kf < 4; kf++) {
            uint32_t bh[8][2];
#pragma unroll
            for (int u = 0; u < 4; u++) {
                const uint32_t off =
                    (uint32_t)((b_r + u * 16) * KSTR + b_c + kf * 16) * 2;
                uint32_t t[4];
                ldsm_x4(t, kb + off);
                bh[2 * u][0] = t[0]; bh[2 * u][1] = t[1];
                bh[2 * u + 1][0] = t[2]; bh[2 * u + 1][1] = t[3];
            }
#pragma unroll
            for (int n = 0; n < 8; n++) {
                mma_f16(s0[n], qf0[kf], bh[n]);
                mma_f16(s1[n], qf1[kf], bh[n]);
            }
        }

        // ---- scale into base-2 domain + additive mask bias + row maxes ----
        float mx[4] = {-1e30f, -1e30f, -1e30f, -1e30f};
#pragma unroll
        for (int n = 0; n < 8; n++) {
            const int c = kv + n * 8 + mc;
            const __half2 q0 = *(const __half2*)(mb0 + c);
            const __half2 q1 = *(const __half2*)(mb1 + c);
            const __half2 q2 = *(const __half2*)(mb2 + c);
            const __half2 q3 = *(const __half2*)(mb3 + c);
            s0[n][0] = fmaf(s0[n][0], KSC, __low2float(q0));
            s0[n][1] = fmaf(s0[n][1], KSC, __high2float(q0));
            s0[n][2] = fmaf(s0[n][2], KSC, __low2float(q1));
            s0[n][3] = fmaf(s0[n][3], KSC, __high2float(q1));
            s1[n][0] = fmaf(s1[n][0], KSC, __low2float(q2));
            s1[n][1] = fmaf(s1[n][1], KSC, __high2float(q2));
            s1[n][2] = fmaf(s1[n][2], KSC, __low2float(q3));
            s1[n][3] = fmaf(s1[n][3], KSC, __high2float(q3));
            mx[0] = fmaxf(mx[0], fmaxf(s0[n][0], s0[n][1]));
            mx[1] = fmaxf(mx[1], fmaxf(s0[n][2], s0[n][3]));
            mx[2] = fmaxf(mx[2], fmaxf(s1[n][0], s1[n][1]));
            mx[3] = fmaxf(mx[3], fmaxf(s1[n][2], s1[n][3]));
        }
        float corr[4];
#pragma unroll
        for (int i = 0; i < 4; i++) {
            mx[i] = fmaxf(mx[i], __shfl_xor_sync(0xffffffffu, mx[i], 1));
            mx[i] = fmaxf(mx[i], __shfl_xor_sync(0xffffffffu, mx[i], 2));
            const float mn = fmaxf(m[i], mx[i]);
            corr[i] = ex2f(m[i] - mn);
            m[i] = mn;
        }

        float rs[4] = {0.f, 0.f, 0.f, 0.f};
#pragma unroll
        for (int n = 0; n < 8; n++) {
            s0[n][0] = ex2f(s0[n][0] - m[0]); s0[n][1] = ex2f(s0[n][1] - m[0]);
            s0[n][2] = ex2f(s0[n][2] - m[1]); s0[n][3] = ex2f(s0[n][3] - m[1]);
            s1[n][0] = ex2f(s1[n][0] - m[2]); s1[n][1] = ex2f(s1[n][1] - m[2]);
            s1[n][2] = ex2f(s1[n][2] - m[3]); s1[n][3] = ex2f(s1[n][3] - m[3]);
            rs[0] += s0[n][0] + s0[n][1];
            rs[1] += s0[n][2] + s0[n][3];
            rs[2] += s1[n][0] + s1[n][1];
            rs[3] += s1[n][2] + s1[n][3];
            o0[n][0] *= corr[0]; o0[n][1] *= corr[0];
            o0[n][2] *= corr[1]; o0[n][3] *= corr[1];
            o1[n][0] *= corr[2]; o1[n][1] *= corr[2];
            o1[n][2] *= corr[3]; o1[n][3] *= corr[3];
        }
#pragma unroll
        for (int i = 0; i < 4; i++) {
            rs[i] += __shfl_xor_sync(0xffffffffu, rs[i], 1);
            rs[i] += __shfl_xor_sync(0xffffffffu, rs[i], 2);
            l[i] = l[i] * corr[i] + rs[i];
        }

        // ---- pack P fragments (both halves) ----
        uint32_t pf0[4][4], pf1[4][4];
#pragma unroll
        for (int kf = 0; kf < 4; kf++) {
            const int n0 = 2 * kf, n1 = 2 * kf + 1;
            pf0[kf][0] = h2u(__halves2half2(__float2half_rn(s0[n0][0]), __float2half_rn(s0[n0][1])));
            pf0[kf][1] = h2u(__halves2half2(__float2half_rn(s0[n0][2]), __float2half_rn(s0[n0][3])));
            pf0[kf][2] = h2u(__halves2half2(__float2half_rn(s0[n1][0]), __float2half_rn(s0[n1][1])));
            pf0[kf][3] = h2u(__halves2half2(__float2half_rn(s0[n1][2]), __float2half_rn(s0[n1][3])));
            pf1[kf][0] = h2u(__halves2half2(__float2half_rn(s1[n0][0]), __float2half_rn(s1[n0][1])));
            pf1[kf][1] = h2u(__halves2half2(__float2half_rn(s1[n0][2]), __float2half_rn(s1[n0][3])));
            pf1[kf][2] = h2u(__halves2half2(__float2half_rn(s1[n1][0]), __float2half_rn(s1[n1][1])));
            pf1[kf][3] = h2u(__halves2half2(__float2half_rn(s1[n1][2]), __float2half_rn(s1[n1][3])));
        }

        // ---- O += P V, V frags loaded once, used by both halves ----
#pragma unroll
        for (int kf = 0; kf < 4; kf++) {
            uint32_t wh[8][2];
#pragma unroll
            for (int u = 0; u < 4; u++) {
                const uint32_t off =
                    (uint32_t)((v_r + kf * 16) * KSTR + v_c + u * 16) * 2;
                uint32_t t[4];
                ldsm_x4_t(t, vb + off);
                wh[2 * u][0] = t[0]; wh[2 * u][1] = t[1];
                wh[2 * u + 1][0] = t[2]; wh[2 * u + 1][1] = t[3];
            }
#pragma unroll
            for (int n = 0; n < 8; n++) {
                mma_f16(o0[n], pf0[kf], wh[n]);
                mma_f16(o1[n], pf1[kf], wh[n]);
            }
        }
        stg = (stg + 1 == 3) ? 0 : stg + 1;
    }

    // ---- normalize and write (4 row groups x 8 n-blocks) ----
    const float i0 = 1.f / l[0], i1 = 1.f / l[1];
    const float i2 = 1.f / l[2], i3 = 1.f / l[3];
#pragma unroll
    for (int n = 0; n < 8; n++) {
        const int col = hb + n * 8 + mc;
        *(__half2*)(Oh + (size_t)r_base * Ev + col) =
            __halves2half2(__float2half_rn(o0[n][0] * i0), __float2half_rn(o0[n][1] * i0));
        *(__half2*)(Oh + (size_t)(r_base + 8) * Ev + col) =
            __halves2half2(__float2half_rn(o0[n][2] * i1), __float2half_rn(o0[n][3] * i1));
        *(__half2*)(Oh + (size_t)(r_base + 16) * Ev + col) =
            __halves2half2(__float2half_rn(o1[n][0] * i2), __float2half_rn(o1[n][1] * i2));
        *(__half2*)(Oh + (size_t)(r_base + 24) * Ev + col) =
            __halves2half2(__float2half_rn(o1[n][2] * i3), __float2half_rn(o1[n][3] * i3));
    }
}

// ---------------------------------------------------------------------------
extern "C" void kernel_launch(void* const* d_in, const int* in_sizes, int n_in,
                              void* d_out, int out_size)
{
    (void)in_sizes; (void)n_in; (void)out_size;
    const float* query = (const float*)d_in[0];
    const float* key   = (const float*)d_in[1];
    const float* value = (const float*)d_in[2];
    const int*   mask  = (const int*)  d_in[3];
    const float* Wq = (const float*)d_in[4];
    const float* bq = (const float*)d_in[5];
    const float* Wk = (const float*)d_in[6];
    const float* bk = (const float*)d_in[7];
    const float* Wv = (const float*)d_in[8];
    const float* bv = (const float*)d_in[9];
    const float* Wo = (const float*)d_in[10];
    const float* bo = (const float*)d_in[11];
    float* out = (float*)d_out;

    __half *xh, *wh, *woh, *wol, *qh, *kh, *vh, *oh, *mb;
    cudaGetSymbolAddress((void**)&xh, g_xh);
    cudaGetSymbolAddress((void**)&wh, g_wh);
    cudaGetSymbolAddress((void**)&woh, g_woh);
    cudaGetSymbolAddress((void**)&wol, g_wol);
    cudaGetSymbolAddress((void**)&qh, g_qh);
    cudaGetSymbolAddress((void**)&kh, g_kh);
    cudaGetSymbolAddress((void**)&vh, g_vh);
    cudaGetSymbolAddress((void**)&oh, g_oh);
    cudaGetSymbolAddress((void**)&mb, g_mb);

    cudaFuncSetAttribute(gemm_qkv,
                         cudaFuncAttributeMaxDynamicSharedMemorySize, QKV_SMEM);
    cudaFuncSetAttribute(gemm_out,
                         cudaFuncAttributeMaxDynamicSharedMemorySize, OUT_SMEM);
    cudaFuncSetAttribute(flash_mma,
                         cudaFuncAttributeMaxDynamicSharedMemorySize, FLASH_SMEM);

    const int nA4 = (Mv * Ev) / 4;
    const int nW4 = (Ev * Ev) / 4;
    const int nM4 = (Bv * Sv * Sv) / 4;
    const size_t WE = (size_t)Ev * Ev;

    conv_acts<<<dim3(nA4 / 256, 3), 256>>>((const float4*)query, (const float4*)key,
                                           (const float4*)value, (uint2*)xh, nA4);
    conv_mask<<<nM4 / 256, 256>>>((const int4*)mask, (uint2*)mb, nM4);

    WSplitPtrs wp;
    wp.src[0] = (const float4*)Wq; wp.src[1] = (const float4*)Wk;
    wp.src[2] = (const float4*)Wv; wp.src[3] = (const float4*)Wo;
    wp.hi[0] = (uint2*)wh;
    wp.hi[1] = (uint2*)(wh + WE);
    wp.hi[2] = (uint2*)(wh + 2 * WE);
    wp.hi[3] = (uint2*)woh;
    wp.lo = (uint2*)wol;
    split_w<<<dim3(nW4 / 256, 4), 256>>>(wp, nW4);

    QKVParams p;
    p.bias0 = bq; p.bias1 = bk; p.bias2 = bv;
    p.Ch0 = qh; p.Ch1 = kh; p.Ch2 = vh;
    gemm_qkv<<<dim3(GN / 128, Mv / 128, 3), 256, QKV_SMEM>>>(xh, wh, p);

    flash_mma<<<dim3(Sv / 128, Hv, Bv), 128, FLASH_SMEM>>>(qh, kh, vh, mb, oh);

    gemm_out<<<dim3(GN / 128, Mv / 128), 256, OUT_SMEM>>>(oh, woh, wol, bo, out);
}